// round 1
// baseline (speedup 1.0000x reference)
#include <cuda_runtime.h>
#include <math.h>

#define Bb     512
#define Ss     64
#define Dd     128
#define Vv     256
#define NHs    4
#define HDs    32
#define INNERc 256
#define NHMc   4
#define DHMc   64
#define NBc    64
#define Kc     4
#define FFc    128
#define Tt     (Bb*Ss)   /* 32768 tokens */

// ---------------- workspaces (static device globals; no allocation) ----------
__device__ float g_h[Tt*Dd];            // residual stream
__device__ float g_xln[Tt*Dd];          // LN output
__device__ float g_big[Tt*2*INNERc];    // slstm gx [s][b][4][128]  OR  mlstm up out [t][512]
__device__ float g_y[Tt*Dd];            // slstm y / ffn activation
__device__ float g_ffn[Tt*2*FFc];       // ffn up output
__device__ float g_xconv[Tt*INNERc];
__device__ float g_q[Tt*INNERc];        // q, later reused as mlstm combine buffer
__device__ float g_k[Tt*INNERc];
__device__ float g_v[Tt*INNERc];
__device__ float g_hatt[Tt*INNERc];
__device__ float g_ig[Bb*NHMc*Ss];
__device__ float g_fg[Bb*NHMc*Ss];

// ---------------- device math helpers ---------------------------------------
__device__ __forceinline__ float sigf(float x){ return 1.0f/(1.0f+expf(-x)); }
__device__ __forceinline__ float logsigf(float x){ return fminf(x,0.0f) - log1pf(expf(-fabsf(x))); }
__device__ __forceinline__ float geluf(float x){
    float x3 = x*x*x;
    return 0.5f*x*(1.0f+tanhf(0.7978845608028654f*(x+0.044715f*x3)));
}

// ---------------- embedding --------------------------------------------------
__global__ void k_embed(const int* __restrict__ x, const float* __restrict__ emb){
    int t = blockIdx.x;
    g_h[t*Dd + threadIdx.x] = emb[x[t]*Dd + threadIdx.x];
}

// ---------------- layernorm (warp per token, D=128) --------------------------
__global__ void k_ln(const float* __restrict__ in, const float* __restrict__ w,
                     float* __restrict__ out){
    int warp = (blockIdx.x*blockDim.x + threadIdx.x) >> 5;
    int lane = threadIdx.x & 31;
    if (warp >= Tt) return;
    const float* xp = in + (size_t)warp*Dd;
    float v0=xp[lane], v1=xp[lane+32], v2=xp[lane+64], v3=xp[lane+96];
    float s  = v0+v1+v2+v3;
    float ss = v0*v0+v1*v1+v2*v2+v3*v3;
    #pragma unroll
    for(int o=16;o;o>>=1){ s += __shfl_xor_sync(~0u,s,o); ss += __shfl_xor_sync(~0u,ss,o); }
    float mu  = s*(1.0f/Dd);
    float var = ss*(1.0f/Dd) - mu*mu;
    float r   = rsqrtf(var + 1e-5f);
    float* op = out + (size_t)warp*Dd;
    op[lane]    = (v0-mu)*r*w[lane];
    op[lane+32] = (v1-mu)*r*w[lane+32];
    op[lane+64] = (v2-mu)*r*w[lane+64];
    op[lane+96] = (v3-mu)*r*w[lane+96];
}

// ---------------- generic tiled SGEMM: C[M,N] (+)= A[M,K] @ W[K,N] (+bias) ---
template<bool ADD, bool BIAS>
__global__ void __launch_bounds__(256) k_sgemm(
        const float* __restrict__ A, const float* __restrict__ W,
        float* __restrict__ C, const float* __restrict__ bias,
        int M, int N, int K){
    __shared__ float As[16][64];
    __shared__ float Ws[16][64];
    int bm = blockIdx.y*64, bn = blockIdx.x*64;
    int tid = threadIdx.x;
    int tx = tid & 15, ty = tid >> 4;
    float acc[4][4] = {};
    for(int kk=0; kk<K; kk+=16){
        { // A tile 64 rows x 16 cols, store transposed
            int r = tid >> 2, c = (tid & 3)*4;
            float4 va = *(const float4*)(A + (size_t)(bm+r)*K + kk + c);
            As[c  ][r]=va.x; As[c+1][r]=va.y; As[c+2][r]=va.z; As[c+3][r]=va.w;
        }
        { // W tile 16 rows x 64 cols
            int r = tid >> 4, c = (tid & 15)*4;
            *(float4*)&Ws[r][c] = *(const float4*)(W + (size_t)(kk+r)*N + bn + c);
        }
        __syncthreads();
        #pragma unroll
        for(int k=0;k<16;k++){
            float4 a4 = *(const float4*)&As[k][ty*4];
            float4 b4 = *(const float4*)&Ws[k][tx*4];
            float a[4]={a4.x,a4.y,a4.z,a4.w};
            float b[4]={b4.x,b4.y,b4.z,b4.w};
            #pragma unroll
            for(int i=0;i<4;i++)
                #pragma unroll
                for(int j=0;j<4;j++) acc[i][j] += a[i]*b[j];
        }
        __syncthreads();
    }
    #pragma unroll
    for(int i=0;i<4;i++){
        float* cp = C + (size_t)(bm+ty*4+i)*N + bn + tx*4;
        #pragma unroll
        for(int j=0;j<4;j++){
            float val = acc[i][j];
            if (BIAS) val += bias[bn + tx*4 + j];
            if (ADD)  cp[j] += val; else cp[j] = val;
        }
    }
}

// ---------------- sLSTM gate projection gx[s][b][g][n*32+e] ------------------
__global__ void k_sgx(const float* __restrict__ xln, const float* __restrict__ gw,
                      const float* __restrict__ bias){
    int t = blockIdx.x; int b = t/Ss, s = t%Ss;
    __shared__ float xs[Dd];
    if (threadIdx.x < Dd) xs[threadIdx.x] = xln[(size_t)t*Dd + threadIdx.x];
    __syncthreads();
    for(int o = threadIdx.x; o < 4*Dd; o += blockDim.x){
        int g  = o >> 7;
        int ne = o & 127;
        int n  = ne >> 5, e = ne & 31;
        const float* wp = gw + (((g*NHs + n)*HDs + e)*HDs);
        const float* xp = xs + n*HDs;
        float acc = bias[g*Dd + ne];
        #pragma unroll
        for(int d=0; d<HDs; d++) acc += xp[d]*wp[d];
        g_big[((size_t)(s*Bb + b)*4 + g)*Dd + ne] = acc;
    }
}

// ---------------- sLSTM recurrence scan: warp per (b,n) ----------------------
__global__ void k_scan(const float* __restrict__ rec){
    int blk = blockIdx.x; int b = blk / NHs, n = blk % NHs;
    int e = threadIdx.x;                     // 0..31
    __shared__ float rw[4][HDs][HDs];        // [g][e][d]
    __shared__ float hs[HDs];
    for(int idx=e; idx<4*HDs*HDs; idx+=HDs){
        int g = idx/(HDs*HDs); int rem = idx%(HDs*HDs);
        rw[g][rem/HDs][rem%HDs] = rec[(size_t)(g*NHs+n)*HDs*HDs + rem];
    }
    hs[e] = 0.0f;
    float c=0.0f, nn=0.0f, m=0.0f;
    __syncwarp();
    for(int s=0;s<Ss;s++){
        const float* gxp = g_big + ((size_t)(s*Bb + b)*4)*Dd + n*HDs + e;
        float raw[4];
        #pragma unroll
        for(int g=0; g<4; g++){
            float acc = gxp[(size_t)g*Dd];
            const float* wp = rw[g][e];
            #pragma unroll
            for(int d=0; d<HDs; d++) acc += hs[d]*wp[d];
            raw[g] = acc;
        }
        float lfm = m + logsigf(raw[1]);
        float mn  = fmaxf(raw[0], lfm);
        float i   = expf(raw[0]-mn);
        float f   = expf(lfm-mn);
        c  = f*c + i*tanhf(raw[2]);
        nn = f*nn + i;
        float hnew = sigf(raw[3]) * c / nn;
        m = mn;
        __syncwarp();
        hs[e] = hnew;
        __syncwarp();
        g_y[((size_t)(b*Ss+s))*Dd + n*HDs + e] = hnew;
    }
}

// ---------------- sLSTM group norm (G=32) + residual add into g_h ------------
__global__ void k_gn_slstm(const float* __restrict__ gn){
    int t = blockIdx.x;
    int n = threadIdx.x >> 5, lane = threadIdx.x & 31;
    float v = g_y[(size_t)t*Dd + n*HDs + lane];
    float s=v, ss=v*v;
    #pragma unroll
    for(int o=16;o;o>>=1){ s += __shfl_xor_sync(~0u,s,o); ss += __shfl_xor_sync(~0u,ss,o); }
    float mu = s*(1.0f/HDs), var = ss*(1.0f/HDs)-mu*mu;
    float r = rsqrtf(var + 1e-5f);
    g_h[(size_t)t*Dd + n*HDs + lane] += (v-mu)*r*gn[n*HDs+lane];
}

// ---------------- FFN gate activation: gelu(g)*u ------------------------------
__global__ void k_glu(){
    int i = blockIdx.x*blockDim.x + threadIdx.x;
    if (i >= Tt*FFc) return;
    int t = i/FFc, f = i%FFc;
    float g = g_ffn[(size_t)t*2*FFc + f];
    float u = g_ffn[(size_t)t*2*FFc + FFc + f];
    g_y[i] = geluf(g)*u;
}

// ---------------- mLSTM causal depthwise conv + silu -------------------------
__global__ void k_conv(const float* __restrict__ cw, const float* __restrict__ cb){
    int t = blockIdx.x; int c = threadIdx.x;
    int b = t/Ss, s = t%Ss;
    float acc = cb[c];
    #pragma unroll
    for(int tt=0; tt<Kc; tt++){
        int si = s - (Kc-1) + tt;
        if (si >= 0) acc += g_big[((size_t)(b*Ss+si))*2*INNERc + c]*cw[c*Kc+tt];
    }
    g_xconv[(size_t)t*INNERc + c] = acc*sigf(acc);
}

// ---------------- blocked qkv projections ------------------------------------
__global__ void k_qkv(const float* __restrict__ w){
    int t = blockIdx.x; int c = threadIdx.x;
    int n = c >> 2, o = c & 3;
    const float* wq = w + n*16 + o*4;
    const float* wk = wq + NBc*16;
    const float* wv = wk + NBc*16;
    const float* xc = g_xconv + (size_t)t*INNERc + n*4;
    const float* xm = g_big   + (size_t)t*2*INNERc + n*4;
    float q=0,k=0,v=0;
    #pragma unroll
    for(int i=0;i<4;i++){ q += xc[i]*wq[i]; k += xc[i]*wk[i]; v += xm[i]*wv[i]; }
    g_q[(size_t)t*INNERc+c]=q; g_k[(size_t)t*INNERc+c]=k; g_v[(size_t)t*INNERc+c]=v;
}

// ---------------- input/forget gate projections ------------------------------
__global__ void k_gates(const float* __restrict__ igw, const float* __restrict__ igb,
                        const float* __restrict__ fgw, const float* __restrict__ fgb){
    int t = blockIdx.x;
    int hm = threadIdx.x >> 5, lane = threadIdx.x & 31;
    int b = t/Ss, s = t%Ss;
    float ia=0, fa=0;
    for(int j=lane; j<3*INNERc; j+=32){
        float val = (j < INNERc)   ? g_q[(size_t)t*INNERc + j]
                  : (j < 2*INNERc) ? g_k[(size_t)t*INNERc + j - INNERc]
                                   : g_v[(size_t)t*INNERc + j - 2*INNERc];
        ia += val*igw[j*NHMc + hm];
        fa += val*fgw[j*NHMc + hm];
    }
    #pragma unroll
    for(int o=16;o;o>>=1){ ia += __shfl_xor_sync(~0u,ia,o); fa += __shfl_xor_sync(~0u,fa,o); }
    if (lane == 0){
        g_ig[(size_t)(b*NHMc+hm)*Ss + s] = ia + igb[hm];
        g_fg[(size_t)(b*NHMc+hm)*Ss + s] = fa + fgb[hm];
    }
}

// ---------------- mLSTM attention: block per (b, head) -----------------------
__global__ void __launch_bounds__(256) k_attn(){
    int blk = blockIdx.x; int b = blk >> 2, hm = blk & 3;
    __shared__ float qs[Ss][DHMc+1], ks[Ss][DHMc+1];
    __shared__ float cldf[Ss+1], igs[Ss];
    __shared__ float cn[8][Ss];
    int tid = threadIdx.x;
    for(int l=tid; l<Ss*DHMc; l+=256){
        int j = l >> 6, d = l & 63;
        qs[j][d] = g_q[((size_t)(b*Ss+j))*INNERc + hm*DHMc + d];
        ks[j][d] = g_k[((size_t)(b*Ss+j))*INNERc + hm*DHMc + d];
    }
    if (tid < Ss) igs[tid] = g_ig[(size_t)(b*NHMc+hm)*Ss + tid];
    if (tid == 0){
        float cacc = 0.0f; cldf[0] = 0.0f;
        for(int s=0;s<Ss;s++){ cacc += logsigf(g_fg[(size_t)(b*NHMc+hm)*Ss + s]); cldf[s+1]=cacc; }
    }
    __syncthreads();
    int w = tid >> 5, lane = tid & 31;
    const float* vp = g_v + (size_t)b*Ss*INNERc + hm*DHMc;
    for(int r=0;r<8;r++){
        int i = w*8 + r;
        int j1 = lane + 32;
        float dot0=0, dot1=0, ld0=-1e30f, ld1=-1e30f;
        if (lane <= i){
            #pragma unroll
            for(int d=0; d<DHMc; d++) dot0 += qs[i][d]*ks[lane][d];
            ld0 = cldf[i+1]-cldf[lane+1] + igs[lane];
        }
        if (j1 <= i){
            #pragma unroll
            for(int d=0; d<DHMc; d++) dot1 += qs[i][d]*ks[j1][d];
            ld1 = cldf[i+1]-cldf[j1+1] + igs[j1];
        }
        float mx = fmaxf(ld0, ld1);
        #pragma unroll
        for(int o=16;o;o>>=1) mx = fmaxf(mx, __shfl_xor_sync(~0u,mx,o));
        float cm0 = (lane <= i) ? dot0*0.125f*expf(ld0-mx) : 0.0f;
        float cm1 = (j1   <= i) ? dot1*0.125f*expf(ld1-mx) : 0.0f;
        float sm = cm0 + cm1;
        #pragma unroll
        for(int o=16;o;o>>=1) sm += __shfl_xor_sync(~0u,sm,o);
        float norm = fmaxf(fabsf(sm), expf(-mx)) + 1e-6f;
        cn[w][lane] = cm0/norm;
        cn[w][j1]   = cm1/norm;
        __syncwarp();
        float a0=0, a1=0;
        for(int j=0;j<=i;j++){
            float cc = cn[w][j];
            a0 += cc*vp[(size_t)j*INNERc + lane];
            a1 += cc*vp[(size_t)j*INNERc + lane + 32];
        }
        g_hatt[((size_t)(b*Ss+i))*INNERc + hm*DHMc + lane]      = a0;
        g_hatt[((size_t)(b*Ss+i))*INNERc + hm*DHMc + lane + 32] = a1;
        __syncwarp();
    }
}

// ---------------- mLSTM groupnorm (G=64) + skip/silu combine -----------------
__global__ void k_gn_comb(const float* __restrict__ onw, const float* __restrict__ skip){
    int t = blockIdx.x;
    int hm = threadIdx.x >> 5, lane = threadIdx.x & 31;
    size_t base = (size_t)t*INNERc + hm*DHMc;
    float v0 = g_hatt[base+lane], v1 = g_hatt[base+lane+32];
    float s = v0+v1, ss = v0*v0+v1*v1;
    #pragma unroll
    for(int o=16;o;o>>=1){ s += __shfl_xor_sync(~0u,s,o); ss += __shfl_xor_sync(~0u,ss,o); }
    float mu = s*(1.0f/DHMc), var = ss*(1.0f/DHMc)-mu*mu;
    float r = rsqrtf(var + 1e-5f);
    #pragma unroll
    for(int p=0;p<2;p++){
        int c = hm*DHMc + lane + p*32;
        float v = p ? v1 : v0;
        float z = g_big[(size_t)t*2*INNERc + INNERc + c];
        float out = ((v-mu)*r*onw[c] + skip[c]*g_xconv[(size_t)t*INNERc + c]) * z*sigf(z);
        g_q[(size_t)t*INNERc + c] = out;   // reuse g_q as combine buffer
    }
}

// ---------------- host-side --------------------------------------------------
static float* symf(const void* s){ void* p=nullptr; cudaGetSymbolAddress(&p, s); return (float*)p; }

extern "C" void kernel_launch(void* const* d_in, const int* in_sizes, int n_in,
                              void* d_out, int out_size){
    const int*   x         = (const int*)  d_in[0];
    const float* embed     = (const float*)d_in[1];
    const float* s_ln1     = (const float*)d_in[2];
    const float* s_gates_w = (const float*)d_in[3];
    const float* s_rec     = (const float*)d_in[4];
    const float* s_bias    = (const float*)d_in[5];
    const float* s_gn      = (const float*)d_in[6];
    const float* s_ln2     = (const float*)d_in[7];
    const float* s_ff_up   = (const float*)d_in[8];
    const float* s_ff_down = (const float*)d_in[9];
    const float* m_ln1     = (const float*)d_in[10];
    const float* m_up      = (const float*)d_in[11];
    const float* m_conv_w  = (const float*)d_in[12];
    const float* m_conv_b  = (const float*)d_in[13];
    const float* m_qkv_w   = (const float*)d_in[14];
    const float* m_ig_w    = (const float*)d_in[15];
    const float* m_ig_b    = (const float*)d_in[16];
    const float* m_fg_w    = (const float*)d_in[17];
    const float* m_fg_b    = (const float*)d_in[18];
    const float* m_skip    = (const float*)d_in[19];
    const float* m_onorm   = (const float*)d_in[20];
    const float* m_down    = (const float*)d_in[21];
    const float* m_ln2     = (const float*)d_in[22];
    const float* m_ff_up   = (const float*)d_in[23];
    const float* m_ff_down = (const float*)d_in[24];
    const float* post_ln   = (const float*)d_in[25];
    const float* head_w    = (const float*)d_in[26];
    const float* head_b    = (const float*)d_in[27];

    float* h    = symf(g_h);
    float* xln  = symf(g_xln);
    float* big  = symf(g_big);
    float* y    = symf(g_y);
    float* ffn  = symf(g_ffn);
    float* qb   = symf(g_q);

    float* out = (float*)d_out;

    k_embed<<<Tt, Dd>>>(x, embed);

    for(int i=0;i<2;i++){
        // ---- sLSTM block ----
        k_ln<<<Tt/8,256>>>(h, s_ln1 + i*Dd, xln);
        k_sgx<<<Tt,256>>>(xln, s_gates_w + (size_t)i*4*NHs*HDs*HDs, s_bias + i*4*Dd);
        k_scan<<<Bb*NHs,HDs>>>(s_rec + (size_t)i*4*NHs*HDs*HDs);
        k_gn_slstm<<<Tt,128>>>(s_gn + i*Dd);

        // ---- FFN 1 ----
        k_ln<<<Tt/8,256>>>(h, s_ln2 + i*Dd, xln);
        k_sgemm<false,false><<<dim3(2*FFc/64, Tt/64),256>>>(xln, s_ff_up + (size_t)i*Dd*2*FFc, ffn, nullptr, Tt, 2*FFc, Dd);
        k_glu<<<(Tt*FFc+255)/256,256>>>();
        k_sgemm<true ,false><<<dim3(Dd/64,   Tt/64),256>>>(y,  s_ff_down + (size_t)i*FFc*Dd, h, nullptr, Tt, Dd, FFc);

        // ---- mLSTM block ----
        k_ln<<<Tt/8,256>>>(h, m_ln1 + i*Dd, xln);
        k_sgemm<false,false><<<dim3(2*INNERc/64, Tt/64),256>>>(xln, m_up + (size_t)i*Dd*2*INNERc, big, nullptr, Tt, 2*INNERc, Dd);
        k_conv<<<Tt,INNERc>>>(m_conv_w + (size_t)i*INNERc*Kc, m_conv_b + i*INNERc);
        k_qkv<<<Tt,INNERc>>>(m_qkv_w + (size_t)i*3*NBc*16);
        k_gates<<<Tt,128>>>(m_ig_w + (size_t)i*3*INNERc*NHMc, m_ig_b + i*NHMc,
                            m_fg_w + (size_t)i*3*INNERc*NHMc, m_fg_b + i*NHMc);
        k_attn<<<Bb*NHMc,256>>>();
        k_gn_comb<<<Tt,128>>>(m_onorm + i*INNERc, m_skip + i*INNERc);
        k_sgemm<true ,false><<<dim3(Dd/64, Tt/64),256>>>(qb, m_down + (size_t)i*INNERc*Dd, h, nullptr, Tt, Dd, INNERc);

        // ---- FFN 2 ----
        k_ln<<<Tt/8,256>>>(h, m_ln2 + i*Dd, xln);
        k_sgemm<false,false><<<dim3(2*FFc/64, Tt/64),256>>>(xln, m_ff_up + (size_t)i*Dd*2*FFc, ffn, nullptr, Tt, 2*FFc, Dd);
        k_glu<<<(Tt*FFc+255)/256,256>>>();
        k_sgemm<true ,false><<<dim3(Dd/64,   Tt/64),256>>>(y, m_ff_down + (size_t)i*FFc*Dd, h, nullptr, Tt, Dd, FFc);
    }

    // ---- final LN + head ----
    k_ln<<<Tt/8,256>>>(h, post_ln, xln);
    k_sgemm<false,true><<<dim3(Vv/64, Tt/64),256>>>(xln, head_w, out, head_b, Tt, Vv, Dd);
}

// round 2
// speedup vs baseline: 1.1403x; 1.1403x over previous
#include <cuda_runtime.h>
#include <math.h>

#define Bb     512
#define Ss     64
#define Dd     128
#define Vv     256
#define NHs    4
#define HDs    32
#define INNERc 256
#define NHMc   4
#define DHMc   64
#define NBc    64
#define Kc     4
#define FFc    128
#define Tt     (Bb*Ss)   /* 32768 tokens */

// ---------------- workspaces (static device globals; no allocation) ----------
__device__ float g_h[Tt*Dd];            // residual stream
__device__ float g_xln[Tt*Dd];          // LN output
__device__ float g_big[Tt*2*INNERc];    // slstm gx [s][b][4][128]  OR  mlstm up out [t][512]
__device__ float g_y[Tt*Dd];            // slstm y / ffn activation
__device__ float g_ffn[Tt*2*FFc];       // ffn up output
__device__ float g_xconv[Tt*INNERc];
__device__ float g_q[Tt*INNERc];        // q, later reused as mlstm combine buffer
__device__ float g_k[Tt*INNERc];
__device__ float g_v[Tt*INNERc];
__device__ float g_hatt[Tt*INNERc];
__device__ float g_ig[Bb*NHMc*Ss];
__device__ float g_fg[Bb*NHMc*Ss];

// ---------------- device math helpers ---------------------------------------
__device__ __forceinline__ float sigf(float x){ return 1.0f/(1.0f+expf(-x)); }
__device__ __forceinline__ float logsigf(float x){ return fminf(x,0.0f) - log1pf(expf(-fabsf(x))); }
__device__ __forceinline__ float geluf(float x){
    float x3 = x*x*x;
    return 0.5f*x*(1.0f+tanhf(0.7978845608028654f*(x+0.044715f*x3)));
}

// ---------------- embedding --------------------------------------------------
__global__ void k_embed(const int* __restrict__ x, const float* __restrict__ emb){
    int t = blockIdx.x;
    g_h[t*Dd + threadIdx.x] = emb[x[t]*Dd + threadIdx.x];
}

// ---------------- layernorm (warp per token, D=128) --------------------------
__global__ void k_ln(const float* __restrict__ in, const float* __restrict__ w,
                     float* __restrict__ out){
    int warp = (blockIdx.x*blockDim.x + threadIdx.x) >> 5;
    int lane = threadIdx.x & 31;
    if (warp >= Tt) return;
    const float* xp = in + (size_t)warp*Dd;
    float v0=xp[lane], v1=xp[lane+32], v2=xp[lane+64], v3=xp[lane+96];
    float s  = v0+v1+v2+v3;
    float ss = v0*v0+v1*v1+v2*v2+v3*v3;
    #pragma unroll
    for(int o=16;o;o>>=1){ s += __shfl_xor_sync(~0u,s,o); ss += __shfl_xor_sync(~0u,ss,o); }
    float mu  = s*(1.0f/Dd);
    float var = ss*(1.0f/Dd) - mu*mu;
    float r   = rsqrtf(var + 1e-5f);
    float* op = out + (size_t)warp*Dd;
    op[lane]    = (v0-mu)*r*w[lane];
    op[lane+32] = (v1-mu)*r*w[lane+32];
    op[lane+64] = (v2-mu)*r*w[lane+64];
    op[lane+96] = (v3-mu)*r*w[lane+96];
}

// ---------------- double-buffered SGEMM: C[M,N] (+)= A[M,K] @ W[K,N] ----------
// BM=128, BN=64, BK=8, 256 threads, 8x4 microtile.
template<bool ADD, bool BIAS>
__global__ void __launch_bounds__(256) k_gemm(
        const float* __restrict__ A, const float* __restrict__ W,
        float* __restrict__ C, const float* __restrict__ bias,
        int M, int N, int K){
    __shared__ float As[2][8][128];
    __shared__ float Bs[2][8][64];
    int bm = blockIdx.y*128, bn = blockIdx.x*64;
    int tid = threadIdx.x;
    int tx = tid & 15, ty = tid >> 4;
    int ar = tid >> 1, ac = (tid & 1)*4;
    int br = tid >> 4, bc = (tid & 15)*4;

    const float* Ap = A + (size_t)(bm+ar)*K + ac;
    const float* Wp = W + bn + bc;

    float acc[8][4] = {};

    // prologue: stage 0
    {
        float4 va = *(const float4*)(Ap);
        As[0][ac  ][ar]=va.x; As[0][ac+1][ar]=va.y; As[0][ac+2][ar]=va.z; As[0][ac+3][ar]=va.w;
        if (tid < 128)
            *(float4*)&Bs[0][br][bc] = *(const float4*)(Wp + (size_t)br*N);
    }
    __syncthreads();

    int nstage = K >> 3;
    for (int st=0; st<nstage; st++){
        int cur = st & 1;
        if (st+1 < nstage){
            int k0 = (st+1)*8;
            int nxt = cur^1;
            float4 va = *(const float4*)(Ap + k0);
            As[nxt][ac  ][ar]=va.x; As[nxt][ac+1][ar]=va.y;
            As[nxt][ac+2][ar]=va.z; As[nxt][ac+3][ar]=va.w;
            if (tid < 128)
                *(float4*)&Bs[nxt][br][bc] = *(const float4*)(Wp + (size_t)(k0+br)*N);
        }
        #pragma unroll
        for(int k=0;k<8;k++){
            float4 b4 = *(const float4*)&Bs[cur][k][tx*4];
            float4 a0 = *(const float4*)&As[cur][k][ty*8];
            float4 a1 = *(const float4*)&As[cur][k][ty*8+4];
            float a[8]={a0.x,a0.y,a0.z,a0.w,a1.x,a1.y,a1.z,a1.w};
            float bq[4]={b4.x,b4.y,b4.z,b4.w};
            #pragma unroll
            for(int i=0;i<8;i++)
                #pragma unroll
                for(int j=0;j<4;j++) acc[i][j] += a[i]*bq[j];
        }
        __syncthreads();
    }
    #pragma unroll
    for(int i=0;i<8;i++){
        float* cp = C + (size_t)(bm+ty*8+i)*N + bn + tx*4;
        #pragma unroll
        for(int j=0;j<4;j++){
            float v = acc[i][j];
            if (BIAS) v += bias[bn + tx*4 + j];
            if (ADD)  cp[j] += v; else cp[j] = v;
        }
    }
}

// ---------------- sLSTM gate projection gx[s][b][g][n*32+e] ------------------
__global__ void k_sgx(const float* __restrict__ xln, const float* __restrict__ gw,
                      const float* __restrict__ bias){
    int t = blockIdx.x; int b = t/Ss, s = t%Ss;
    __shared__ float xs[Dd];
    if (threadIdx.x < Dd) xs[threadIdx.x] = xln[(size_t)t*Dd + threadIdx.x];
    __syncthreads();
    for(int o = threadIdx.x; o < 4*Dd; o += blockDim.x){
        int g  = o >> 7;
        int ne = o & 127;
        int n  = ne >> 5, e = ne & 31;
        const float* wp = gw + (((g*NHs + n)*HDs + e)*HDs);
        const float* xp = xs + n*HDs;
        float acc = bias[g*Dd + ne];
        #pragma unroll
        for(int d=0; d<HDs; d++) acc += xp[d]*wp[d];
        g_big[((size_t)(s*Bb + b)*4 + g)*Dd + ne] = acc;
    }
}

// ---------------- sLSTM recurrence scan: 8 warps/block, shared weights -------
// block = (head n, batch group of 8). rw transposed into [g][e][36] (padded) so
// per-lane float4 reads are bank-phase conflict-free.
__global__ void __launch_bounds__(256) k_scan(const float* __restrict__ rec){
    int n  = blockIdx.x & 3;
    int bg = blockIdx.x >> 2;           // 0..63
    int w  = threadIdx.x >> 5;
    int e  = threadIdx.x & 31;
    int b  = bg*8 + w;
    __shared__ float rw[4][HDs][36];
    __shared__ float hs[8][HDs];
    for (int idx = threadIdx.x; idx < 4*HDs*HDs; idx += 256){
        int g = idx >> 10, rem = idx & 1023;
        int e2 = rem >> 5, d = rem & 31;
        rw[g][e2][d] = rec[((size_t)(g*NHs+n)*HDs + e2)*HDs + d];
    }
    hs[w][e] = 0.0f;
    __syncthreads();
    float c=0.0f, nn=0.0f, m=0.0f;
    const int gb = n*HDs + e;
    for(int s=0;s<Ss;s++){
        const float* gxp = g_big + ((size_t)(s*Bb + b)*4)*Dd + gb;
        float r0=gxp[0], r1=gxp[Dd], r2=gxp[2*Dd], r3=gxp[3*Dd];
        #pragma unroll
        for(int dq=0; dq<8; dq++){
            float4 hv = *(const float4*)&hs[w][dq*4];
            float4 w0 = *(const float4*)&rw[0][e][dq*4];
            float4 w1 = *(const float4*)&rw[1][e][dq*4];
            float4 w2 = *(const float4*)&rw[2][e][dq*4];
            float4 w3 = *(const float4*)&rw[3][e][dq*4];
            r0 += hv.x*w0.x + hv.y*w0.y + hv.z*w0.z + hv.w*w0.w;
            r1 += hv.x*w1.x + hv.y*w1.y + hv.z*w1.z + hv.w*w1.w;
            r2 += hv.x*w2.x + hv.y*w2.y + hv.z*w2.z + hv.w*w2.w;
            r3 += hv.x*w3.x + hv.y*w3.y + hv.z*w3.z + hv.w*w3.w;
        }
        float lfm = m + logsigf(r1);
        float mn  = fmaxf(r0, lfm);
        float i   = expf(r0-mn);
        float f   = expf(lfm-mn);
        c  = f*c + i*tanhf(r2);
        nn = f*nn + i;
        float hnew = sigf(r3) * c / nn;
        m = mn;
        __syncwarp();
        hs[w][e] = hnew;
        __syncwarp();
        g_y[((size_t)(b*Ss+s))*Dd + gb] = hnew;
    }
}

// ---------------- sLSTM group norm (G=32) + residual add into g_h ------------
__global__ void k_gn_slstm(const float* __restrict__ gn){
    int t = blockIdx.x;
    int n = threadIdx.x >> 5, lane = threadIdx.x & 31;
    float v = g_y[(size_t)t*Dd + n*HDs + lane];
    float s=v, ss=v*v;
    #pragma unroll
    for(int o=16;o;o>>=1){ s += __shfl_xor_sync(~0u,s,o); ss += __shfl_xor_sync(~0u,ss,o); }
    float mu = s*(1.0f/HDs), var = ss*(1.0f/HDs)-mu*mu;
    float r = rsqrtf(var + 1e-5f);
    g_h[(size_t)t*Dd + n*HDs + lane] += (v-mu)*r*gn[n*HDs+lane];
}

// ---------------- FFN gate activation: gelu(g)*u (float4) --------------------
__global__ void k_glu(){
    int i = blockIdx.x*blockDim.x + threadIdx.x;   // over Tt*FFc/4
    if (i >= Tt*FFc/4) return;
    int t = i/(FFc/4), f4 = i%(FFc/4);
    const float4 g4 = *(const float4*)&g_ffn[(size_t)t*2*FFc + f4*4];
    const float4 u4 = *(const float4*)&g_ffn[(size_t)t*2*FFc + FFc + f4*4];
    float4 o;
    o.x = geluf(g4.x)*u4.x; o.y = geluf(g4.y)*u4.y;
    o.z = geluf(g4.z)*u4.z; o.w = geluf(g4.w)*u4.w;
    *(float4*)&g_y[(size_t)t*FFc + f4*4] = o;
}

// ---------------- mLSTM causal depthwise conv + silu -------------------------
__global__ void k_conv(const float* __restrict__ cw, const float* __restrict__ cb){
    int t = blockIdx.x; int c = threadIdx.x;
    int b = t/Ss, s = t%Ss;
    float acc = cb[c];
    #pragma unroll
    for(int tt=0; tt<Kc; tt++){
        int si = s - (Kc-1) + tt;
        if (si >= 0) acc += g_big[((size_t)(b*Ss+si))*2*INNERc + c]*cw[c*Kc+tt];
    }
    g_xconv[(size_t)t*INNERc + c] = acc*sigf(acc);
}

// ---------------- blocked qkv projections ------------------------------------
__global__ void k_qkv(const float* __restrict__ w){
    int t = blockIdx.x; int c = threadIdx.x;
    int n = c >> 2, o = c & 3;
    const float* wq = w + n*16 + o*4;
    const float* wk = wq + NBc*16;
    const float* wv = wk + NBc*16;
    const float* xc = g_xconv + (size_t)t*INNERc + n*4;
    const float* xm = g_big   + (size_t)t*2*INNERc + n*4;
    float q=0,k=0,v=0;
    #pragma unroll
    for(int i=0;i<4;i++){ q += xc[i]*wq[i]; k += xc[i]*wk[i]; v += xm[i]*wv[i]; }
    g_q[(size_t)t*INNERc+c]=q; g_k[(size_t)t*INNERc+c]=k; g_v[(size_t)t*INNERc+c]=v;
}

// ---------------- input/forget gate projections ------------------------------
__global__ void k_gates(const float* __restrict__ igw, const float* __restrict__ igb,
                        const float* __restrict__ fgw, const float* __restrict__ fgb){
    int t = blockIdx.x;
    int hm = threadIdx.x >> 5, lane = threadIdx.x & 31;
    int b = t/Ss, s = t%Ss;
    float ia=0, fa=0;
    for(int j=lane; j<3*INNERc; j+=32){
        float val = (j < INNERc)   ? g_q[(size_t)t*INNERc + j]
                  : (j < 2*INNERc) ? g_k[(size_t)t*INNERc + j - INNERc]
                                   : g_v[(size_t)t*INNERc + j - 2*INNERc];
        ia += val*igw[j*NHMc + hm];
        fa += val*fgw[j*NHMc + hm];
    }
    #pragma unroll
    for(int o=16;o;o>>=1){ ia += __shfl_xor_sync(~0u,ia,o); fa += __shfl_xor_sync(~0u,fa,o); }
    if (lane == 0){
        g_ig[(size_t)(b*NHMc+hm)*Ss + s] = ia + igb[hm];
        g_fg[(size_t)(b*NHMc+hm)*Ss + s] = fa + fgb[hm];
    }
}

// ---------------- mLSTM attention: block per (b, head) -----------------------
__global__ void __launch_bounds__(256) k_attn(){
    int blk = blockIdx.x; int b = blk >> 2, hm = blk & 3;
    __shared__ float qs[Ss][DHMc+1], ks[Ss][DHMc+1];
    __shared__ float cldf[Ss+1], igs[Ss];
    __shared__ float cn[8][Ss];
    int tid = threadIdx.x;
    for(int l=tid; l<Ss*DHMc; l+=256){
        int j = l >> 6, d = l & 63;
        qs[j][d] = g_q[((size_t)(b*Ss+j))*INNERc + hm*DHMc + d];
        ks[j][d] = g_k[((size_t)(b*Ss+j))*INNERc + hm*DHMc + d];
    }
    if (tid < Ss) igs[tid] = g_ig[(size_t)(b*NHMc+hm)*Ss + tid];
    if (tid == 0){
        float cacc = 0.0f; cldf[0] = 0.0f;
        for(int s=0;s<Ss;s++){ cacc += logsigf(g_fg[(size_t)(b*NHMc+hm)*Ss + s]); cldf[s+1]=cacc; }
    }
    __syncthreads();
    int w = tid >> 5, lane = tid & 31;
    const float* vp = g_v + (size_t)b*Ss*INNERc + hm*DHMc;
    for(int r=0;r<8;r++){
        int i = w*8 + r;
        int j1 = lane + 32;
        float dot0=0, dot1=0, ld0=-1e30f, ld1=-1e30f;
        if (lane <= i){
            #pragma unroll
            for(int d=0; d<DHMc; d++) dot0 += qs[i][d]*ks[lane][d];
            ld0 = cldf[i+1]-cldf[lane+1] + igs[lane];
        }
        if (j1 <= i){
            #pragma unroll
            for(int d=0; d<DHMc; d++) dot1 += qs[i][d]*ks[j1][d];
            ld1 = cldf[i+1]-cldf[j1+1] + igs[j1];
        }
        float mx = fmaxf(ld0, ld1);
        #pragma unroll
        for(int o=16;o;o>>=1) mx = fmaxf(mx, __shfl_xor_sync(~0u,mx,o));
        float cm0 = (lane <= i) ? dot0*0.125f*expf(ld0-mx) : 0.0f;
        float cm1 = (j1   <= i) ? dot1*0.125f*expf(ld1-mx) : 0.0f;
        float sm = cm0 + cm1;
        #pragma unroll
        for(int o=16;o;o>>=1) sm += __shfl_xor_sync(~0u,sm,o);
        float norm = fmaxf(fabsf(sm), expf(-mx)) + 1e-6f;
        cn[w][lane] = cm0/norm;
        cn[w][j1]   = cm1/norm;
        __syncwarp();
        float a0=0, a1=0;
        for(int j=0;j<=i;j++){
            float cc = cn[w][j];
            a0 += cc*vp[(size_t)j*INNERc + lane];
            a1 += cc*vp[(size_t)j*INNERc + lane + 32];
        }
        g_hatt[((size_t)(b*Ss+i))*INNERc + hm*DHMc + lane]      = a0;
        g_hatt[((size_t)(b*Ss+i))*INNERc + hm*DHMc + lane + 32] = a1;
        __syncwarp();
    }
}

// ---------------- mLSTM groupnorm (G=64) + skip/silu combine -----------------
__global__ void k_gn_comb(const float* __restrict__ onw, const float* __restrict__ skip){
    int t = blockIdx.x;
    int hm = threadIdx.x >> 5, lane = threadIdx.x & 31;
    size_t base = (size_t)t*INNERc + hm*DHMc;
    float v0 = g_hatt[base+lane], v1 = g_hatt[base+lane+32];
    float s = v0+v1, ss = v0*v0+v1*v1;
    #pragma unroll
    for(int o=16;o;o>>=1){ s += __shfl_xor_sync(~0u,s,o); ss += __shfl_xor_sync(~0u,ss,o); }
    float mu = s*(1.0f/DHMc), var = ss*(1.0f/DHMc)-mu*mu;
    float r = rsqrtf(var + 1e-5f);
    #pragma unroll
    for(int p=0;p<2;p++){
        int c = hm*DHMc + lane + p*32;
        float v = p ? v1 : v0;
        float z = g_big[(size_t)t*2*INNERc + INNERc + c];
        float out = ((v-mu)*r*onw[c] + skip[c]*g_xconv[(size_t)t*INNERc + c]) * z*sigf(z);
        g_q[(size_t)t*INNERc + c] = out;   // reuse g_q as combine buffer
    }
}

// ---------------- host-side --------------------------------------------------
static float* symf(const void* s){ void* p=nullptr; cudaGetSymbolAddress(&p, s); return (float*)p; }

extern "C" void kernel_launch(void* const* d_in, const int* in_sizes, int n_in,
                              void* d_out, int out_size){
    const int*   x         = (const int*)  d_in[0];
    const float* embed     = (const float*)d_in[1];
    const float* s_ln1     = (const float*)d_in[2];
    const float* s_gates_w = (const float*)d_in[3];
    const float* s_rec     = (const float*)d_in[4];
    const float* s_bias    = (const float*)d_in[5];
    const float* s_gn      = (const float*)d_in[6];
    const float* s_ln2     = (const float*)d_in[7];
    const float* s_ff_up   = (const float*)d_in[8];
    const float* s_ff_down = (const float*)d_in[9];
    const float* m_ln1     = (const float*)d_in[10];
    const float* m_up      = (const float*)d_in[11];
    const float* m_conv_w  = (const float*)d_in[12];
    const float* m_conv_b  = (const float*)d_in[13];
    const float* m_qkv_w   = (const float*)d_in[14];
    const float* m_ig_w    = (const float*)d_in[15];
    const float* m_ig_b    = (const float*)d_in[16];
    const float* m_fg_w    = (const float*)d_in[17];
    const float* m_fg_b    = (const float*)d_in[18];
    const float* m_skip    = (const float*)d_in[19];
    const float* m_onorm   = (const float*)d_in[20];
    const float* m_down    = (const float*)d_in[21];
    const float* m_ln2     = (const float*)d_in[22];
    const float* m_ff_up   = (const float*)d_in[23];
    const float* m_ff_down = (const float*)d_in[24];
    const float* post_ln   = (const float*)d_in[25];
    const float* head_w    = (const float*)d_in[26];
    const float* head_b    = (const float*)d_in[27];

    float* h    = symf(g_h);
    float* xln  = symf(g_xln);
    float* big  = symf(g_big);
    float* y    = symf(g_y);
    float* ffn  = symf(g_ffn);
    float* qb   = symf(g_q);

    float* out = (float*)d_out;

    k_embed<<<Tt, Dd>>>(x, embed);

    for(int i=0;i<2;i++){
        // ---- sLSTM block ----
        k_ln<<<Tt/8,256>>>(h, s_ln1 + i*Dd, xln);
        k_sgx<<<Tt,256>>>(xln, s_gates_w + (size_t)i*4*NHs*HDs*HDs, s_bias + i*4*Dd);
        k_scan<<<NHs*(Bb/8),256>>>(s_rec + (size_t)i*4*NHs*HDs*HDs);
        k_gn_slstm<<<Tt,128>>>(s_gn + i*Dd);

        // ---- FFN 1 ----
        k_ln<<<Tt/8,256>>>(h, s_ln2 + i*Dd, xln);
        k_gemm<false,false><<<dim3(2*FFc/64, Tt/128),256>>>(xln, s_ff_up + (size_t)i*Dd*2*FFc, ffn, nullptr, Tt, 2*FFc, Dd);
        k_glu<<<(Tt*FFc/4+255)/256,256>>>();
        k_gemm<true ,false><<<dim3(Dd/64,   Tt/128),256>>>(y,  s_ff_down + (size_t)i*FFc*Dd, h, nullptr, Tt, Dd, FFc);

        // ---- mLSTM block ----
        k_ln<<<Tt/8,256>>>(h, m_ln1 + i*Dd, xln);
        k_gemm<false,false><<<dim3(2*INNERc/64, Tt/128),256>>>(xln, m_up + (size_t)i*Dd*2*INNERc, big, nullptr, Tt, 2*INNERc, Dd);
        k_conv<<<Tt,INNERc>>>(m_conv_w + (size_t)i*INNERc*Kc, m_conv_b + i*INNERc);
        k_qkv<<<Tt,INNERc>>>(m_qkv_w + (size_t)i*3*NBc*16);
        k_gates<<<Tt,128>>>(m_ig_w + (size_t)i*3*INNERc*NHMc, m_ig_b + i*NHMc,
                            m_fg_w + (size_t)i*3*INNERc*NHMc, m_fg_b + i*NHMc);
        k_attn<<<Bb*NHMc,256>>>();
        k_gn_comb<<<Tt,128>>>(m_onorm + i*INNERc, m_skip + i*INNERc);
        k_gemm<true ,false><<<dim3(Dd/64, Tt/128),256>>>(qb, m_down + (size_t)i*INNERc*Dd, h, nullptr, Tt, Dd, INNERc);

        // ---- FFN 2 ----
        k_ln<<<Tt/8,256>>>(h, m_ln2 + i*Dd, xln);
        k_gemm<false,false><<<dim3(2*FFc/64, Tt/128),256>>>(xln, m_ff_up + (size_t)i*Dd*2*FFc, ffn, nullptr, Tt, 2*FFc, Dd);
        k_glu<<<(Tt*FFc/4+255)/256,256>>>();
        k_gemm<true ,false><<<dim3(Dd/64,   Tt/128),256>>>(y, m_ff_down + (size_t)i*FFc*Dd, h, nullptr, Tt, Dd, FFc);
    }

    // ---- final LN + head ----
    k_ln<<<Tt/8,256>>>(h, post_ln, xln);
    k_gemm<false,true><<<dim3(Vv/64, Tt/128),256>>>(xln, head_w, out, head_b, Tt, Vv, Dd);
}

// round 3
// speedup vs baseline: 1.2056x; 1.0573x over previous
#include <cuda_runtime.h>
#include <math.h>

#define Bb     512
#define Ss     64
#define Dd     128
#define Vv     256
#define NHs    4
#define HDs    32
#define INNERc 256
#define NHMc   4
#define DHMc   64
#define NBc    64
#define Kc     4
#define FFc    128
#define Tt     (Bb*Ss)   /* 32768 tokens */

// ---------------- workspaces (static device globals; no allocation) ----------
__device__ float g_h[Tt*Dd];            // residual stream
__device__ float g_xln[Tt*Dd];          // LN output
__device__ float g_big[Tt*2*INNERc];    // slstm gx [s][b][4][128]  OR  mlstm up out [t][512]
__device__ float g_y[Tt*Dd];            // slstm y / ffn activation
__device__ float g_ffn[Tt*2*FFc];       // ffn up output
__device__ float g_xconv[Tt*INNERc];
__device__ float g_q[Tt*INNERc];        // q, later reused as mlstm combine buffer
__device__ float g_k[Tt*INNERc];
__device__ float g_v[Tt*INNERc];
__device__ float g_hatt[Tt*INNERc];
__device__ float g_ig[Bb*NHMc*Ss];
__device__ float g_fg[Bb*NHMc*Ss];

// ---------------- device math helpers ---------------------------------------
__device__ __forceinline__ float sigf(float x){ return 1.0f/(1.0f+expf(-x)); }
__device__ __forceinline__ float logsigf(float x){ return fminf(x,0.0f) - log1pf(expf(-fabsf(x))); }
__device__ __forceinline__ float geluf(float x){
    float x3 = x*x*x;
    return 0.5f*x*(1.0f+tanhf(0.7978845608028654f*(x+0.044715f*x3)));
}

// ---------------- embedding --------------------------------------------------
__global__ void k_embed(const int* __restrict__ x, const float* __restrict__ emb){
    int t = blockIdx.x;
    g_h[t*Dd + threadIdx.x] = emb[x[t]*Dd + threadIdx.x];
}

// ---------------- layernorm (warp per token, D=128) --------------------------
__global__ void k_ln(const float* __restrict__ in, const float* __restrict__ w,
                     float* __restrict__ out){
    int warp = (blockIdx.x*blockDim.x + threadIdx.x) >> 5;
    int lane = threadIdx.x & 31;
    if (warp >= Tt) return;
    const float* xp = in + (size_t)warp*Dd;
    float v0=xp[lane], v1=xp[lane+32], v2=xp[lane+64], v3=xp[lane+96];
    float s  = v0+v1+v2+v3;
    float ss = v0*v0+v1*v1+v2*v2+v3*v3;
    #pragma unroll
    for(int o=16;o;o>>=1){ s += __shfl_xor_sync(~0u,s,o); ss += __shfl_xor_sync(~0u,ss,o); }
    float mu  = s*(1.0f/Dd);
    float var = ss*(1.0f/Dd) - mu*mu;
    float r   = rsqrtf(var + 1e-5f);
    float* op = out + (size_t)warp*Dd;
    op[lane]    = (v0-mu)*r*w[lane];
    op[lane+32] = (v1-mu)*r*w[lane+32];
    op[lane+64] = (v2-mu)*r*w[lane+64];
    op[lane+96] = (v3-mu)*r*w[lane+96];
}

// ---------------- SGEMM 128x128x16, 256 thr, 8x8 microtile, double-buffered --
// warps 4x2 (wm 0-3, wn 0-1); lanes 4x8 (lm 0-3, ln 0-7); split 4+4 fragments.
template<bool ADD, bool BIAS>
__global__ void __launch_bounds__(256) k_gemm(
        const float* __restrict__ A, const float* __restrict__ W,
        float* __restrict__ C, const float* __restrict__ bias,
        int M, int N, int K){
    __shared__ float As[2][16][128];
    __shared__ float Bs[2][16][128];
    const int tid = threadIdx.x;
    const int bm = blockIdx.y*128, bn = blockIdx.x*128;
    const int wid = tid >> 5, lane = tid & 31;
    const int wm = wid & 3, wn = wid >> 2;
    const int lm = lane & 3, ln = lane >> 2;
    const int ra0 = wm*32 + lm*4, ra1 = ra0 + 16;
    const int cb0 = wn*64 + ln*4, cb1 = cb0 + 32;

    const int ar = tid >> 1, ac = (tid & 1)*8;   // A: 128 rows x 16 cols, 2 thr/row
    const int br = tid >> 4, bc = (tid & 15)*8;  // B: 16 rows x 128 cols

    const float* Ap = A + (size_t)(bm+ar)*K + ac;
    const float* Wp = W + bn + bc;

    float acc[8][8] = {};

    #define LOADSTAGE(buf, k0) do {                                              \
        float4 va0 = *(const float4*)(Ap + (k0));                                \
        float4 va1 = *(const float4*)(Ap + (k0) + 4);                            \
        As[buf][ac  ][ar]=va0.x; As[buf][ac+1][ar]=va0.y;                        \
        As[buf][ac+2][ar]=va0.z; As[buf][ac+3][ar]=va0.w;                        \
        As[buf][ac+4][ar]=va1.x; As[buf][ac+5][ar]=va1.y;                        \
        As[buf][ac+6][ar]=va1.z; As[buf][ac+7][ar]=va1.w;                        \
        *(float4*)&Bs[buf][br][bc]   = *(const float4*)(Wp + (size_t)((k0)+br)*N);   \
        *(float4*)&Bs[buf][br][bc+4] = *(const float4*)(Wp + (size_t)((k0)+br)*N + 4);\
    } while(0)

    LOADSTAGE(0, 0);
    __syncthreads();
    const int nstage = K >> 4;
    for (int st=0; st<nstage; st++){
        int cur = st & 1;
        if (st+1 < nstage){ LOADSTAGE(cur^1, (st+1)*16); }
        #pragma unroll
        for(int k=0;k<16;k++){
            float4 a0 = *(const float4*)&As[cur][k][ra0];
            float4 a1 = *(const float4*)&As[cur][k][ra1];
            float4 b0 = *(const float4*)&Bs[cur][k][cb0];
            float4 b1 = *(const float4*)&Bs[cur][k][cb1];
            float av[8]={a0.x,a0.y,a0.z,a0.w,a1.x,a1.y,a1.z,a1.w};
            float bv[8]={b0.x,b0.y,b0.z,b0.w,b1.x,b1.y,b1.z,b1.w};
            #pragma unroll
            for(int i=0;i<8;i++)
                #pragma unroll
                for(int j=0;j<8;j++) acc[i][j] += av[i]*bv[j];
        }
        __syncthreads();
    }
    #undef LOADSTAGE

    #pragma unroll
    for(int i=0;i<8;i++){
        int row = bm + ((i<4) ? (ra0 + i) : (ra1 + i - 4));
        float* cp0 = C + (size_t)row*N + bn + cb0;
        float* cp1 = C + (size_t)row*N + bn + cb1;
        float4 v0 = make_float4(acc[i][0],acc[i][1],acc[i][2],acc[i][3]);
        float4 v1 = make_float4(acc[i][4],acc[i][5],acc[i][6],acc[i][7]);
        if (BIAS){
            v0.x += bias[bn+cb0]; v0.y += bias[bn+cb0+1]; v0.z += bias[bn+cb0+2]; v0.w += bias[bn+cb0+3];
            v1.x += bias[bn+cb1]; v1.y += bias[bn+cb1+1]; v1.z += bias[bn+cb1+2]; v1.w += bias[bn+cb1+3];
        }
        if (ADD){
            float4 o0 = *(const float4*)cp0, o1 = *(const float4*)cp1;
            v0.x += o0.x; v0.y += o0.y; v0.z += o0.z; v0.w += o0.w;
            v1.x += o1.x; v1.y += o1.y; v1.z += o1.z; v1.w += o1.w;
        }
        *(float4*)cp0 = v0;
        *(float4*)cp1 = v1;
    }
}

// ---------------- sLSTM gate projection gx[s][b][g][n*32+e] ------------------
__global__ void k_sgx(const float* __restrict__ xln, const float* __restrict__ gw,
                      const float* __restrict__ bias){
    int t = blockIdx.x; int b = t/Ss, s = t%Ss;
    __shared__ float xs[Dd];
    if (threadIdx.x < Dd) xs[threadIdx.x] = xln[(size_t)t*Dd + threadIdx.x];
    __syncthreads();
    for(int o = threadIdx.x; o < 4*Dd; o += blockDim.x){
        int g  = o >> 7;
        int ne = o & 127;
        int n  = ne >> 5, e = ne & 31;
        const float* wp = gw + (((g*NHs + n)*HDs + e)*HDs);
        const float* xp = xs + n*HDs;
        float acc = bias[g*Dd + ne];
        #pragma unroll
        for(int d=0; d<HDs; d++) acc += xp[d]*wp[d];
        g_big[((size_t)(s*Bb + b)*4 + g)*Dd + ne] = acc;
    }
}

// ---------------- sLSTM recurrence scan: 8 warps/block, shared weights -------
__global__ void __launch_bounds__(256) k_scan(const float* __restrict__ rec){
    int n  = blockIdx.x & 3;
    int bg = blockIdx.x >> 2;           // 0..63
    int w  = threadIdx.x >> 5;
    int e  = threadIdx.x & 31;
    int b  = bg*8 + w;
    __shared__ float rw[4][HDs][36];
    __shared__ float hs[8][HDs];
    for (int idx = threadIdx.x; idx < 4*HDs*HDs; idx += 256){
        int g = idx >> 10, rem = idx & 1023;
        int e2 = rem >> 5, d = rem & 31;
        rw[g][e2][d] = rec[((size_t)(g*NHs+n)*HDs + e2)*HDs + d];
    }
    hs[w][e] = 0.0f;
    __syncthreads();
    float c=0.0f, nn=0.0f, m=0.0f;
    const int gb = n*HDs + e;
    for(int s=0;s<Ss;s++){
        const float* gxp = g_big + ((size_t)(s*Bb + b)*4)*Dd + gb;
        float r0=gxp[0], r1=gxp[Dd], r2=gxp[2*Dd], r3=gxp[3*Dd];
        #pragma unroll
        for(int dq=0; dq<8; dq++){
            float4 hv = *(const float4*)&hs[w][dq*4];
            float4 w0 = *(const float4*)&rw[0][e][dq*4];
            float4 w1 = *(const float4*)&rw[1][e][dq*4];
            float4 w2 = *(const float4*)&rw[2][e][dq*4];
            float4 w3 = *(const float4*)&rw[3][e][dq*4];
            r0 += hv.x*w0.x + hv.y*w0.y + hv.z*w0.z + hv.w*w0.w;
            r1 += hv.x*w1.x + hv.y*w1.y + hv.z*w1.z + hv.w*w1.w;
            r2 += hv.x*w2.x + hv.y*w2.y + hv.z*w2.z + hv.w*w2.w;
            r3 += hv.x*w3.x + hv.y*w3.y + hv.z*w3.z + hv.w*w3.w;
        }
        float lfm = m + logsigf(r1);
        float mn  = fmaxf(r0, lfm);
        float i   = expf(r0-mn);
        float f   = expf(lfm-mn);
        c  = f*c + i*tanhf(r2);
        nn = f*nn + i;
        float hnew = sigf(r3) * c / nn;
        m = mn;
        __syncwarp();
        hs[w][e] = hnew;
        __syncwarp();
        g_y[((size_t)(b*Ss+s))*Dd + gb] = hnew;
    }
}

// ---------------- sLSTM group norm (G=32) + residual add into g_h ------------
__global__ void k_gn_slstm(const float* __restrict__ gn){
    int t = blockIdx.x;
    int n = threadIdx.x >> 5, lane = threadIdx.x & 31;
    float v = g_y[(size_t)t*Dd + n*HDs + lane];
    float s=v, ss=v*v;
    #pragma unroll
    for(int o=16;o;o>>=1){ s += __shfl_xor_sync(~0u,s,o); ss += __shfl_xor_sync(~0u,ss,o); }
    float mu = s*(1.0f/HDs), var = ss*(1.0f/HDs)-mu*mu;
    float r = rsqrtf(var + 1e-5f);
    g_h[(size_t)t*Dd + n*HDs + lane] += (v-mu)*r*gn[n*HDs+lane];
}

// ---------------- FFN gate activation: gelu(g)*u (float4) --------------------
__global__ void k_glu(){
    int i = blockIdx.x*blockDim.x + threadIdx.x;   // over Tt*FFc/4
    if (i >= Tt*FFc/4) return;
    int t = i/(FFc/4), f4 = i%(FFc/4);
    const float4 g4 = *(const float4*)&g_ffn[(size_t)t*2*FFc + f4*4];
    const float4 u4 = *(const float4*)&g_ffn[(size_t)t*2*FFc + FFc + f4*4];
    float4 o;
    o.x = geluf(g4.x)*u4.x; o.y = geluf(g4.y)*u4.y;
    o.z = geluf(g4.z)*u4.z; o.w = geluf(g4.w)*u4.w;
    *(float4*)&g_y[(size_t)t*FFc + f4*4] = o;
}

// ---------------- mLSTM causal depthwise conv + silu -------------------------
__global__ void k_conv(const float* __restrict__ cw, const float* __restrict__ cb){
    int t = blockIdx.x; int c = threadIdx.x;
    int b = t/Ss, s = t%Ss;
    float acc = cb[c];
    #pragma unroll
    for(int tt=0; tt<Kc; tt++){
        int si = s - (Kc-1) + tt;
        if (si >= 0) acc += g_big[((size_t)(b*Ss+si))*2*INNERc + c]*cw[c*Kc+tt];
    }
    g_xconv[(size_t)t*INNERc + c] = acc*sigf(acc);
}

// ---------------- blocked qkv projections ------------------------------------
__global__ void k_qkv(const float* __restrict__ w){
    int t = blockIdx.x; int c = threadIdx.x;
    int n = c >> 2, o = c & 3;
    const float* wq = w + n*16 + o*4;
    const float* wk = wq + NBc*16;
    const float* wv = wk + NBc*16;
    const float* xc = g_xconv + (size_t)t*INNERc + n*4;
    const float* xm = g_big   + (size_t)t*2*INNERc + n*4;
    float q=0,k=0,v=0;
    #pragma unroll
    for(int i=0;i<4;i++){ q += xc[i]*wq[i]; k += xc[i]*wk[i]; v += xm[i]*wv[i]; }
    g_q[(size_t)t*INNERc+c]=q; g_k[(size_t)t*INNERc+c]=k; g_v[(size_t)t*INNERc+c]=v;
}

// ---------------- input/forget gate projections ------------------------------
__global__ void k_gates(const float* __restrict__ igw, const float* __restrict__ igb,
                        const float* __restrict__ fgw, const float* __restrict__ fgb){
    int t = blockIdx.x;
    int hm = threadIdx.x >> 5, lane = threadIdx.x & 31;
    int b = t/Ss, s = t%Ss;
    float ia=0, fa=0;
    for(int j=lane; j<3*INNERc; j+=32){
        float val = (j < INNERc)   ? g_q[(size_t)t*INNERc + j]
                  : (j < 2*INNERc) ? g_k[(size_t)t*INNERc + j - INNERc]
                                   : g_v[(size_t)t*INNERc + j - 2*INNERc];
        ia += val*igw[j*NHMc + hm];
        fa += val*fgw[j*NHMc + hm];
    }
    #pragma unroll
    for(int o=16;o;o>>=1){ ia += __shfl_xor_sync(~0u,ia,o); fa += __shfl_xor_sync(~0u,fa,o); }
    if (lane == 0){
        g_ig[(size_t)(b*NHMc+hm)*Ss + s] = ia + igb[hm];
        g_fg[(size_t)(b*NHMc+hm)*Ss + s] = fa + fgb[hm];
    }
}

// ---------------- mLSTM attention: block per (b, head) -----------------------
__global__ void __launch_bounds__(256) k_attn(){
    int blk = blockIdx.x; int b = blk >> 2, hm = blk & 3;
    __shared__ float qs[Ss][DHMc+1], ks[Ss][DHMc+1];
    __shared__ float cldf[Ss+1], igs[Ss];
    __shared__ float cn[8][Ss];
    int tid = threadIdx.x;
    for(int l=tid; l<Ss*DHMc; l+=256){
        int j = l >> 6, d = l & 63;
        qs[j][d] = g_q[((size_t)(b*Ss+j))*INNERc + hm*DHMc + d];
        ks[j][d] = g_k[((size_t)(b*Ss+j))*INNERc + hm*DHMc + d];
    }
    if (tid < Ss) igs[tid] = g_ig[(size_t)(b*NHMc+hm)*Ss + tid];
    if (tid == 0){
        float cacc = 0.0f; cldf[0] = 0.0f;
        for(int s=0;s<Ss;s++){ cacc += logsigf(g_fg[(size_t)(b*NHMc+hm)*Ss + s]); cldf[s+1]=cacc; }
    }
    __syncthreads();
    int w = tid >> 5, lane = tid & 31;
    const float* vp = g_v + (size_t)b*Ss*INNERc + hm*DHMc;
    for(int r=0;r<8;r++){
        int i = w*8 + r;
        int j1 = lane + 32;
        float dot0=0, dot1=0, ld0=-1e30f, ld1=-1e30f;
        if (lane <= i){
            #pragma unroll
            for(int d=0; d<DHMc; d++) dot0 += qs[i][d]*ks[lane][d];
            ld0 = cldf[i+1]-cldf[lane+1] + igs[lane];
        }
        if (j1 <= i){
            #pragma unroll
            for(int d=0; d<DHMc; d++) dot1 += qs[i][d]*ks[j1][d];
            ld1 = cldf[i+1]-cldf[j1+1] + igs[j1];
        }
        float mx = fmaxf(ld0, ld1);
        #pragma unroll
        for(int o=16;o;o>>=1) mx = fmaxf(mx, __shfl_xor_sync(~0u,mx,o));
        float cm0 = (lane <= i) ? dot0*0.125f*expf(ld0-mx) : 0.0f;
        float cm1 = (j1   <= i) ? dot1*0.125f*expf(ld1-mx) : 0.0f;
        float sm = cm0 + cm1;
        #pragma unroll
        for(int o=16;o;o>>=1) sm += __shfl_xor_sync(~0u,sm,o);
        float norm = fmaxf(fabsf(sm), expf(-mx)) + 1e-6f;
        cn[w][lane] = cm0/norm;
        cn[w][j1]   = cm1/norm;
        __syncwarp();
        float a0=0, a1=0;
        for(int j=0;j<=i;j++){
            float cc = cn[w][j];
            a0 += cc*vp[(size_t)j*INNERc + lane];
            a1 += cc*vp[(size_t)j*INNERc + lane + 32];
        }
        g_hatt[((size_t)(b*Ss+i))*INNERc + hm*DHMc + lane]      = a0;
        g_hatt[((size_t)(b*Ss+i))*INNERc + hm*DHMc + lane + 32] = a1;
        __syncwarp();
    }
}

// ---------------- mLSTM groupnorm (G=64) + skip/silu combine -----------------
__global__ void k_gn_comb(const float* __restrict__ onw, const float* __restrict__ skip){
    int t = blockIdx.x;
    int hm = threadIdx.x >> 5, lane = threadIdx.x & 31;
    size_t base = (size_t)t*INNERc + hm*DHMc;
    float v0 = g_hatt[base+lane], v1 = g_hatt[base+lane+32];
    float s = v0+v1, ss = v0*v0+v1*v1;
    #pragma unroll
    for(int o=16;o;o>>=1){ s += __shfl_xor_sync(~0u,s,o); ss += __shfl_xor_sync(~0u,ss,o); }
    float mu = s*(1.0f/DHMc), var = ss*(1.0f/DHMc)-mu*mu;
    float r = rsqrtf(var + 1e-5f);
    #pragma unroll
    for(int p=0;p<2;p++){
        int c = hm*DHMc + lane + p*32;
        float v = p ? v1 : v0;
        float z = g_big[(size_t)t*2*INNERc + INNERc + c];
        float out = ((v-mu)*r*onw[c] + skip[c]*g_xconv[(size_t)t*INNERc + c]) * z*sigf(z);
        g_q[(size_t)t*INNERc + c] = out;   // reuse g_q as combine buffer
    }
}

// ---------------- host-side --------------------------------------------------
static float* symf(const void* s){ void* p=nullptr; cudaGetSymbolAddress(&p, s); return (float*)p; }

extern "C" void kernel_launch(void* const* d_in, const int* in_sizes, int n_in,
                              void* d_out, int out_size){
    const int*   x         = (const int*)  d_in[0];
    const float* embed     = (const float*)d_in[1];
    const float* s_ln1     = (const float*)d_in[2];
    const float* s_gates_w = (const float*)d_in[3];
    const float* s_rec     = (const float*)d_in[4];
    const float* s_bias    = (const float*)d_in[5];
    const float* s_gn      = (const float*)d_in[6];
    const float* s_ln2     = (const float*)d_in[7];
    const float* s_ff_up   = (const float*)d_in[8];
    const float* s_ff_down = (const float*)d_in[9];
    const float* m_ln1     = (const float*)d_in[10];
    const float* m_up      = (const float*)d_in[11];
    const float* m_conv_w  = (const float*)d_in[12];
    const float* m_conv_b  = (const float*)d_in[13];
    const float* m_qkv_w   = (const float*)d_in[14];
    const float* m_ig_w    = (const float*)d_in[15];
    const float* m_ig_b    = (const float*)d_in[16];
    const float* m_fg_w    = (const float*)d_in[17];
    const float* m_fg_b    = (const float*)d_in[18];
    const float* m_skip    = (const float*)d_in[19];
    const float* m_onorm   = (const float*)d_in[20];
    const float* m_down    = (const float*)d_in[21];
    const float* m_ln2     = (const float*)d_in[22];
    const float* m_ff_up   = (const float*)d_in[23];
    const float* m_ff_down = (const float*)d_in[24];
    const float* post_ln   = (const float*)d_in[25];
    const float* head_w    = (const float*)d_in[26];
    const float* head_b    = (const float*)d_in[27];

    float* h    = symf(g_h);
    float* xln  = symf(g_xln);
    float* big  = symf(g_big);
    float* y    = symf(g_y);
    float* ffn  = symf(g_ffn);
    float* qb   = symf(g_q);

    float* out = (float*)d_out;

    k_embed<<<Tt, Dd>>>(x, embed);

    for(int i=0;i<2;i++){
        // ---- sLSTM block ----
        k_ln<<<Tt/8,256>>>(h, s_ln1 + i*Dd, xln);
        k_sgx<<<Tt,256>>>(xln, s_gates_w + (size_t)i*4*NHs*HDs*HDs, s_bias + i*4*Dd);
        k_scan<<<NHs*(Bb/8),256>>>(s_rec + (size_t)i*4*NHs*HDs*HDs);
        k_gn_slstm<<<Tt,128>>>(s_gn + i*Dd);

        // ---- FFN 1 ----
        k_ln<<<Tt/8,256>>>(h, s_ln2 + i*Dd, xln);
        k_gemm<false,false><<<dim3(2*FFc/128, Tt/128),256>>>(xln, s_ff_up + (size_t)i*Dd*2*FFc, ffn, nullptr, Tt, 2*FFc, Dd);
        k_glu<<<(Tt*FFc/4+255)/256,256>>>();
        k_gemm<true ,false><<<dim3(Dd/128,   Tt/128),256>>>(y,  s_ff_down + (size_t)i*FFc*Dd, h, nullptr, Tt, Dd, FFc);

        // ---- mLSTM block ----
        k_ln<<<Tt/8,256>>>(h, m_ln1 + i*Dd, xln);
        k_gemm<false,false><<<dim3(2*INNERc/128, Tt/128),256>>>(xln, m_up + (size_t)i*Dd*2*INNERc, big, nullptr, Tt, 2*INNERc, Dd);
        k_conv<<<Tt,INNERc>>>(m_conv_w + (size_t)i*INNERc*Kc, m_conv_b + i*INNERc);
        k_qkv<<<Tt,INNERc>>>(m_qkv_w + (size_t)i*3*NBc*16);
        k_gates<<<Tt,128>>>(m_ig_w + (size_t)i*3*INNERc*NHMc, m_ig_b + i*NHMc,
                            m_fg_w + (size_t)i*3*INNERc*NHMc, m_fg_b + i*NHMc);
        k_attn<<<Bb*NHMc,256>>>();
        k_gn_comb<<<Tt,128>>>(m_onorm + i*INNERc, m_skip + i*INNERc);
        k_gemm<true ,false><<<dim3(Dd/128, Tt/128),256>>>(qb, m_down + (size_t)i*INNERc*Dd, h, nullptr, Tt, Dd, INNERc);

        // ---- FFN 2 ----
        k_ln<<<Tt/8,256>>>(h, m_ln2 + i*Dd, xln);
        k_gemm<false,false><<<dim3(2*FFc/128, Tt/128),256>>>(xln, m_ff_up + (size_t)i*Dd*2*FFc, ffn, nullptr, Tt, 2*FFc, Dd);
        k_glu<<<(Tt*FFc/4+255)/256,256>>>();
        k_gemm<true ,false><<<dim3(Dd/128,   Tt/128),256>>>(y, m_ff_down + (size_t)i*FFc*Dd, h, nullptr, Tt, Dd, FFc);
    }

    // ---- final LN + head ----
    k_ln<<<Tt/8,256>>>(h, post_ln, xln);
    k_gemm<false,true><<<dim3(Vv/128, Tt/128),256>>>(xln, head_w, out, head_b, Tt, Vv, Dd);
}

// round 4
// speedup vs baseline: 3.4790x; 2.8856x over previous
#include <cuda_runtime.h>
#include <math.h>

#define Bb     512
#define Ss     64
#define Dd     128
#define Vv     256
#define NHs    4
#define HDs    32
#define INNERc 256
#define NHMc   4
#define DHMc   64
#define NBc    64
#define Kc     4
#define FFc    128
#define Tt     (Bb*Ss)   /* 32768 tokens */

// ---------------- workspaces (static device globals; no allocation) ----------
__device__ float g_h[Tt*Dd];            // residual stream
__device__ float g_xln[Tt*Dd];          // LN output
__device__ float g_big[Tt*2*INNERc];    // slstm gx [t][4][128]  OR  mlstm up out [t][512]
__device__ float g_y[Tt*Dd];            // slstm y / ffn activation
__device__ float g_ffn[Tt*2*FFc];       // ffn up output
__device__ float g_xconv[Tt*INNERc];
__device__ float g_q[Tt*INNERc];        // q, later reused as mlstm combine buffer
__device__ float g_k[Tt*INNERc];
__device__ float g_v[Tt*INNERc];
__device__ float g_hatt[Tt*INNERc];
__device__ float g_ig[Bb*NHMc*Ss];
__device__ float g_fg[Bb*NHMc*Ss];
__device__ float g_wd[Dd*4*Dd];         // densified slstm gate weights [128][512]

// ---------------- device math helpers ---------------------------------------
__device__ __forceinline__ float sigf(float x){ return 1.0f/(1.0f+expf(-x)); }
__device__ __forceinline__ float logsigf(float x){ return fminf(x,0.0f) - log1pf(expf(-fabsf(x))); }
__device__ __forceinline__ float geluf(float x){
    float x3 = x*x*x;
    return 0.5f*x*(1.0f+tanhf(0.7978845608028654f*(x+0.044715f*x3)));
}

// ---------------- embedding --------------------------------------------------
__global__ void k_embed(const int* __restrict__ x, const float* __restrict__ emb){
    int t = blockIdx.x;
    g_h[t*Dd + threadIdx.x] = emb[x[t]*Dd + threadIdx.x];
}

// ---------------- layernorm (warp per token, D=128) --------------------------
__global__ void k_ln(const float* __restrict__ in, const float* __restrict__ w,
                     float* __restrict__ out){
    int warp = (blockIdx.x*blockDim.x + threadIdx.x) >> 5;
    int lane = threadIdx.x & 31;
    if (warp >= Tt) return;
    const float* xp = in + (size_t)warp*Dd;
    float v0=xp[lane], v1=xp[lane+32], v2=xp[lane+64], v3=xp[lane+96];
    float s  = v0+v1+v2+v3;
    float ss = v0*v0+v1*v1+v2*v2+v3*v3;
    #pragma unroll
    for(int o=16;o;o>>=1){ s += __shfl_xor_sync(~0u,s,o); ss += __shfl_xor_sync(~0u,ss,o); }
    float mu  = s*(1.0f/Dd);
    float var = ss*(1.0f/Dd) - mu*mu;
    float r   = rsqrtf(var + 1e-5f);
    float* op = out + (size_t)warp*Dd;
    op[lane]    = (v0-mu)*r*w[lane];
    op[lane+32] = (v1-mu)*r*w[lane+32];
    op[lane+64] = (v2-mu)*r*w[lane+64];
    op[lane+96] = (v3-mu)*r*w[lane+96];
}

// ---------------- SGEMM 128x128x16, 256 thr, 8x8 microtile, double-buffered --
template<bool ADD, bool BIAS>
__global__ void __launch_bounds__(256) k_gemm(
        const float* __restrict__ A, const float* __restrict__ W,
        float* __restrict__ C, const float* __restrict__ bias,
        int M, int N, int K){
    __shared__ float As[2][16][128];
    __shared__ float Bs[2][16][128];
    const int tid = threadIdx.x;
    const int bm = blockIdx.y*128, bn = blockIdx.x*128;
    const int wid = tid >> 5, lane = tid & 31;
    const int wm = wid & 3, wn = wid >> 2;
    const int lm = lane & 3, ln = lane >> 2;
    const int ra0 = wm*32 + lm*4, ra1 = ra0 + 16;
    const int cb0 = wn*64 + ln*4, cb1 = cb0 + 32;

    const int ar = tid >> 1, ac = (tid & 1)*8;   // A: 128 rows x 16 cols
    const int br = tid >> 4, bc = (tid & 15)*8;  // B: 16 rows x 128 cols

    const float* Ap = A + (size_t)(bm+ar)*K + ac;
    const float* Wp = W + bn + bc;

    float acc[8][8] = {};

    #define LOADSTAGE(buf, k0) do {                                              \
        float4 va0 = *(const float4*)(Ap + (k0));                                \
        float4 va1 = *(const float4*)(Ap + (k0) + 4);                            \
        As[buf][ac  ][ar]=va0.x; As[buf][ac+1][ar]=va0.y;                        \
        As[buf][ac+2][ar]=va0.z; As[buf][ac+3][ar]=va0.w;                        \
        As[buf][ac+4][ar]=va1.x; As[buf][ac+5][ar]=va1.y;                        \
        As[buf][ac+6][ar]=va1.z; As[buf][ac+7][ar]=va1.w;                        \
        *(float4*)&Bs[buf][br][bc]   = *(const float4*)(Wp + (size_t)((k0)+br)*N);   \
        *(float4*)&Bs[buf][br][bc+4] = *(const float4*)(Wp + (size_t)((k0)+br)*N + 4);\
    } while(0)

    LOADSTAGE(0, 0);
    __syncthreads();
    const int nstage = K >> 4;
    for (int st=0; st<nstage; st++){
        int cur = st & 1;
        if (st+1 < nstage){ LOADSTAGE(cur^1, (st+1)*16); }
        #pragma unroll
        for(int k=0;k<16;k++){
            float4 a0 = *(const float4*)&As[cur][k][ra0];
            float4 a1 = *(const float4*)&As[cur][k][ra1];
            float4 b0 = *(const float4*)&Bs[cur][k][cb0];
            float4 b1 = *(const float4*)&Bs[cur][k][cb1];
            float av[8]={a0.x,a0.y,a0.z,a0.w,a1.x,a1.y,a1.z,a1.w};
            float bv[8]={b0.x,b0.y,b0.z,b0.w,b1.x,b1.y,b1.z,b1.w};
            #pragma unroll
            for(int i=0;i<8;i++)
                #pragma unroll
                for(int j=0;j<8;j++) acc[i][j] += av[i]*bv[j];
        }
        __syncthreads();
    }
    #undef LOADSTAGE

    #pragma unroll
    for(int i=0;i<8;i++){
        int row = bm + ((i<4) ? (ra0 + i) : (ra1 + i - 4));
        float* cp0 = C + (size_t)row*N + bn + cb0;
        float* cp1 = C + (size_t)row*N + bn + cb1;
        float4 v0 = make_float4(acc[i][0],acc[i][1],acc[i][2],acc[i][3]);
        float4 v1 = make_float4(acc[i][4],acc[i][5],acc[i][6],acc[i][7]);
        if (BIAS){
            v0.x += bias[bn+cb0]; v0.y += bias[bn+cb0+1]; v0.z += bias[bn+cb0+2]; v0.w += bias[bn+cb0+3];
            v1.x += bias[bn+cb1]; v1.y += bias[bn+cb1+1]; v1.z += bias[bn+cb1+2]; v1.w += bias[bn+cb1+3];
        }
        if (ADD){
            float4 o0 = *(const float4*)cp0, o1 = *(const float4*)cp1;
            v0.x += o0.x; v0.y += o0.y; v0.z += o0.z; v0.w += o0.w;
            v1.x += o1.x; v1.y += o1.y; v1.z += o1.z; v1.w += o1.w;
        }
        *(float4*)cp0 = v0;
        *(float4*)cp1 = v1;
    }
}

// ---------------- densify slstm gate weights: W_dense[d][(g,n,e)] ------------
__global__ void k_sgx_prep(const float* __restrict__ gw){
    int idx = blockIdx.x*blockDim.x + threadIdx.x;   // over 128*512
    if (idx >= Dd*4*Dd) return;
    int d = idx >> 9;          // 0..127
    int o = idx & 511;         // (g, n, e)
    int g = o >> 7;
    int ne = o & 127;
    int n = ne >> 5, e = ne & 31;
    float w = 0.0f;
    if ((d >> 5) == n) w = gw[(((g*NHs + n)*HDs + e)*HDs) + (d & 31)];
    g_wd[(size_t)d*512 + o] = w;
}

// ---------------- sLSTM recurrence scan: 8 warps/block, shared weights -------
__global__ void __launch_bounds__(256) k_scan(const float* __restrict__ rec){
    int n  = blockIdx.x & 3;
    int bg = blockIdx.x >> 2;           // 0..63
    int w  = threadIdx.x >> 5;
    int e  = threadIdx.x & 31;
    int b  = bg*8 + w;
    __shared__ float rw[4][HDs][36];
    __shared__ float hs[8][HDs];
    for (int idx = threadIdx.x; idx < 4*HDs*HDs; idx += 256){
        int g = idx >> 10, rem = idx & 1023;
        int e2 = rem >> 5, d = rem & 31;
        rw[g][e2][d] = rec[((size_t)(g*NHs+n)*HDs + e2)*HDs + d];
    }
    hs[w][e] = 0.0f;
    __syncthreads();
    float c=0.0f, nn=0.0f, m=0.0f;
    const int gb = n*HDs + e;
    for(int s=0;s<Ss;s++){
        const float* gxp = g_big + (size_t)(b*Ss + s)*512 + gb;   // token-major
        float r0=gxp[0], r1=gxp[Dd], r2=gxp[2*Dd], r3=gxp[3*Dd];
        #pragma unroll
        for(int dq=0; dq<8; dq++){
            float4 hv = *(const float4*)&hs[w][dq*4];
            float4 w0 = *(const float4*)&rw[0][e][dq*4];
            float4 w1 = *(const float4*)&rw[1][e][dq*4];
            float4 w2 = *(const float4*)&rw[2][e][dq*4];
            float4 w3 = *(const float4*)&rw[3][e][dq*4];
            r0 += hv.x*w0.x + hv.y*w0.y + hv.z*w0.z + hv.w*w0.w;
            r1 += hv.x*w1.x + hv.y*w1.y + hv.z*w1.z + hv.w*w1.w;
            r2 += hv.x*w2.x + hv.y*w2.y + hv.z*w2.z + hv.w*w2.w;
            r3 += hv.x*w3.x + hv.y*w3.y + hv.z*w3.z + hv.w*w3.w;
        }
        float lfm = m + logsigf(r1);
        float mn  = fmaxf(r0, lfm);
        float i   = expf(r0-mn);
        float f   = expf(lfm-mn);
        c  = f*c + i*tanhf(r2);
        nn = f*nn + i;
        float hnew = sigf(r3) * c / nn;
        m = mn;
        __syncwarp();
        hs[w][e] = hnew;
        __syncwarp();
        g_y[((size_t)(b*Ss+s))*Dd + gb] = hnew;
    }
}

// ---------------- sLSTM group norm (G=32) + residual add into g_h ------------
__global__ void k_gn_slstm(const float* __restrict__ gn){
    int t = blockIdx.x;
    int n = threadIdx.x >> 5, lane = threadIdx.x & 31;
    float v = g_y[(size_t)t*Dd + n*HDs + lane];
    float s=v, ss=v*v;
    #pragma unroll
    for(int o=16;o;o>>=1){ s += __shfl_xor_sync(~0u,s,o); ss += __shfl_xor_sync(~0u,ss,o); }
    float mu = s*(1.0f/HDs), var = ss*(1.0f/HDs)-mu*mu;
    float r = rsqrtf(var + 1e-5f);
    g_h[(size_t)t*Dd + n*HDs + lane] += (v-mu)*r*gn[n*HDs+lane];
}

// ---------------- FFN gate activation: gelu(g)*u (float4) --------------------
__global__ void k_glu(){
    int i = blockIdx.x*blockDim.x + threadIdx.x;   // over Tt*FFc/4
    if (i >= Tt*FFc/4) return;
    int t = i/(FFc/4), f4 = i%(FFc/4);
    const float4 g4 = *(const float4*)&g_ffn[(size_t)t*2*FFc + f4*4];
    const float4 u4 = *(const float4*)&g_ffn[(size_t)t*2*FFc + FFc + f4*4];
    float4 o;
    o.x = geluf(g4.x)*u4.x; o.y = geluf(g4.y)*u4.y;
    o.z = geluf(g4.z)*u4.z; o.w = geluf(g4.w)*u4.w;
    *(float4*)&g_y[(size_t)t*FFc + f4*4] = o;
}

// ---------------- mLSTM causal depthwise conv + silu -------------------------
__global__ void k_conv(const float* __restrict__ cw, const float* __restrict__ cb){
    int t = blockIdx.x; int c = threadIdx.x;
    int b = t/Ss, s = t%Ss;
    float acc = cb[c];
    #pragma unroll
    for(int tt=0; tt<Kc; tt++){
        int si = s - (Kc-1) + tt;
        if (si >= 0) acc += g_big[((size_t)(b*Ss+si))*2*INNERc + c]*cw[c*Kc+tt];
    }
    g_xconv[(size_t)t*INNERc + c] = acc*sigf(acc);
}

// ---------------- blocked qkv projections ------------------------------------
__global__ void k_qkv(const float* __restrict__ w){
    int t = blockIdx.x; int c = threadIdx.x;
    int n = c >> 2, o = c & 3;
    const float* wq = w + n*16 + o*4;
    const float* wk = wq + NBc*16;
    const float* wv = wk + NBc*16;
    const float* xc = g_xconv + (size_t)t*INNERc + n*4;
    const float* xm = g_big   + (size_t)t*2*INNERc + n*4;
    float q=0,k=0,v=0;
    #pragma unroll
    for(int i=0;i<4;i++){ q += xc[i]*wq[i]; k += xc[i]*wk[i]; v += xm[i]*wv[i]; }
    g_q[(size_t)t*INNERc+c]=q; g_k[(size_t)t*INNERc+c]=k; g_v[(size_t)t*INNERc+c]=v;
}

// ---------------- input/forget gates: 32 tokens/block, weights in smem -------
__global__ void __launch_bounds__(256) k_gates(
        const float* __restrict__ igw, const float* __restrict__ igb,
        const float* __restrict__ fgw, const float* __restrict__ fgb){
    __shared__ float4 iws[3*INNERc];
    __shared__ float4 fws[3*INNERc];
    for (int j = threadIdx.x; j < 3*INNERc; j += 256){
        iws[j] = *(const float4*)&igw[j*NHMc];
        fws[j] = *(const float4*)&fgw[j*NHMc];
    }
    __syncthreads();
    int w = threadIdx.x >> 5, lane = threadIdx.x & 31;
    int t0 = blockIdx.x*32 + w*4;
    for (int tt = 0; tt < 4; tt++){
        int t = t0 + tt;
        float ia0=0,ia1=0,ia2=0,ia3=0, fa0=0,fa1=0,fa2=0,fa3=0;
        const float* qp = g_q + (size_t)t*INNERc;
        const float* kp = g_k + (size_t)t*INNERc;
        const float* vp = g_v + (size_t)t*INNERc;
        for (int j = lane; j < 3*INNERc; j += 32){
            float val = (j < INNERc) ? qp[j] : (j < 2*INNERc) ? kp[j-INNERc] : vp[j-2*INNERc];
            float4 iw = iws[j], fw = fws[j];
            ia0 += val*iw.x; ia1 += val*iw.y; ia2 += val*iw.z; ia3 += val*iw.w;
            fa0 += val*fw.x; fa1 += val*fw.y; fa2 += val*fw.z; fa3 += val*fw.w;
        }
        #pragma unroll
        for (int o=16;o;o>>=1){
            ia0 += __shfl_xor_sync(~0u,ia0,o); ia1 += __shfl_xor_sync(~0u,ia1,o);
            ia2 += __shfl_xor_sync(~0u,ia2,o); ia3 += __shfl_xor_sync(~0u,ia3,o);
            fa0 += __shfl_xor_sync(~0u,fa0,o); fa1 += __shfl_xor_sync(~0u,fa1,o);
            fa2 += __shfl_xor_sync(~0u,fa2,o); fa3 += __shfl_xor_sync(~0u,fa3,o);
        }
        if (lane == 0){
            int b = t/Ss, s = t%Ss;
            g_ig[(size_t)(b*NHMc+0)*Ss + s] = ia0 + igb[0];
            g_ig[(size_t)(b*NHMc+1)*Ss + s] = ia1 + igb[1];
            g_ig[(size_t)(b*NHMc+2)*Ss + s] = ia2 + igb[2];
            g_ig[(size_t)(b*NHMc+3)*Ss + s] = ia3 + igb[3];
            g_fg[(size_t)(b*NHMc+0)*Ss + s] = fa0 + fgb[0];
            g_fg[(size_t)(b*NHMc+1)*Ss + s] = fa1 + fgb[1];
            g_fg[(size_t)(b*NHMc+2)*Ss + s] = fa2 + fgb[2];
            g_fg[(size_t)(b*NHMc+3)*Ss + s] = fa3 + fgb[3];
        }
    }
}

// ---------------- mLSTM attention: block per (b, head), v in smem ------------
__global__ void __launch_bounds__(256) k_attn(){
    int blk = blockIdx.x; int b = blk >> 2, hm = blk & 3;
    __shared__ float qs[Ss][DHMc+1], ks[Ss][DHMc+1], vs[Ss][DHMc+1];
    __shared__ float cldf[Ss+1], igs[Ss];
    __shared__ float cn[8][Ss];
    int tid = threadIdx.x;
    for(int l=tid; l<Ss*DHMc; l+=256){
        int j = l >> 6, d = l & 63;
        size_t base = ((size_t)(b*Ss+j))*INNERc + hm*DHMc + d;
        qs[j][d] = g_q[base];
        ks[j][d] = g_k[base];
        vs[j][d] = g_v[base];
    }
    if (tid < Ss) igs[tid] = g_ig[(size_t)(b*NHMc+hm)*Ss + tid];
    if (tid == 0){
        float cacc = 0.0f; cldf[0] = 0.0f;
        for(int s=0;s<Ss;s++){ cacc += logsigf(g_fg[(size_t)(b*NHMc+hm)*Ss + s]); cldf[s+1]=cacc; }
    }
    __syncthreads();
    int w = tid >> 5, lane = tid & 31;
    for(int r=0;r<8;r++){
        int i = w*8 + r;
        int j1 = lane + 32;
        float dot0=0, dot1=0, ld0=-1e30f, ld1=-1e30f;
        if (lane <= i){
            #pragma unroll
            for(int d=0; d<DHMc; d++) dot0 += qs[i][d]*ks[lane][d];
            ld0 = cldf[i+1]-cldf[lane+1] + igs[lane];
        }
        if (j1 <= i){
            #pragma unroll
            for(int d=0; d<DHMc; d++) dot1 += qs[i][d]*ks[j1][d];
            ld1 = cldf[i+1]-cldf[j1+1] + igs[j1];
        }
        float mx = fmaxf(ld0, ld1);
        #pragma unroll
        for(int o=16;o;o>>=1) mx = fmaxf(mx, __shfl_xor_sync(~0u,mx,o));
        float cm0 = (lane <= i) ? dot0*0.125f*expf(ld0-mx) : 0.0f;
        float cm1 = (j1   <= i) ? dot1*0.125f*expf(ld1-mx) : 0.0f;
        float sm = cm0 + cm1;
        #pragma unroll
        for(int o=16;o;o>>=1) sm += __shfl_xor_sync(~0u,sm,o);
        float norm = fmaxf(fabsf(sm), expf(-mx)) + 1e-6f;
        cn[w][lane] = cm0/norm;
        cn[w][j1]   = cm1/norm;
        __syncwarp();
        float a0=0, a1=0;
        for(int j=0;j<=i;j++){
            float cc = cn[w][j];
            a0 += cc*vs[j][lane];
            a1 += cc*vs[j][lane+32];
        }
        g_hatt[((size_t)(b*Ss+i))*INNERc + hm*DHMc + lane]      = a0;
        g_hatt[((size_t)(b*Ss+i))*INNERc + hm*DHMc + lane + 32] = a1;
        __syncwarp();
    }
}

// ---------------- mLSTM groupnorm (G=64) + skip/silu combine -----------------
__global__ void k_gn_comb(const float* __restrict__ onw, const float* __restrict__ skip){
    int t = blockIdx.x;
    int hm = threadIdx.x >> 5, lane = threadIdx.x & 31;
    size_t base = (size_t)t*INNERc + hm*DHMc;
    float v0 = g_hatt[base+lane], v1 = g_hatt[base+lane+32];
    float s = v0+v1, ss = v0*v0+v1*v1;
    #pragma unroll
    for(int o=16;o;o>>=1){ s += __shfl_xor_sync(~0u,s,o); ss += __shfl_xor_sync(~0u,ss,o); }
    float mu = s*(1.0f/DHMc), var = ss*(1.0f/DHMc)-mu*mu;
    float r = rsqrtf(var + 1e-5f);
    #pragma unroll
    for(int p=0;p<2;p++){
        int c = hm*DHMc + lane + p*32;
        float v = p ? v1 : v0;
        float z = g_big[(size_t)t*2*INNERc + INNERc + c];
        float out = ((v-mu)*r*onw[c] + skip[c]*g_xconv[(size_t)t*INNERc + c]) * z*sigf(z);
        g_q[(size_t)t*INNERc + c] = out;   // reuse g_q as combine buffer
    }
}

// ---------------- host-side --------------------------------------------------
static float* symf(const void* s){ void* p=nullptr; cudaGetSymbolAddress(&p, s); return (float*)p; }

extern "C" void kernel_launch(void* const* d_in, const int* in_sizes, int n_in,
                              void* d_out, int out_size){
    const int*   x         = (const int*)  d_in[0];
    const float* embed     = (const float*)d_in[1];
    const float* s_ln1     = (const float*)d_in[2];
    const float* s_gates_w = (const float*)d_in[3];
    const float* s_rec     = (const float*)d_in[4];
    const float* s_bias    = (const float*)d_in[5];
    const float* s_gn      = (const float*)d_in[6];
    const float* s_ln2     = (const float*)d_in[7];
    const float* s_ff_up   = (const float*)d_in[8];
    const float* s_ff_down = (const float*)d_in[9];
    const float* m_ln1     = (const float*)d_in[10];
    const float* m_up      = (const float*)d_in[11];
    const float* m_conv_w  = (const float*)d_in[12];
    const float* m_conv_b  = (const float*)d_in[13];
    const float* m_qkv_w   = (const float*)d_in[14];
    const float* m_ig_w    = (const float*)d_in[15];
    const float* m_ig_b    = (const float*)d_in[16];
    const float* m_fg_w    = (const float*)d_in[17];
    const float* m_fg_b    = (const float*)d_in[18];
    const float* m_skip    = (const float*)d_in[19];
    const float* m_onorm   = (const float*)d_in[20];
    const float* m_down    = (const float*)d_in[21];
    const float* m_ln2     = (const float*)d_in[22];
    const float* m_ff_up   = (const float*)d_in[23];
    const float* m_ff_down = (const float*)d_in[24];
    const float* post_ln   = (const float*)d_in[25];
    const float* head_w    = (const float*)d_in[26];
    const float* head_b    = (const float*)d_in[27];

    float* h    = symf(g_h);
    float* xln  = symf(g_xln);
    float* big  = symf(g_big);
    float* y    = symf(g_y);
    float* ffn  = symf(g_ffn);
    float* qb   = symf(g_q);
    float* wd   = symf(g_wd);

    float* out = (float*)d_out;

    k_embed<<<Tt, Dd>>>(x, embed);

    for(int i=0;i<2;i++){
        // ---- sLSTM block ----
        k_ln<<<Tt/8,256>>>(h, s_ln1 + i*Dd, xln);
        k_sgx_prep<<<(Dd*4*Dd+255)/256,256>>>(s_gates_w + (size_t)i*4*NHs*HDs*HDs);
        k_gemm<false,true><<<dim3(4, Tt/128),256>>>(xln, wd, big, s_bias + i*4*Dd, Tt, 4*Dd, Dd);
        k_scan<<<NHs*(Bb/8),256>>>(s_rec + (size_t)i*4*NHs*HDs*HDs);
        k_gn_slstm<<<Tt,128>>>(s_gn + i*Dd);

        // ---- FFN 1 ----
        k_ln<<<Tt/8,256>>>(h, s_ln2 + i*Dd, xln);
        k_gemm<false,false><<<dim3(2*FFc/128, Tt/128),256>>>(xln, s_ff_up + (size_t)i*Dd*2*FFc, ffn, nullptr, Tt, 2*FFc, Dd);
        k_glu<<<(Tt*FFc/4+255)/256,256>>>();
        k_gemm<true ,false><<<dim3(Dd/128,   Tt/128),256>>>(y,  s_ff_down + (size_t)i*FFc*Dd, h, nullptr, Tt, Dd, FFc);

        // ---- mLSTM block ----
        k_ln<<<Tt/8,256>>>(h, m_ln1 + i*Dd, xln);
        k_gemm<false,false><<<dim3(2*INNERc/128, Tt/128),256>>>(xln, m_up + (size_t)i*Dd*2*INNERc, big, nullptr, Tt, 2*INNERc, Dd);
        k_conv<<<Tt,INNERc>>>(m_conv_w + (size_t)i*INNERc*Kc, m_conv_b + i*INNERc);
        k_qkv<<<Tt,INNERc>>>(m_qkv_w + (size_t)i*3*NBc*16);
        k_gates<<<Tt/32,256>>>(m_ig_w + (size_t)i*3*INNERc*NHMc, m_ig_b + i*NHMc,
                               m_fg_w + (size_t)i*3*INNERc*NHMc, m_fg_b + i*NHMc);
        k_attn<<<Bb*NHMc,256>>>();
        k_gn_comb<<<Tt,128>>>(m_onorm + i*INNERc, m_skip + i*INNERc);
        k_gemm<true ,false><<<dim3(Dd/128, Tt/128),256>>>(qb, m_down + (size_t)i*INNERc*Dd, h, nullptr, Tt, Dd, INNERc);

        // ---- FFN 2 ----
        k_ln<<<Tt/8,256>>>(h, m_ln2 + i*Dd, xln);
        k_gemm<false,false><<<dim3(2*FFc/128, Tt/128),256>>>(xln, m_ff_up + (size_t)i*Dd*2*FFc, ffn, nullptr, Tt, 2*FFc, Dd);
        k_glu<<<(Tt*FFc/4+255)/256,256>>>();
        k_gemm<true ,false><<<dim3(Dd/128,   Tt/128),256>>>(y, m_ff_down + (size_t)i*FFc*Dd, h, nullptr, Tt, Dd, FFc);
    }

    // ---- final LN + head ----
    k_ln<<<Tt/8,256>>>(h, post_ln, xln);
    k_gemm<false,true><<<dim3(Vv/128, Tt/128),256>>>(xln, head_w, out, head_b, Tt, Vv, Dd);
}

// round 6
// speedup vs baseline: 4.3723x; 1.2568x over previous
#include <cuda_runtime.h>
#include <cuda_bf16.h>
#include <math.h>
#include <stdint.h>

#define Bb     512
#define Ss     64
#define Dd     128
#define Vv     256
#define NHs    4
#define HDs    32
#define INNERc 256
#define NHMc   4
#define DHMc   64
#define NBc    64
#define Kc     4
#define FFc    128
#define Tt     (Bb*Ss)   /* 32768 tokens */

// ---------------- workspaces (static device globals; no allocation) ----------
__device__ float g_h[Tt*Dd];            // residual stream
__device__ float g_xln[Tt*Dd];          // LN output
__device__ float g_big[Tt*2*INNERc];    // slstm gx [t][512]  OR  mlstm up out [t][512]
__device__ float g_y[Tt*Dd];            // slstm y / ffn activation
__device__ float g_ffn[Tt*2*FFc];       // ffn up output
__device__ float g_xconv[Tt*INNERc];
__device__ float g_q[Tt*INNERc];        // q, later reused as mlstm combine buffer
__device__ float g_k[Tt*INNERc];
__device__ float g_v[Tt*INNERc];
__device__ float g_hatt[Tt*INNERc];
__device__ float g_ig[Bb*NHMc*Ss];
__device__ float g_fg[Bb*NHMc*Ss];
__device__ __nv_bfloat16 g_wt_hi[512*256];  // transposed split weights [N][K]
__device__ __nv_bfloat16 g_wt_lo[512*256];

// ---------------- device math helpers ---------------------------------------
__device__ __forceinline__ float sigf(float x){ return 1.0f/(1.0f+expf(-x)); }
__device__ __forceinline__ float logsigf(float x){ return fminf(x,0.0f) - log1pf(expf(-fabsf(x))); }
__device__ __forceinline__ float geluf(float x){
    float x3 = x*x*x;
    return 0.5f*x*(1.0f+tanhf(0.7978845608028654f*(x+0.044715f*x3)));
}
__device__ __forceinline__ uint32_t smem_u32(const void* p){
    uint32_t a;
    asm("{ .reg .u64 t; cvta.to.shared.u64 t, %1; cvt.u32.u64 %0, t; }" : "=r"(a) : "l"(p));
    return a;
}
__device__ __forceinline__ void split2(float a, float b, uint32_t &hi, uint32_t &lo){
    __nv_bfloat162 h = __floats2bfloat162_rn(a, b);
    float ra = a - __bfloat162float(h.x);
    float rb = b - __bfloat162float(h.y);
    __nv_bfloat162 l = __floats2bfloat162_rn(ra, rb);
    hi = *(uint32_t*)&h; lo = *(uint32_t*)&l;
}

#define LDM4(r0,r1,r2,r3,addr) \
    asm volatile("ldmatrix.sync.aligned.m8n8.x4.shared.b16 {%0,%1,%2,%3}, [%4];" \
        : "=r"(r0),"=r"(r1),"=r"(r2),"=r"(r3) : "r"(addr))

#define MMA16816(d,a,b) \
    asm volatile("mma.sync.aligned.m16n8k16.row.col.f32.bf16.bf16.f32 " \
        "{%0,%1,%2,%3}, {%4,%5,%6,%7}, {%8,%9}, {%0,%1,%2,%3};" \
        : "+f"((d)[0]),"+f"((d)[1]),"+f"((d)[2]),"+f"((d)[3]) \
        : "r"((a)[0]),"r"((a)[1]),"r"((a)[2]),"r"((a)[3]), "r"((b)[0]),"r"((b)[1]))

// smem layout: 4 tiles of [128 rows][136 bf16] = 34816 B each
#define MG_STRIDE 136
#define MG_TILE   (128*MG_STRIDE*2)
#define MG_AH 0
#define MG_AL (MG_TILE)
#define MG_BH (2*MG_TILE)
#define MG_BL (3*MG_TILE)
#define MG_SMEM (4*MG_TILE)

// ---------------- tensor-core GEMM: C[M,N] (+)= A[M,K] @ Wt^T (+bias) --------
// Wt (g_wt_hi/lo) is [N][K] bf16 split. Tile 128x128, K chunked by 128.
// Split-bf16: acc += Ah*Bh + Ah*Bl + Al*Bh  (fp32 accumulate).
template<bool ADD, bool BIAS>
__global__ void __launch_bounds__(256) k_mgemm(
        const float* __restrict__ A, float* __restrict__ C,
        const float* __restrict__ bias, int N, int K){
    extern __shared__ char smem[];
    const int tid = threadIdx.x, w = tid>>5, lane = tid&31;
    const int bm = blockIdx.y*128, bn = blockIdx.x*128;
    const int wm = w & 3, wn = w >> 2;          // warp tile: rows wm*32, cols wn*64
    const int gID = lane >> 2, qid = lane & 3;

    float acc[2][8][4] = {};

    // ldmatrix lane address components
    const int a_row = lane & 15;                 // 0..15 within m16 tile
    const int a_koff = (lane >> 4) * 8;          // 0 or 8
    const int b_noff = (lane & 7) + ((lane >> 4) & 1) * 8;
    const int b_koff = ((lane >> 3) & 1) * 8;

    const uint32_t sb = smem_u32(smem);

    const int nchunk = K >> 7;
    for (int kc = 0; kc < nchunk; kc++){
        // ---- stage A chunk: fp32 -> bf16 hi/lo ----
        #pragma unroll
        for (int it = 0; it < 8; it++){
            int g4 = tid + it*256;               // 0..2047
            int row = g4 >> 4, kg = g4 & 15;
            const float4* ap = (const float4*)(A + (size_t)(bm+row)*K + kc*128 + kg*8);
            float4 v0 = ap[0], v1 = ap[1];
            uint32_t h0,h1,h2,h3, l0,l1,l2,l3;
            split2(v0.x, v0.y, h0, l0);
            split2(v0.z, v0.w, h1, l1);
            split2(v1.x, v1.y, h2, l2);
            split2(v1.z, v1.w, h3, l3);
            uint32_t off = (uint32_t)(row*(MG_STRIDE*2) + kg*16);
            *(uint4*)(smem + MG_AH + off) = make_uint4(h0,h1,h2,h3);
            *(uint4*)(smem + MG_AL + off) = make_uint4(l0,l1,l2,l3);
        }
        // ---- stage B chunk: copy pre-split weights ----
        #pragma unroll
        for (int it = 0; it < 8; it++){
            int g4 = tid + it*256;
            int n = g4 >> 4, kg = g4 & 15;
            size_t gi = (size_t)(bn+n)*K + kc*128 + kg*8;
            uint4 hv = *(const uint4*)(g_wt_hi + gi);
            uint4 lv = *(const uint4*)(g_wt_lo + gi);
            uint32_t off = (uint32_t)(n*(MG_STRIDE*2) + kg*16);
            *(uint4*)(smem + MG_BH + off) = hv;
            *(uint4*)(smem + MG_BL + off) = lv;
        }
        __syncthreads();

        // ---- compute: 8 k-steps of 16 ----
        #pragma unroll
        for (int ks = 0; ks < 8; ks++){
            uint32_t ah[2][4], al[2][4];
            #pragma unroll
            for (int mt = 0; mt < 2; mt++){
                uint32_t aoff = (uint32_t)((wm*32 + mt*16 + a_row)*(MG_STRIDE*2)
                                           + (ks*16 + a_koff)*2);
                LDM4(ah[mt][0],ah[mt][1],ah[mt][2],ah[mt][3], sb + MG_AH + aoff);
                LDM4(al[mt][0],al[mt][1],al[mt][2],al[mt][3], sb + MG_AL + aoff);
            }
            uint32_t bh[8][2], bl[8][2];
            #pragma unroll
            for (int ng = 0; ng < 4; ng++){
                uint32_t boff = (uint32_t)((wn*64 + ng*16 + b_noff)*(MG_STRIDE*2)
                                           + (ks*16 + b_koff)*2);
                uint32_t r0,r1,r2,r3;
                LDM4(r0,r1,r2,r3, sb + MG_BH + boff);
                bh[ng*2][0]=r0; bh[ng*2][1]=r1; bh[ng*2+1][0]=r2; bh[ng*2+1][1]=r3;
                LDM4(r0,r1,r2,r3, sb + MG_BL + boff);
                bl[ng*2][0]=r0; bl[ng*2][1]=r1; bl[ng*2+1][0]=r2; bl[ng*2+1][1]=r3;
            }
            #pragma unroll
            for (int mt = 0; mt < 2; mt++)
                #pragma unroll
                for (int nt = 0; nt < 8; nt++){
                    MMA16816(acc[mt][nt], ah[mt], bh[nt]);
                    MMA16816(acc[mt][nt], ah[mt], bl[nt]);
                    MMA16816(acc[mt][nt], al[mt], bh[nt]);
                }
        }
        __syncthreads();
    }

    // ---- epilogue ----
    #pragma unroll
    for (int mt = 0; mt < 2; mt++){
        #pragma unroll
        for (int nt = 0; nt < 8; nt++){
            int row0 = bm + wm*32 + mt*16 + gID;
            int col  = bn + wn*64 + nt*8 + qid*2;
            float2 v0 = make_float2(acc[mt][nt][0], acc[mt][nt][1]);
            float2 v1 = make_float2(acc[mt][nt][2], acc[mt][nt][3]);
            if (BIAS){
                float2 bv = *(const float2*)&bias[col];
                v0.x += bv.x; v0.y += bv.y;
                v1.x += bv.x; v1.y += bv.y;
            }
            float* p0 = C + (size_t)row0*N + col;
            float* p1 = C + (size_t)(row0+8)*N + col;
            if (ADD){
                float2 o0 = *(const float2*)p0, o1 = *(const float2*)p1;
                v0.x += o0.x; v0.y += o0.y;
                v1.x += o1.x; v1.y += o1.y;
            }
            *(float2*)p0 = v0;
            *(float2*)p1 = v1;
        }
    }
}

// ---------------- weight transpose + bf16 split: W[K][N] -> Wt[N][K] ---------
__global__ void k_wt(const float* __restrict__ W, int K, int N){
    __shared__ float t[32][33];
    int bk = blockIdx.x*32, bn = blockIdx.y*32;
    int tx = threadIdx.x, ty = threadIdx.y;  // 32 x 8
    #pragma unroll
    for (int r = 0; r < 32; r += 8)
        t[ty+r][tx] = W[(size_t)(bk+ty+r)*N + bn+tx];
    __syncthreads();
    #pragma unroll
    for (int r = 0; r < 32; r += 8){
        float v = t[tx][ty+r];
        __nv_bfloat16 h = __float2bfloat16(v);
        size_t o = (size_t)(bn+ty+r)*K + bk+tx;
        g_wt_hi[o] = h;
        g_wt_lo[o] = __float2bfloat16(v - __bfloat162float(h));
    }
}

// ---------------- densify + transpose + split slstm gate weights -------------
__global__ void k_sgx_prep(const float* __restrict__ gw){
    int idx = blockIdx.x*blockDim.x + threadIdx.x;   // over 128*512
    if (idx >= Dd*4*Dd) return;
    int d = idx >> 9;          // 0..127
    int o = idx & 511;         // (g, n, e)
    int g = o >> 7;
    int ne = o & 127;
    int n = ne >> 5, e = ne & 31;
    float wv = 0.0f;
    if ((d >> 5) == n) wv = gw[(((g*NHs + n)*HDs + e)*HDs) + (d & 31)];
    __nv_bfloat16 h = __float2bfloat16(wv);
    g_wt_hi[(size_t)o*Dd + d] = h;
    g_wt_lo[(size_t)o*Dd + d] = __float2bfloat16(wv - __bfloat162float(h));
}

// ---------------- embedding --------------------------------------------------
__global__ void k_embed(const int* __restrict__ x, const float* __restrict__ emb){
    int t = blockIdx.x;
    g_h[t*Dd + threadIdx.x] = emb[x[t]*Dd + threadIdx.x];
}

// ---------------- layernorm (warp per token, D=128) --------------------------
__global__ void k_ln(const float* __restrict__ in, const float* __restrict__ w,
                     float* __restrict__ out){
    int warp = (blockIdx.x*blockDim.x + threadIdx.x) >> 5;
    int lane = threadIdx.x & 31;
    if (warp >= Tt) return;
    const float* xp = in + (size_t)warp*Dd;
    float v0=xp[lane], v1=xp[lane+32], v2=xp[lane+64], v3=xp[lane+96];
    float s  = v0+v1+v2+v3;
    float ss = v0*v0+v1*v1+v2*v2+v3*v3;
    #pragma unroll
    for(int o=16;o;o>>=1){ s += __shfl_xor_sync(~0u,s,o); ss += __shfl_xor_sync(~0u,ss,o); }
    float mu  = s*(1.0f/Dd);
    float var = ss*(1.0f/Dd) - mu*mu;
    float r   = rsqrtf(var + 1e-5f);
    float* op = out + (size_t)warp*Dd;
    op[lane]    = (v0-mu)*r*w[lane];
    op[lane+32] = (v1-mu)*r*w[lane+32];
    op[lane+64] = (v2-mu)*r*w[lane+64];
    op[lane+96] = (v3-mu)*r*w[lane+96];
}

// ---------------- sLSTM recurrence scan: 8 warps/block, shared weights -------
__global__ void __launch_bounds__(256) k_scan(const float* __restrict__ rec){
    int n  = blockIdx.x & 3;
    int bg = blockIdx.x >> 2;           // 0..63
    int w  = threadIdx.x >> 5;
    int e  = threadIdx.x & 31;
    int b  = bg*8 + w;
    __shared__ float rw[4][HDs][36];
    __shared__ float hs[8][HDs];
    for (int idx = threadIdx.x; idx < 4*HDs*HDs; idx += 256){
        int g = idx >> 10, rem = idx & 1023;
        int e2 = rem >> 5, d = rem & 31;
        rw[g][e2][d] = rec[((size_t)(g*NHs+n)*HDs + e2)*HDs + d];
    }
    hs[w][e] = 0.0f;
    __syncthreads();
    float c=0.0f, nn=0.0f, m=0.0f;
    const int gb = n*HDs + e;
    for(int s=0;s<Ss;s++){
        const float* gxp = g_big + (size_t)(b*Ss + s)*512 + gb;   // token-major
        float r0=gxp[0], r1=gxp[Dd], r2=gxp[2*Dd], r3=gxp[3*Dd];
        #pragma unroll
        for(int dq=0; dq<8; dq++){
            float4 hv = *(const float4*)&hs[w][dq*4];
            float4 w0 = *(const float4*)&rw[0][e][dq*4];
            float4 w1 = *(const float4*)&rw[1][e][dq*4];
            float4 w2 = *(const float4*)&rw[2][e][dq*4];
            float4 w3 = *(const float4*)&rw[3][e][dq*4];
            r0 += hv.x*w0.x + hv.y*w0.y + hv.z*w0.z + hv.w*w0.w;
            r1 += hv.x*w1.x + hv.y*w1.y + hv.z*w1.z + hv.w*w1.w;
            r2 += hv.x*w2.x + hv.y*w2.y + hv.z*w2.z + hv.w*w2.w;
            r3 += hv.x*w3.x + hv.y*w3.y + hv.z*w3.z + hv.w*w3.w;
        }
        float lfm = m + logsigf(r1);
        float mn  = fmaxf(r0, lfm);
        float i   = expf(r0-mn);
        float f   = expf(lfm-mn);
        c  = f*c + i*tanhf(r2);
        nn = f*nn + i;
        float hnew = sigf(r3) * c / nn;
        m = mn;
        __syncwarp();
        hs[w][e] = hnew;
        __syncwarp();
        g_y[((size_t)(b*Ss+s))*Dd + gb] = hnew;
    }
}

// ---------------- sLSTM group norm (G=32) + residual add into g_h ------------
__global__ void k_gn_slstm(const float* __restrict__ gn){
    int t = blockIdx.x;
    int n = threadIdx.x >> 5, lane = threadIdx.x & 31;
    float v = g_y[(size_t)t*Dd + n*HDs + lane];
    float s=v, ss=v*v;
    #pragma unroll
    for(int o=16;o;o>>=1){ s += __shfl_xor_sync(~0u,s,o); ss += __shfl_xor_sync(~0u,ss,o); }
    float mu = s*(1.0f/HDs), var = ss*(1.0f/HDs)-mu*mu;
    float r = rsqrtf(var + 1e-5f);
    g_h[(size_t)t*Dd + n*HDs + lane] += (v-mu)*r*gn[n*HDs+lane];
}

// ---------------- FFN gate activation: gelu(g)*u (float4) --------------------
__global__ void k_glu(){
    int i = blockIdx.x*blockDim.x + threadIdx.x;   // over Tt*FFc/4
    if (i >= Tt*FFc/4) return;
    int t = i/(FFc/4), f4 = i%(FFc/4);
    const float4 g4 = *(const float4*)&g_ffn[(size_t)t*2*FFc + f4*4];
    const float4 u4 = *(const float4*)&g_ffn[(size_t)t*2*FFc + FFc + f4*4];
    float4 o;
    o.x = geluf(g4.x)*u4.x; o.y = geluf(g4.y)*u4.y;
    o.z = geluf(g4.z)*u4.z; o.w = geluf(g4.w)*u4.w;
    *(float4*)&g_y[(size_t)t*FFc + f4*4] = o;
}

// ---------------- mLSTM causal depthwise conv + silu -------------------------
__global__ void k_conv(const float* __restrict__ cw, const float* __restrict__ cb){
    int t = blockIdx.x; int c = threadIdx.x;
    int b = t/Ss, s = t%Ss;
    float acc = cb[c];
    #pragma unroll
    for(int tt=0; tt<Kc; tt++){
        int si = s - (Kc-1) + tt;
        if (si >= 0) acc += g_big[((size_t)(b*Ss+si))*2*INNERc + c]*cw[c*Kc+tt];
    }
    g_xconv[(size_t)t*INNERc + c] = acc*sigf(acc);
}

// ---------------- blocked qkv projections ------------------------------------
__global__ void k_qkv(const float* __restrict__ w){
    int t = blockIdx.x; int c = threadIdx.x;
    int n = c >> 2, o = c & 3;
    const float* wq = w + n*16 + o*4;
    const float* wk = wq + NBc*16;
    const float* wv = wk + NBc*16;
    const float* xc = g_xconv + (size_t)t*INNERc + n*4;
    const float* xm = g_big   + (size_t)t*2*INNERc + n*4;
    float q=0,k=0,v=0;
    #pragma unroll
    for(int i=0;i<4;i++){ q += xc[i]*wq[i]; k += xc[i]*wk[i]; v += xm[i]*wv[i]; }
    g_q[(size_t)t*INNERc+c]=q; g_k[(size_t)t*INNERc+c]=k; g_v[(size_t)t*INNERc+c]=v;
}

// ---------------- input/forget gates: 32 tokens/block, weights in smem -------
__global__ void __launch_bounds__(256) k_gates(
        const float* __restrict__ igw, const float* __restrict__ igb,
        const float* __restrict__ fgw, const float* __restrict__ fgb){
    __shared__ float4 iws[3*INNERc];
    __shared__ float4 fws[3*INNERc];
    for (int j = threadIdx.x; j < 3*INNERc; j += 256){
        iws[j] = *(const float4*)&igw[j*NHMc];
        fws[j] = *(const float4*)&fgw[j*NHMc];
    }
    __syncthreads();
    int w = threadIdx.x >> 5, lane = threadIdx.x & 31;
    int t0 = blockIdx.x*32 + w*4;
    for (int tt = 0; tt < 4; tt++){
        int t = t0 + tt;
        float ia0=0,ia1=0,ia2=0,ia3=0, fa0=0,fa1=0,fa2=0,fa3=0;
        const float* qp = g_q + (size_t)t*INNERc;
        const float* kp = g_k + (size_t)t*INNERc;
        const float* vp = g_v + (size_t)t*INNERc;
        for (int j = lane; j < 3*INNERc; j += 32){
            float val = (j < INNERc) ? qp[j] : (j < 2*INNERc) ? kp[j-INNERc] : vp[j-2*INNERc];
            float4 iw = iws[j], fw = fws[j];
            ia0 += val*iw.x; ia1 += val*iw.y; ia2 += val*iw.z; ia3 += val*iw.w;
            fa0 += val*fw.x; fa1 += val*fw.y; fa2 += val*fw.z; fa3 += val*fw.w;
        }
        #pragma unroll
        for (int o=16;o;o>>=1){
            ia0 += __shfl_xor_sync(~0u,ia0,o); ia1 += __shfl_xor_sync(~0u,ia1,o);
            ia2 += __shfl_xor_sync(~0u,ia2,o); ia3 += __shfl_xor_sync(~0u,ia3,o);
            fa0 += __shfl_xor_sync(~0u,fa0,o); fa1 += __shfl_xor_sync(~0u,fa1,o);
            fa2 += __shfl_xor_sync(~0u,fa2,o); fa3 += __shfl_xor_sync(~0u,fa3,o);
        }
        if (lane == 0){
            int b = t/Ss, s = t%Ss;
            g_ig[(size_t)(b*NHMc+0)*Ss + s] = ia0 + igb[0];
            g_ig[(size_t)(b*NHMc+1)*Ss + s] = ia1 + igb[1];
            g_ig[(size_t)(b*NHMc+2)*Ss + s] = ia2 + igb[2];
            g_ig[(size_t)(b*NHMc+3)*Ss + s] = ia3 + igb[3];
            g_fg[(size_t)(b*NHMc+0)*Ss + s] = fa0 + fgb[0];
            g_fg[(size_t)(b*NHMc+1)*Ss + s] = fa1 + fgb[1];
            g_fg[(size_t)(b*NHMc+2)*Ss + s] = fa2 + fgb[2];
            g_fg[(size_t)(b*NHMc+3)*Ss + s] = fa3 + fgb[3];
        }
    }
}

// ---------------- mLSTM attention: block per (b, head), v in smem ------------
__global__ void __launch_bounds__(256) k_attn(){
    int blk = blockIdx.x; int b = blk >> 2, hm = blk & 3;
    __shared__ float qs[Ss][DHMc+1], ks[Ss][DHMc+1], vs[Ss][DHMc+1];
    __shared__ float cldf[Ss+1], igs[Ss];
    __shared__ float cn[8][Ss];
    int tid = threadIdx.x;
    for(int l=tid; l<Ss*DHMc; l+=256){
        int j = l >> 6, d = l & 63;
        size_t base = ((size_t)(b*Ss+j))*INNERc + hm*DHMc + d;
        qs[j][d] = g_q[base];
        ks[j][d] = g_k[base];
        vs[j][d] = g_v[base];
    }
    if (tid < Ss) igs[tid] = g_ig[(size_t)(b*NHMc+hm)*Ss + tid];
    if (tid == 0){
        float cacc = 0.0f; cldf[0] = 0.0f;
        for(int s=0;s<Ss;s++){ cacc += logsigf(g_fg[(size_t)(b*NHMc+hm)*Ss + s]); cldf[s+1]=cacc; }
    }
    __syncthreads();
    int w = tid >> 5, lane = tid & 31;
    for(int r=0;r<8;r++){
        int i = w*8 + r;
        int j1 = lane + 32;
        float dot0=0, dot1=0, ld0=-1e30f, ld1=-1e30f;
        if (lane <= i){
            #pragma unroll
            for(int d=0; d<DHMc; d++) dot0 += qs[i][d]*ks[lane][d];
            ld0 = cldf[i+1]-cldf[lane+1] + igs[lane];
        }
        if (j1 <= i){
            #pragma unroll
            for(int d=0; d<DHMc; d++) dot1 += qs[i][d]*ks[j1][d];
            ld1 = cldf[i+1]-cldf[j1+1] + igs[j1];
        }
        float mx = fmaxf(ld0, ld1);
        #pragma unroll
        for(int o=16;o;o>>=1) mx = fmaxf(mx, __shfl_xor_sync(~0u,mx,o));
        float cm0 = (lane <= i) ? dot0*0.125f*expf(ld0-mx) : 0.0f;
        float cm1 = (j1   <= i) ? dot1*0.125f*expf(ld1-mx) : 0.0f;
        float sm = cm0 + cm1;
        #pragma unroll
        for(int o=16;o;o>>=1) sm += __shfl_xor_sync(~0u,sm,o);
        float norm = fmaxf(fabsf(sm), expf(-mx)) + 1e-6f;
        cn[w][lane] = cm0/norm;
        cn[w][j1]   = cm1/norm;
        __syncwarp();
        float a0=0, a1=0;
        for(int j=0;j<=i;j++){
            float cc = cn[w][j];
            a0 += cc*vs[j][lane];
            a1 += cc*vs[j][lane+32];
        }
        g_hatt[((size_t)(b*Ss+i))*INNERc + hm*DHMc + lane]      = a0;
        g_hatt[((size_t)(b*Ss+i))*INNERc + hm*DHMc + lane + 32] = a1;
        __syncwarp();
    }
}

// ---------------- mLSTM groupnorm (G=64) + skip/silu combine -----------------
__global__ void k_gn_comb(const float* __restrict__ onw, const float* __restrict__ skip){
    int t = blockIdx.x;
    int hm = threadIdx.x >> 5, lane = threadIdx.x & 31;
    size_t base = (size_t)t*INNERc + hm*DHMc;
    float v0 = g_hatt[base+lane], v1 = g_hatt[base+lane+32];
    float s = v0+v1, ss = v0*v0+v1*v1;
    #pragma unroll
    for(int o=16;o;o>>=1){ s += __shfl_xor_sync(~0u,s,o); ss += __shfl_xor_sync(~0u,ss,o); }
    float mu = s*(1.0f/DHMc), var = ss*(1.0f/DHMc)-mu*mu;
    float r = rsqrtf(var + 1e-5f);
    #pragma unroll
    for(int p=0;p<2;p++){
        int c = hm*DHMc + lane + p*32;
        float v = p ? v1 : v0;
        float z = g_big[(size_t)t*2*INNERc + INNERc + c];
        float out = ((v-mu)*r*onw[c] + skip[c]*g_xconv[(size_t)t*INNERc + c]) * z*sigf(z);
        g_q[(size_t)t*INNERc + c] = out;   // reuse g_q as combine buffer
    }
}

// ---------------- host-side --------------------------------------------------
static float* symf(const void* s){ void* p=nullptr; cudaGetSymbolAddress(&p, s); return (float*)p; }

extern "C" void kernel_launch(void* const* d_in, const int* in_sizes, int n_in,
                              void* d_out, int out_size){
    const int*   x         = (const int*)  d_in[0];
    const float* embed     = (const float*)d_in[1];
    const float* s_ln1     = (const float*)d_in[2];
    const float* s_gates_w = (const float*)d_in[3];
    const float* s_rec     = (const float*)d_in[4];
    const float* s_bias    = (const float*)d_in[5];
    const float* s_gn      = (const float*)d_in[6];
    const float* s_ln2     = (const float*)d_in[7];
    const float* s_ff_up   = (const float*)d_in[8];
    const float* s_ff_down = (const float*)d_in[9];
    const float* m_ln1     = (const float*)d_in[10];
    const float* m_up      = (const float*)d_in[11];
    const float* m_conv_w  = (const float*)d_in[12];
    const float* m_conv_b  = (const float*)d_in[13];
    const float* m_qkv_w   = (const float*)d_in[14];
    const float* m_ig_w    = (const float*)d_in[15];
    const float* m_ig_b    = (const float*)d_in[16];
    const float* m_fg_w    = (const float*)d_in[17];
    const float* m_fg_b    = (const float*)d_in[18];
    const float* m_skip    = (const float*)d_in[19];
    const float* m_onorm   = (const float*)d_in[20];
    const float* m_down    = (const float*)d_in[21];
    const float* m_ln2     = (const float*)d_in[22];
    const float* m_ff_up   = (const float*)d_in[23];
    const float* m_ff_down = (const float*)d_in[24];
    const float* post_ln   = (const float*)d_in[25];
    const float* head_w    = (const float*)d_in[26];
    const float* head_b    = (const float*)d_in[27];

    float* h    = symf(g_h);
    float* xln  = symf(g_xln);
    float* big  = symf(g_big);
    float* y    = symf(g_y);
    float* ffn  = symf(g_ffn);
    float* qb   = symf(g_q);

    float* out = (float*)d_out;

    cudaFuncSetAttribute(k_mgemm<false,false>, cudaFuncAttributeMaxDynamicSharedMemorySize, MG_SMEM);
    cudaFuncSetAttribute(k_mgemm<true ,false>, cudaFuncAttributeMaxDynamicSharedMemorySize, MG_SMEM);
    cudaFuncSetAttribute(k_mgemm<false,true >, cudaFuncAttributeMaxDynamicSharedMemorySize, MG_SMEM);

    k_embed<<<Tt, Dd>>>(x, embed);

    for(int i=0;i<2;i++){
        // ---- sLSTM block ----
        k_ln<<<Tt/8,256>>>(h, s_ln1 + i*Dd, xln);
        k_sgx_prep<<<(Dd*4*Dd+255)/256,256>>>(s_gates_w + (size_t)i*4*NHs*HDs*HDs);
        k_mgemm<false,true><<<dim3(4, Tt/128),256,MG_SMEM>>>(xln, big, s_bias + i*4*Dd, 4*Dd, Dd);
        k_scan<<<NHs*(Bb/8),256>>>(s_rec + (size_t)i*4*NHs*HDs*HDs);
        k_gn_slstm<<<Tt,128>>>(s_gn + i*Dd);

        // ---- FFN 1 ----
        k_ln<<<Tt/8,256>>>(h, s_ln2 + i*Dd, xln);
        k_wt<<<dim3(Dd/32, 2*FFc/32), dim3(32,8)>>>(s_ff_up + (size_t)i*Dd*2*FFc, Dd, 2*FFc);
        k_mgemm<false,false><<<dim3(2*FFc/128, Tt/128),256,MG_SMEM>>>(xln, ffn, nullptr, 2*FFc, Dd);
        k_glu<<<(Tt*FFc/4+255)/256,256>>>();
        k_wt<<<dim3(FFc/32, Dd/32), dim3(32,8)>>>(s_ff_down + (size_t)i*FFc*Dd, FFc, Dd);
        k_mgemm<true,false><<<dim3(Dd/128, Tt/128),256,MG_SMEM>>>(y, h, nullptr, Dd, FFc);

        // ---- mLSTM block ----
        k_ln<<<Tt/8,256>>>(h, m_ln1 + i*Dd, xln);
        k_wt<<<dim3(Dd/32, 2*INNERc/32), dim3(32,8)>>>(m_up + (size_t)i*Dd*2*INNERc, Dd, 2*INNERc);
        k_mgemm<false,false><<<dim3(2*INNERc/128, Tt/128),256,MG_SMEM>>>(xln, big, nullptr, 2*INNERc, Dd);
        k_conv<<<Tt,INNERc>>>(m_conv_w + (size_t)i*INNERc*Kc, m_conv_b + i*INNERc);
        k_qkv<<<Tt,INNERc>>>(m_qkv_w + (size_t)i*3*NBc*16);
        k_gates<<<Tt/32,256>>>(m_ig_w + (size_t)i*3*INNERc*NHMc, m_ig_b + i*NHMc,
                               m_fg_w + (size_t)i*3*INNERc*NHMc, m_fg_b + i*NHMc);
        k_attn<<<Bb*NHMc,256>>>();
        k_gn_comb<<<Tt,128>>>(m_onorm + i*INNERc, m_skip + i*INNERc);
        k_wt<<<dim3(INNERc/32, Dd/32), dim3(32,8)>>>(m_down + (size_t)i*INNERc*Dd, INNERc, Dd);
        k_mgemm<true,false><<<dim3(Dd/128, Tt/128),256,MG_SMEM>>>(qb, h, nullptr, Dd, INNERc);

        // ---- FFN 2 ----
        k_ln<<<Tt/8,256>>>(h, m_ln2 + i*Dd, xln);
        k_wt<<<dim3(Dd/32, 2*FFc/32), dim3(32,8)>>>(m_ff_up + (size_t)i*Dd*2*FFc, Dd, 2*FFc);
        k_mgemm<false,false><<<dim3(2*FFc/128, Tt/128),256,MG_SMEM>>>(xln, ffn, nullptr, 2*FFc, Dd);
        k_glu<<<(Tt*FFc/4+255)/256,256>>>();
        k_wt<<<dim3(FFc/32, Dd/32), dim3(32,8)>>>(m_ff_down + (size_t)i*FFc*Dd, FFc, Dd);
        k_mgemm<true,false><<<dim3(Dd/128, Tt/128),256,MG_SMEM>>>(y, h, nullptr, Dd, FFc);
    }

    // ---- final LN + head ----
    k_ln<<<Tt/8,256>>>(h, post_ln, xln);
    k_wt<<<dim3(Dd/32, Vv/32), dim3(32,8)>>>(head_w, Dd, Vv);
    k_mgemm<false,true><<<dim3(Vv/128, Tt/128),256,MG_SMEM>>>(xln, out, head_b, Vv, Dd);
}

// round 7
// speedup vs baseline: 4.5531x; 1.0414x over previous
#include <cuda_runtime.h>
#include <cuda_bf16.h>
#include <math.h>
#include <stdint.h>

#define Bb     512
#define Ss     64
#define Dd     128
#define Vv     256
#define NHs    4
#define HDs    32
#define INNERc 256
#define NHMc   4
#define DHMc   64
#define NBc    64
#define Kc     4
#define FFc    128
#define Tt     (Bb*Ss)   /* 32768 tokens */

// ---------------- workspaces (static device globals; no allocation) ----------
__device__ float g_h[Tt*Dd];            // residual stream
__device__ float g_big[Tt*2*INNERc];    // slstm gx [t][512]  OR  mlstm up out [t][512]
__device__ float g_y[Tt*Dd];            // slstm y buffer
__device__ float g_ffn[Tt*2*FFc];       // ffn up output
__device__ float g_xconv[Tt*INNERc];
__device__ float g_q[Tt*INNERc];        // q, later reused as mlstm combine buffer
__device__ float g_k[Tt*INNERc];
__device__ float g_v[Tt*INNERc];
__device__ float g_hatt[Tt*INNERc];
__device__ float g_ig[Bb*NHMc*Ss];
__device__ float g_fg[Bb*NHMc*Ss];
__device__ __nv_bfloat16 g_wt_hi[512*256];  // transposed split weights [N][K]
__device__ __nv_bfloat16 g_wt_lo[512*256];

// ---------------- device math helpers ---------------------------------------
__device__ __forceinline__ float sigf(float x){ return 1.0f/(1.0f+expf(-x)); }
__device__ __forceinline__ float logsigf(float x){ return fminf(x,0.0f) - log1pf(expf(-fabsf(x))); }
__device__ __forceinline__ float geluf(float x){
    float x3 = x*x*x;
    return 0.5f*x*(1.0f+tanhf(0.7978845608028654f*(x+0.044715f*x3)));
}
__device__ __forceinline__ uint32_t smem_u32(const void* p){
    uint32_t a;
    asm("{ .reg .u64 t; cvta.to.shared.u64 t, %1; cvt.u32.u64 %0, t; }" : "=r"(a) : "l"(p));
    return a;
}
__device__ __forceinline__ void split2(float a, float b, uint32_t &hi, uint32_t &lo){
    __nv_bfloat162 h = __floats2bfloat162_rn(a, b);
    float ra = a - __bfloat162float(h.x);
    float rb = b - __bfloat162float(h.y);
    __nv_bfloat162 l = __floats2bfloat162_rn(ra, rb);
    hi = *(uint32_t*)&h; lo = *(uint32_t*)&l;
}

#define LDM4(r0,r1,r2,r3,addr) \
    asm volatile("ldmatrix.sync.aligned.m8n8.x4.shared.b16 {%0,%1,%2,%3}, [%4];" \
        : "=r"(r0),"=r"(r1),"=r"(r2),"=r"(r3) : "r"(addr))

#define MMA16816(d,a,b) \
    asm volatile("mma.sync.aligned.m16n8k16.row.col.f32.bf16.bf16.f32 " \
        "{%0,%1,%2,%3}, {%4,%5,%6,%7}, {%8,%9}, {%0,%1,%2,%3};" \
        : "+f"((d)[0]),"+f"((d)[1]),"+f"((d)[2]),"+f"((d)[3]) \
        : "r"((a)[0]),"r"((a)[1]),"r"((a)[2]),"r"((a)[3]), "r"((b)[0]),"r"((b)[1]))

// smem layout: A tiles 128x136 bf16 (hi/lo), B tiles 64x136 bf16 (hi/lo)
#define MG_STRIDE 136
#define MG_AH 0
#define MG_AL (128*MG_STRIDE*2)
#define MG_BH (2*128*MG_STRIDE*2)
#define MG_BL (MG_BH + 64*MG_STRIDE*2)
#define MG_SMEM (MG_BL + 64*MG_STRIDE*2)   /* 104448 B */

// ---------------- tensor-core GEMM: C[M,N] (+)= f(A)[M,K] @ Wt^T (+bias) -----
// Wt (g_wt_hi/lo) is [N][K] bf16 split. Tile 128x64, K chunked by 128.
// Split-bf16: acc += Ah*Bh + Ah*Bl + Al*Bh (fp32 accumulate).
// LN:  A-rows layernormed during staging (requires K==128, weight lnw).
// GLU: A = g_ffn [t][256]; staged value = gelu(A[t][f]) * A[t][128+f] (K==128).
template<bool ADD, bool BIAS, bool LN, bool GLU>
__global__ void __launch_bounds__(256,2) k_mgemm(
        const float* __restrict__ A, float* __restrict__ C,
        const float* __restrict__ bias, const float* __restrict__ lnw,
        int N, int K){
    extern __shared__ char smem[];
    const int tid = threadIdx.x, w = tid>>5, lane = tid&31;
    const int bm = blockIdx.y*128, bn = blockIdx.x*64;
    const int wm = w & 3, wn = w >> 2;          // warp tile: rows wm*32, cols wn*32
    const int gID = lane >> 2, qid = lane & 3;

    float acc[2][4][4] = {};

    const int a_row = lane & 15;
    const int a_koff = (lane >> 4) * 8;
    const int b_noff = (lane & 7) + ((lane >> 4) & 1) * 8;
    const int b_koff = ((lane >> 3) & 1) * 8;

    const uint32_t sb = smem_u32(smem);

    const int nchunk = K >> 7;
    for (int kc = 0; kc < nchunk; kc++){
        // ---- stage A chunk (128 rows x 128 cols) ----
        #pragma unroll
        for (int it = 0; it < 8; it++){
            int g4 = tid + it*256;               // 0..2047
            int row = g4 >> 4, kg = g4 & 15;
            float4 v0, v1;
            if (GLU){
                const float* ap = A + (size_t)(bm+row)*256 + kg*8;
                float4 gg0 = *(const float4*)ap,      gg1 = *(const float4*)(ap+4);
                float4 uu0 = *(const float4*)(ap+128), uu1 = *(const float4*)(ap+132);
                v0.x = geluf(gg0.x)*uu0.x; v0.y = geluf(gg0.y)*uu0.y;
                v0.z = geluf(gg0.z)*uu0.z; v0.w = geluf(gg0.w)*uu0.w;
                v1.x = geluf(gg1.x)*uu1.x; v1.y = geluf(gg1.y)*uu1.y;
                v1.z = geluf(gg1.z)*uu1.z; v1.w = geluf(gg1.w)*uu1.w;
            } else {
                const float4* ap = (const float4*)(A + (size_t)(bm+row)*K + kc*128 + kg*8);
                v0 = ap[0]; v1 = ap[1];
            }
            if (LN){
                float s  = v0.x+v0.y+v0.z+v0.w + v1.x+v1.y+v1.z+v1.w;
                float ss = v0.x*v0.x+v0.y*v0.y+v0.z*v0.z+v0.w*v0.w
                         + v1.x*v1.x+v1.y*v1.y+v1.z*v1.z+v1.w*v1.w;
                #pragma unroll
                for (int o = 1; o < 16; o <<= 1){
                    s  += __shfl_xor_sync(~0u, s,  o);
                    ss += __shfl_xor_sync(~0u, ss, o);
                }
                float mu  = s*(1.0f/128.0f);
                float var = ss*(1.0f/128.0f) - mu*mu;
                float rr  = rsqrtf(var + 1e-5f);
                float4 w0 = *(const float4*)&lnw[kg*8];
                float4 w1 = *(const float4*)&lnw[kg*8+4];
                v0.x = (v0.x-mu)*rr*w0.x; v0.y = (v0.y-mu)*rr*w0.y;
                v0.z = (v0.z-mu)*rr*w0.z; v0.w = (v0.w-mu)*rr*w0.w;
                v1.x = (v1.x-mu)*rr*w1.x; v1.y = (v1.y-mu)*rr*w1.y;
                v1.z = (v1.z-mu)*rr*w1.z; v1.w = (v1.w-mu)*rr*w1.w;
            }
            uint32_t h0,h1,h2,h3, l0,l1,l2,l3;
            split2(v0.x, v0.y, h0, l0);
            split2(v0.z, v0.w, h1, l1);
            split2(v1.x, v1.y, h2, l2);
            split2(v1.z, v1.w, h3, l3);
            uint32_t off = (uint32_t)(row*(MG_STRIDE*2) + kg*16);
            *(uint4*)(smem + MG_AH + off) = make_uint4(h0,h1,h2,h3);
            *(uint4*)(smem + MG_AL + off) = make_uint4(l0,l1,l2,l3);
        }
        // ---- stage B chunk (64 rows x 128 cols, pre-split weights) ----
        #pragma unroll
        for (int it = 0; it < 4; it++){
            int g4 = tid + it*256;
            int n = g4 >> 4, kg = g4 & 15;
            size_t gi = (size_t)(bn+n)*K + kc*128 + kg*8;
            uint4 hv = *(const uint4*)(g_wt_hi + gi);
            uint4 lv = *(const uint4*)(g_wt_lo + gi);
            uint32_t off = (uint32_t)(n*(MG_STRIDE*2) + kg*16);
            *(uint4*)(smem + MG_BH + off) = hv;
            *(uint4*)(smem + MG_BL + off) = lv;
        }
        __syncthreads();

        // ---- compute: 8 k-steps of 16 ----
        #pragma unroll
        for (int ks = 0; ks < 8; ks++){
            uint32_t ah[2][4], al[2][4];
            #pragma unroll
            for (int mt = 0; mt < 2; mt++){
                uint32_t aoff = (uint32_t)((wm*32 + mt*16 + a_row)*(MG_STRIDE*2)
                                           + (ks*16 + a_koff)*2);
                LDM4(ah[mt][0],ah[mt][1],ah[mt][2],ah[mt][3], sb + MG_AH + aoff);
                LDM4(al[mt][0],al[mt][1],al[mt][2],al[mt][3], sb + MG_AL + aoff);
            }
            uint32_t bh[4][2], bl[4][2];
            #pragma unroll
            for (int ng = 0; ng < 2; ng++){
                uint32_t boff = (uint32_t)((wn*32 + ng*16 + b_noff)*(MG_STRIDE*2)
                                           + (ks*16 + b_koff)*2);
                uint32_t r0,r1,r2,r3;
                LDM4(r0,r1,r2,r3, sb + MG_BH + boff);
                bh[ng*2][0]=r0; bh[ng*2][1]=r1; bh[ng*2+1][0]=r2; bh[ng*2+1][1]=r3;
                LDM4(r0,r1,r2,r3, sb + MG_BL + boff);
                bl[ng*2][0]=r0; bl[ng*2][1]=r1; bl[ng*2+1][0]=r2; bl[ng*2+1][1]=r3;
            }
            #pragma unroll
            for (int mt = 0; mt < 2; mt++)
                #pragma unroll
                for (int nt = 0; nt < 4; nt++){
                    MMA16816(acc[mt][nt], ah[mt], bh[nt]);
                    MMA16816(acc[mt][nt], ah[mt], bl[nt]);
                    MMA16816(acc[mt][nt], al[mt], bh[nt]);
                }
        }
        __syncthreads();
    }

    // ---- epilogue ----
    #pragma unroll
    for (int mt = 0; mt < 2; mt++){
        #pragma unroll
        for (int nt = 0; nt < 4; nt++){
            int row0 = bm + wm*32 + mt*16 + gID;
            int col  = bn + wn*32 + nt*8 + qid*2;
            float2 v0 = make_float2(acc[mt][nt][0], acc[mt][nt][1]);
            float2 v1 = make_float2(acc[mt][nt][2], acc[mt][nt][3]);
            if (BIAS){
                float2 bv = *(const float2*)&bias[col];
                v0.x += bv.x; v0.y += bv.y;
                v1.x += bv.x; v1.y += bv.y;
            }
            float* p0 = C + (size_t)row0*N + col;
            float* p1 = C + (size_t)(row0+8)*N + col;
            if (ADD){
                float2 o0 = *(const float2*)p0, o1 = *(const float2*)p1;
                v0.x += o0.x; v0.y += o0.y;
                v1.x += o1.x; v1.y += o1.y;
            }
            *(float2*)p0 = v0;
            *(float2*)p1 = v1;
        }
    }
}

// ---------------- weight transpose + bf16 split: W[K][N] -> Wt[N][K] ---------
__global__ void k_wt(const float* __restrict__ W, int K, int N){
    __shared__ float t[32][33];
    int bk = blockIdx.x*32, bn = blockIdx.y*32;
    int tx = threadIdx.x, ty = threadIdx.y;  // 32 x 8
    #pragma unroll
    for (int r = 0; r < 32; r += 8)
        t[ty+r][tx] = W[(size_t)(bk+ty+r)*N + bn+tx];
    __syncthreads();
    #pragma unroll
    for (int r = 0; r < 32; r += 8){
        float v = t[tx][ty+r];
        __nv_bfloat16 h = __float2bfloat16(v);
        size_t o = (size_t)(bn+ty+r)*K + bk+tx;
        g_wt_hi[o] = h;
        g_wt_lo[o] = __float2bfloat16(v - __bfloat162float(h));
    }
}

// ---------------- densify + transpose + split slstm gate weights -------------
__global__ void k_sgx_prep(const float* __restrict__ gw){
    int idx = blockIdx.x*blockDim.x + threadIdx.x;   // over 128*512
    if (idx >= Dd*4*Dd) return;
    int d = idx >> 9;          // 0..127
    int o = idx & 511;         // (g, n, e)
    int g = o >> 7;
    int ne = o & 127;
    int n = ne >> 5, e = ne & 31;
    float wv = 0.0f;
    if ((d >> 5) == n) wv = gw[(((g*NHs + n)*HDs + e)*HDs) + (d & 31)];
    __nv_bfloat16 h = __float2bfloat16(wv);
    g_wt_hi[(size_t)o*Dd + d] = h;
    g_wt_lo[(size_t)o*Dd + d] = __float2bfloat16(wv - __bfloat162float(h));
}

// ---------------- embedding --------------------------------------------------
__global__ void k_embed(const int* __restrict__ x, const float* __restrict__ emb){
    int t = blockIdx.x;
    g_h[t*Dd + threadIdx.x] = emb[x[t]*Dd + threadIdx.x];
}

// ---------------- sLSTM recurrence scan: 8 warps/block, shared weights -------
__global__ void __launch_bounds__(256) k_scan(const float* __restrict__ rec){
    int n  = blockIdx.x & 3;
    int bg = blockIdx.x >> 2;           // 0..63
    int w  = threadIdx.x >> 5;
    int e  = threadIdx.x & 31;
    int b  = bg*8 + w;
    __shared__ float rw[4][HDs][36];
    __shared__ float hs[8][HDs];
    for (int idx = threadIdx.x; idx < 4*HDs*HDs; idx += 256){
        int g = idx >> 10, rem = idx & 1023;
        int e2 = rem >> 5, d = rem & 31;
        rw[g][e2][d] = rec[((size_t)(g*NHs+n)*HDs + e2)*HDs + d];
    }
    hs[w][e] = 0.0f;
    __syncthreads();
    float c=0.0f, nn=0.0f, m=0.0f;
    const int gb = n*HDs + e;
    for(int s=0;s<Ss;s++){
        const float* gxp = g_big + (size_t)(b*Ss + s)*512 + gb;   // token-major
        float r0=gxp[0], r1=gxp[Dd], r2=gxp[2*Dd], r3=gxp[3*Dd];
        #pragma unroll
        for(int dq=0; dq<8; dq++){
            float4 hv = *(const float4*)&hs[w][dq*4];
            float4 w0 = *(const float4*)&rw[0][e][dq*4];
            float4 w1 = *(const float4*)&rw[1][e][dq*4];
            float4 w2 = *(const float4*)&rw[2][e][dq*4];
            float4 w3 = *(const float4*)&rw[3][e][dq*4];
            r0 += hv.x*w0.x + hv.y*w0.y + hv.z*w0.z + hv.w*w0.w;
            r1 += hv.x*w1.x + hv.y*w1.y + hv.z*w1.z + hv.w*w1.w;
            r2 += hv.x*w2.x + hv.y*w2.y + hv.z*w2.z + hv.w*w2.w;
            r3 += hv.x*w3.x + hv.y*w3.y + hv.z*w3.z + hv.w*w3.w;
        }
        float lfm = m + logsigf(r1);
        float mn  = fmaxf(r0, lfm);
        float i   = expf(r0-mn);
        float f   = expf(lfm-mn);
        c  = f*c + i*tanhf(r2);
        nn = f*nn + i;
        float hnew = sigf(r3) * c / nn;
        m = mn;
        __syncwarp();
        hs[w][e] = hnew;
        __syncwarp();
        g_y[((size_t)(b*Ss+s))*Dd + gb] = hnew;
    }
}

// ---------------- sLSTM group norm (G=32) + residual add into g_h ------------
__global__ void k_gn_slstm(const float* __restrict__ gn){
    int t = blockIdx.x;
    int n = threadIdx.x >> 5, lane = threadIdx.x & 31;
    float v = g_y[(size_t)t*Dd + n*HDs + lane];
    float s=v, ss=v*v;
    #pragma unroll
    for(int o=16;o;o>>=1){ s += __shfl_xor_sync(~0u,s,o); ss += __shfl_xor_sync(~0u,ss,o); }
    float mu = s*(1.0f/HDs), var = ss*(1.0f/HDs)-mu*mu;
    float r = rsqrtf(var + 1e-5f);
    g_h[(size_t)t*Dd + n*HDs + lane] += (v-mu)*r*gn[n*HDs+lane];
}

// ---------------- mLSTM causal depthwise conv + silu -------------------------
__global__ void k_conv(const float* __restrict__ cw, const float* __restrict__ cb){
    int t = blockIdx.x; int c = threadIdx.x;
    int b = t/Ss, s = t%Ss;
    float acc = cb[c];
    #pragma unroll
    for(int tt=0; tt<Kc; tt++){
        int si = s - (Kc-1) + tt;
        if (si >= 0) acc += g_big[((size_t)(b*Ss+si))*2*INNERc + c]*cw[c*Kc+tt];
    }
    g_xconv[(size_t)t*INNERc + c] = acc*sigf(acc);
}

// ---------------- blocked qkv projections ------------------------------------
__global__ void k_qkv(const float* __restrict__ w){
    int t = blockIdx.x; int c = threadIdx.x;
    int n = c >> 2, o = c & 3;
    const float* wq = w + n*16 + o*4;
    const float* wk = wq + NBc*16;
    const float* wv = wk + NBc*16;
    const float* xc = g_xconv + (size_t)t*INNERc + n*4;
    const float* xm = g_big   + (size_t)t*2*INNERc + n*4;
    float q=0,k=0,v=0;
    #pragma unroll
    for(int i=0;i<4;i++){ q += xc[i]*wq[i]; k += xc[i]*wk[i]; v += xm[i]*wv[i]; }
    g_q[(size_t)t*INNERc+c]=q; g_k[(size_t)t*INNERc+c]=k; g_v[(size_t)t*INNERc+c]=v;
}

// ---------------- input/forget gates: 32 tokens/block, weights in smem -------
__global__ void __launch_bounds__(256) k_gates(
        const float* __restrict__ igw, const float* __restrict__ igb,
        const float* __restrict__ fgw, const float* __restrict__ fgb){
    __shared__ float4 iws[3*INNERc];
    __shared__ float4 fws[3*INNERc];
    for (int j = threadIdx.x; j < 3*INNERc; j += 256){
        iws[j] = *(const float4*)&igw[j*NHMc];
        fws[j] = *(const float4*)&fgw[j*NHMc];
    }
    __syncthreads();
    int w = threadIdx.x >> 5, lane = threadIdx.x & 31;
    int t0 = blockIdx.x*32 + w*4;
    for (int tt = 0; tt < 4; tt++){
        int t = t0 + tt;
        float ia0=0,ia1=0,ia2=0,ia3=0, fa0=0,fa1=0,fa2=0,fa3=0;
        const float* qp = g_q + (size_t)t*INNERc;
        const float* kp = g_k + (size_t)t*INNERc;
        const float* vp = g_v + (size_t)t*INNERc;
        for (int j = lane; j < 3*INNERc; j += 32){
            float val = (j < INNERc) ? qp[j] : (j < 2*INNERc) ? kp[j-INNERc] : vp[j-2*INNERc];
            float4 iw = iws[j], fw = fws[j];
            ia0 += val*iw.x; ia1 += val*iw.y; ia2 += val*iw.z; ia3 += val*iw.w;
            fa0 += val*fw.x; fa1 += val*fw.y; fa2 += val*fw.z; fa3 += val*fw.w;
        }
        #pragma unroll
        for (int o=16;o;o>>=1){
            ia0 += __shfl_xor_sync(~0u,ia0,o); ia1 += __shfl_xor_sync(~0u,ia1,o);
            ia2 += __shfl_xor_sync(~0u,ia2,o); ia3 += __shfl_xor_sync(~0u,ia3,o);
            fa0 += __shfl_xor_sync(~0u,fa0,o); fa1 += __shfl_xor_sync(~0u,fa1,o);
            fa2 += __shfl_xor_sync(~0u,fa2,o); fa3 += __shfl_xor_sync(~0u,fa3,o);
        }
        if (lane == 0){
            int b = t/Ss, s = t%Ss;
            g_ig[(size_t)(b*NHMc+0)*Ss + s] = ia0 + igb[0];
            g_ig[(size_t)(b*NHMc+1)*Ss + s] = ia1 + igb[1];
            g_ig[(size_t)(b*NHMc+2)*Ss + s] = ia2 + igb[2];
            g_ig[(size_t)(b*NHMc+3)*Ss + s] = ia3 + igb[3];
            g_fg[(size_t)(b*NHMc+0)*Ss + s] = fa0 + fgb[0];
            g_fg[(size_t)(b*NHMc+1)*Ss + s] = fa1 + fgb[1];
            g_fg[(size_t)(b*NHMc+2)*Ss + s] = fa2 + fgb[2];
            g_fg[(size_t)(b*NHMc+3)*Ss + s] = fa3 + fgb[3];
        }
    }
}

// ---------------- mLSTM attention: block per (b, head), v in smem ------------
__global__ void __launch_bounds__(256) k_attn(){
    int blk = blockIdx.x; int b = blk >> 2, hm = blk & 3;
    __shared__ float qs[Ss][DHMc+1], ks[Ss][DHMc+1], vs[Ss][DHMc+1];
    __shared__ float cldf[Ss+1], igs[Ss];
    __shared__ float cn[8][Ss];
    int tid = threadIdx.x;
    for(int l=tid; l<Ss*DHMc; l+=256){
        int j = l >> 6, d = l & 63;
        size_t base = ((size_t)(b*Ss+j))*INNERc + hm*DHMc + d;
        qs[j][d] = g_q[base];
        ks[j][d] = g_k[base];
        vs[j][d] = g_v[base];
    }
    if (tid < Ss) igs[tid] = g_ig[(size_t)(b*NHMc+hm)*Ss + tid];
    if (tid == 0){
        float cacc = 0.0f; cldf[0] = 0.0f;
        for(int s=0;s<Ss;s++){ cacc += logsigf(g_fg[(size_t)(b*NHMc+hm)*Ss + s]); cldf[s+1]=cacc; }
    }
    __syncthreads();
    int w = tid >> 5, lane = tid & 31;
    for(int r=0;r<8;r++){
        int i = w*8 + r;
        int j1 = lane + 32;
        float dot0=0, dot1=0, ld0=-1e30f, ld1=-1e30f;
        if (lane <= i){
            #pragma unroll
            for(int d=0; d<DHMc; d++) dot0 += qs[i][d]*ks[lane][d];
            ld0 = cldf[i+1]-cldf[lane+1] + igs[lane];
        }
        if (j1 <= i){
            #pragma unroll
            for(int d=0; d<DHMc; d++) dot1 += qs[i][d]*ks[j1][d];
            ld1 = cldf[i+1]-cldf[j1+1] + igs[j1];
        }
        float mx = fmaxf(ld0, ld1);
        #pragma unroll
        for(int o=16;o;o>>=1) mx = fmaxf(mx, __shfl_xor_sync(~0u,mx,o));
        float cm0 = (lane <= i) ? dot0*0.125f*expf(ld0-mx) : 0.0f;
        float cm1 = (j1   <= i) ? dot1*0.125f*expf(ld1-mx) : 0.0f;
        float sm = cm0 + cm1;
        #pragma unroll
        for(int o=16;o;o>>=1) sm += __shfl_xor_sync(~0u,sm,o);
        float norm = fmaxf(fabsf(sm), expf(-mx)) + 1e-6f;
        cn[w][lane] = cm0/norm;
        cn[w][j1]   = cm1/norm;
        __syncwarp();
        float a0=0, a1=0;
        for(int j=0;j<=i;j++){
            float cc = cn[w][j];
            a0 += cc*vs[j][lane];
            a1 += cc*vs[j][lane+32];
        }
        g_hatt[((size_t)(b*Ss+i))*INNERc + hm*DHMc + lane]      = a0;
        g_hatt[((size_t)(b*Ss+i))*INNERc + hm*DHMc + lane + 32] = a1;
        __syncwarp();
    }
}

// ---------------- mLSTM groupnorm (G=64) + skip/silu combine -----------------
__global__ void k_gn_comb(const float* __restrict__ onw, const float* __restrict__ skip){
    int t = blockIdx.x;
    int hm = threadIdx.x >> 5, lane = threadIdx.x & 31;
    size_t base = (size_t)t*INNERc + hm*DHMc;
    float v0 = g_hatt[base+lane], v1 = g_hatt[base+lane+32];
    float s = v0+v1, ss = v0*v0+v1*v1;
    #pragma unroll
    for(int o=16;o;o>>=1){ s += __shfl_xor_sync(~0u,s,o); ss += __shfl_xor_sync(~0u,ss,o); }
    float mu = s*(1.0f/DHMc), var = ss*(1.0f/DHMc)-mu*mu;
    float r = rsqrtf(var + 1e-5f);
    #pragma unroll
    for(int p=0;p<2;p++){
        int c = hm*DHMc + lane + p*32;
        float v = p ? v1 : v0;
        float z = g_big[(size_t)t*2*INNERc + INNERc + c];
        float out = ((v-mu)*r*onw[c] + skip[c]*g_xconv[(size_t)t*INNERc + c]) * z*sigf(z);
        g_q[(size_t)t*INNERc + c] = out;   // reuse g_q as combine buffer
    }
}

// ---------------- host-side --------------------------------------------------
static float* symf(const void* s){ void* p=nullptr; cudaGetSymbolAddress(&p, s); return (float*)p; }

extern "C" void kernel_launch(void* const* d_in, const int* in_sizes, int n_in,
                              void* d_out, int out_size){
    const int*   x         = (const int*)  d_in[0];
    const float* embed     = (const float*)d_in[1];
    const float* s_ln1     = (const float*)d_in[2];
    const float* s_gates_w = (const float*)d_in[3];
    const float* s_rec     = (const float*)d_in[4];
    const float* s_bias    = (const float*)d_in[5];
    const float* s_gn      = (const float*)d_in[6];
    const float* s_ln2     = (const float*)d_in[7];
    const float* s_ff_up   = (const float*)d_in[8];
    const float* s_ff_down = (const float*)d_in[9];
    const float* m_ln1     = (const float*)d_in[10];
    const float* m_up      = (const float*)d_in[11];
    const float* m_conv_w  = (const float*)d_in[12];
    const float* m_conv_b  = (const float*)d_in[13];
    const float* m_qkv_w   = (const float*)d_in[14];
    const float* m_ig_w    = (const float*)d_in[15];
    const float* m_ig_b    = (const float*)d_in[16];
    const float* m_fg_w    = (const float*)d_in[17];
    const float* m_fg_b    = (const float*)d_in[18];
    const float* m_skip    = (const float*)d_in[19];
    const float* m_onorm   = (const float*)d_in[20];
    const float* m_down    = (const float*)d_in[21];
    const float* m_ln2     = (const float*)d_in[22];
    const float* m_ff_up   = (const float*)d_in[23];
    const float* m_ff_down = (const float*)d_in[24];
    const float* post_ln   = (const float*)d_in[25];
    const float* head_w    = (const float*)d_in[26];
    const float* head_b    = (const float*)d_in[27];

    float* h    = symf(g_h);
    float* big  = symf(g_big);
    float* ffn  = symf(g_ffn);
    float* qb   = symf(g_q);

    float* out = (float*)d_out;

    cudaFuncSetAttribute(k_mgemm<false,true ,true ,false>, cudaFuncAttributeMaxDynamicSharedMemorySize, MG_SMEM);
    cudaFuncSetAttribute(k_mgemm<false,false,true ,false>, cudaFuncAttributeMaxDynamicSharedMemorySize, MG_SMEM);
    cudaFuncSetAttribute(k_mgemm<true ,false,false,true >, cudaFuncAttributeMaxDynamicSharedMemorySize, MG_SMEM);
    cudaFuncSetAttribute(k_mgemm<true ,false,false,false>, cudaFuncAttributeMaxDynamicSharedMemorySize, MG_SMEM);

    k_embed<<<Tt, Dd>>>(x, embed);

    for(int i=0;i<2;i++){
        // ---- sLSTM block (LN fused into gate GEMM) ----
        k_sgx_prep<<<(Dd*4*Dd+255)/256,256>>>(s_gates_w + (size_t)i*4*NHs*HDs*HDs);
        k_mgemm<false,true,true,false><<<dim3(8, Tt/128),256,MG_SMEM>>>(
            h, big, s_bias + i*4*Dd, s_ln1 + i*Dd, 4*Dd, Dd);
        k_scan<<<NHs*(Bb/8),256>>>(s_rec + (size_t)i*4*NHs*HDs*HDs);
        k_gn_slstm<<<Tt,128>>>(s_gn + i*Dd);

        // ---- FFN 1 (LN fused into up, GLU fused into down) ----
        k_wt<<<dim3(Dd/32, 2*FFc/32), dim3(32,8)>>>(s_ff_up + (size_t)i*Dd*2*FFc, Dd, 2*FFc);
        k_mgemm<false,false,true,false><<<dim3(4, Tt/128),256,MG_SMEM>>>(
            h, ffn, nullptr, s_ln2 + i*Dd, 2*FFc, Dd);
        k_wt<<<dim3(FFc/32, Dd/32), dim3(32,8)>>>(s_ff_down + (size_t)i*FFc*Dd, FFc, Dd);
        k_mgemm<true,false,false,true><<<dim3(2, Tt/128),256,MG_SMEM>>>(
            ffn, h, nullptr, nullptr, Dd, FFc);

        // ---- mLSTM block ----
        k_wt<<<dim3(Dd/32, 2*INNERc/32), dim3(32,8)>>>(m_up + (size_t)i*Dd*2*INNERc, Dd, 2*INNERc);
        k_mgemm<false,false,true,false><<<dim3(8, Tt/128),256,MG_SMEM>>>(
            h, big, nullptr, m_ln1 + i*Dd, 2*INNERc, Dd);
        k_conv<<<Tt,INNERc>>>(m_conv_w + (size_t)i*INNERc*Kc, m_conv_b + i*INNERc);
        k_qkv<<<Tt,INNERc>>>(m_qkv_w + (size_t)i*3*NBc*16);
        k_gates<<<Tt/32,256>>>(m_ig_w + (size_t)i*3*INNERc*NHMc, m_ig_b + i*NHMc,
                               m_fg_w + (size_t)i*3*INNERc*NHMc, m_fg_b + i*NHMc);
        k_attn<<<Bb*NHMc,256>>>();
        k_gn_comb<<<Tt,128>>>(m_onorm + i*INNERc, m_skip + i*INNERc);
        k_wt<<<dim3(INNERc/32, Dd/32), dim3(32,8)>>>(m_down + (size_t)i*INNERc*Dd, INNERc, Dd);
        k_mgemm<true,false,false,false><<<dim3(2, Tt/128),256,MG_SMEM>>>(
            qb, h, nullptr, nullptr, Dd, INNERc);

        // ---- FFN 2 ----
        k_wt<<<dim3(Dd/32, 2*FFc/32), dim3(32,8)>>>(m_ff_up + (size_t)i*Dd*2*FFc, Dd, 2*FFc);
        k_mgemm<false,false,true,false><<<dim3(4, Tt/128),256,MG_SMEM>>>(
            h, ffn, nullptr, m_ln2 + i*Dd, 2*FFc, Dd);
        k_wt<<<dim3(FFc/32, Dd/32), dim3(32,8)>>>(m_ff_down + (size_t)i*FFc*Dd, FFc, Dd);
        k_mgemm<true,false,false,true><<<dim3(2, Tt/128),256,MG_SMEM>>>(
            ffn, h, nullptr, nullptr, Dd, FFc);
    }

    // ---- final LN + head (LN fused) ----
    k_wt<<<dim3(Dd/32, Vv/32), dim3(32,8)>>>(head_w, Dd, Vv);
    k_mgemm<false,true,true,false><<<dim3(4, Tt/128),256,MG_SMEM>>>(
        h, out, head_b, post_ln, Vv, Dd);
}

// round 8
// speedup vs baseline: 5.3495x; 1.1749x over previous
#include <cuda_runtime.h>
#include <cuda_bf16.h>
#include <math.h>
#include <stdint.h>

#define Bb     512
#define Ss     64
#define Dd     128
#define Vv     256
#define NHs    4
#define HDs    32
#define INNERc 256
#define NHMc   4
#define DHMc   64
#define NBc    64
#define Kc     4
#define FFc    128
#define Tt     (Bb*Ss)   /* 32768 tokens */

// ---------------- workspaces (static device globals; no allocation) ----------
__device__ float g_h[Tt*Dd];            // residual stream
__device__ float g_big[Tt*2*INNERc];    // slstm gx [t][512]  OR  mlstm up out [t][512]
__device__ float g_ffn[Tt*2*FFc];       // ffn up output
__device__ float g_xconv[Tt*INNERc];
__device__ float g_q[Tt*INNERc];        // q, later reused as mlstm combine buffer
__device__ float g_k[Tt*INNERc];
__device__ float g_v[Tt*INNERc];
__device__ float g_ig[Bb*NHMc*Ss];
__device__ float g_fg[Bb*NHMc*Ss];

// all GEMM weights, transposed+split [N][K]
#define W_SGX(i)  ((i)*262144 + 0)
#define W_SFU(i)  ((i)*262144 + 65536)
#define W_SFD(i)  ((i)*262144 + 98304)
#define W_MUP(i)  ((i)*262144 + 114688)
#define W_MDN(i)  ((i)*262144 + 180224)
#define W_MFU(i)  ((i)*262144 + 212992)
#define W_MFD(i)  ((i)*262144 + 245760)
#define W_HEAD    (524288)
#define W_TOTAL   (557056)
__device__ __nv_bfloat16 g_wt_hi[W_TOTAL];
__device__ __nv_bfloat16 g_wt_lo[W_TOTAL];
__device__ float g_gw_eff[2*4096];      // folded gate weights [L][4][256][4]

// ---------------- device math helpers ---------------------------------------
__device__ __forceinline__ float sigf(float x){ return 1.0f/(1.0f+expf(-x)); }
__device__ __forceinline__ float logsigf(float x){ return fminf(x,0.0f) - log1pf(expf(-fabsf(x))); }
__device__ __forceinline__ float geluf(float x){
    float x3 = x*x*x;
    return 0.5f*x*(1.0f+tanhf(0.7978845608028654f*(x+0.044715f*x3)));
}
__device__ __forceinline__ uint32_t smem_u32(const void* p){
    uint32_t a;
    asm("{ .reg .u64 t; cvta.to.shared.u64 t, %1; cvt.u32.u64 %0, t; }" : "=r"(a) : "l"(p));
    return a;
}
__device__ __forceinline__ void split2(float a, float b, uint32_t &hi, uint32_t &lo){
    __nv_bfloat162 h = __floats2bfloat162_rn(a, b);
    float ra = a - __bfloat162float(h.x);
    float rb = b - __bfloat162float(h.y);
    __nv_bfloat162 l = __floats2bfloat162_rn(ra, rb);
    hi = *(uint32_t*)&h; lo = *(uint32_t*)&l;
}

#define LDM4(r0,r1,r2,r3,addr) \
    asm volatile("ldmatrix.sync.aligned.m8n8.x4.shared.b16 {%0,%1,%2,%3}, [%4];" \
        : "=r"(r0),"=r"(r1),"=r"(r2),"=r"(r3) : "r"(addr))

#define MMA16816(d,a,b) \
    asm volatile("mma.sync.aligned.m16n8k16.row.col.f32.bf16.bf16.f32 " \
        "{%0,%1,%2,%3}, {%4,%5,%6,%7}, {%8,%9}, {%0,%1,%2,%3};" \
        : "+f"((d)[0]),"+f"((d)[1]),"+f"((d)[2]),"+f"((d)[3]) \
        : "r"((a)[0]),"r"((a)[1]),"r"((a)[2]),"r"((a)[3]), "r"((b)[0]),"r"((b)[1]))

// smem layout: A tiles 128x136 bf16 (hi/lo), B tiles 64x136 bf16 (hi/lo)
#define MG_STRIDE 136
#define MG_AH 0
#define MG_AL (128*MG_STRIDE*2)
#define MG_BH (2*128*MG_STRIDE*2)
#define MG_BL (MG_BH + 64*MG_STRIDE*2)
#define MG_SMEM (MG_BL + 64*MG_STRIDE*2)   /* 104448 B */

// ---------------- tensor-core GEMM: C[M,N] (+)= f(A)[M,K] @ Wt^T (+bias) -----
template<bool ADD, bool BIAS, bool LN, bool GLU>
__global__ void __launch_bounds__(256,2) k_mgemm(
        const float* __restrict__ A, float* __restrict__ C,
        const float* __restrict__ bias, const float* __restrict__ lnw,
        int woff, int N, int K){
    extern __shared__ char smem[];
    const int tid = threadIdx.x, w = tid>>5, lane = tid&31;
    const int bm = blockIdx.y*128, bn = blockIdx.x*64;
    const int wm = w & 3, wn = w >> 2;
    const int gID = lane >> 2, qid = lane & 3;

    float acc[2][4][4] = {};

    const int a_row = lane & 15;
    const int a_koff = (lane >> 4) * 8;
    const int b_noff = (lane & 7) + ((lane >> 4) & 1) * 8;
    const int b_koff = ((lane >> 3) & 1) * 8;

    const uint32_t sb = smem_u32(smem);

    const int nchunk = K >> 7;
    for (int kc = 0; kc < nchunk; kc++){
        // ---- stage A chunk ----
        #pragma unroll
        for (int it = 0; it < 8; it++){
            int g4 = tid + it*256;
            int row = g4 >> 4, kg = g4 & 15;
            float4 v0, v1;
            if (GLU){
                const float* ap = A + (size_t)(bm+row)*256 + kg*8;
                float4 gg0 = *(const float4*)ap,      gg1 = *(const float4*)(ap+4);
                float4 uu0 = *(const float4*)(ap+128), uu1 = *(const float4*)(ap+132);
                v0.x = geluf(gg0.x)*uu0.x; v0.y = geluf(gg0.y)*uu0.y;
                v0.z = geluf(gg0.z)*uu0.z; v0.w = geluf(gg0.w)*uu0.w;
                v1.x = geluf(gg1.x)*uu1.x; v1.y = geluf(gg1.y)*uu1.y;
                v1.z = geluf(gg1.z)*uu1.z; v1.w = geluf(gg1.w)*uu1.w;
            } else {
                const float4* ap = (const float4*)(A + (size_t)(bm+row)*K + kc*128 + kg*8);
                v0 = ap[0]; v1 = ap[1];
            }
            if (LN){
                float s  = v0.x+v0.y+v0.z+v0.w + v1.x+v1.y+v1.z+v1.w;
                float ss = v0.x*v0.x+v0.y*v0.y+v0.z*v0.z+v0.w*v0.w
                         + v1.x*v1.x+v1.y*v1.y+v1.z*v1.z+v1.w*v1.w;
                #pragma unroll
                for (int o = 1; o < 16; o <<= 1){
                    s  += __shfl_xor_sync(~0u, s,  o);
                    ss += __shfl_xor_sync(~0u, ss, o);
                }
                float mu  = s*(1.0f/128.0f);
                float var = ss*(1.0f/128.0f) - mu*mu;
                float rr  = rsqrtf(var + 1e-5f);
                float4 w0 = *(const float4*)&lnw[kg*8];
                float4 w1 = *(const float4*)&lnw[kg*8+4];
                v0.x = (v0.x-mu)*rr*w0.x; v0.y = (v0.y-mu)*rr*w0.y;
                v0.z = (v0.z-mu)*rr*w0.z; v0.w = (v0.w-mu)*rr*w0.w;
                v1.x = (v1.x-mu)*rr*w1.x; v1.y = (v1.y-mu)*rr*w1.y;
                v1.z = (v1.z-mu)*rr*w1.z; v1.w = (v1.w-mu)*rr*w1.w;
            }
            uint32_t h0,h1,h2,h3, l0,l1,l2,l3;
            split2(v0.x, v0.y, h0, l0);
            split2(v0.z, v0.w, h1, l1);
            split2(v1.x, v1.y, h2, l2);
            split2(v1.z, v1.w, h3, l3);
            uint32_t off = (uint32_t)(row*(MG_STRIDE*2) + kg*16);
            *(uint4*)(smem + MG_AH + off) = make_uint4(h0,h1,h2,h3);
            *(uint4*)(smem + MG_AL + off) = make_uint4(l0,l1,l2,l3);
        }
        // ---- stage B chunk ----
        #pragma unroll
        for (int it = 0; it < 4; it++){
            int g4 = tid + it*256;
            int n = g4 >> 4, kg = g4 & 15;
            size_t gi = (size_t)woff + (size_t)(bn+n)*K + kc*128 + kg*8;
            uint4 hv = *(const uint4*)(g_wt_hi + gi);
            uint4 lv = *(const uint4*)(g_wt_lo + gi);
            uint32_t off = (uint32_t)(n*(MG_STRIDE*2) + kg*16);
            *(uint4*)(smem + MG_BH + off) = hv;
            *(uint4*)(smem + MG_BL + off) = lv;
        }
        __syncthreads();

        #pragma unroll
        for (int ks = 0; ks < 8; ks++){
            uint32_t ah[2][4], al[2][4];
            #pragma unroll
            for (int mt = 0; mt < 2; mt++){
                uint32_t aoff = (uint32_t)((wm*32 + mt*16 + a_row)*(MG_STRIDE*2)
                                           + (ks*16 + a_koff)*2);
                LDM4(ah[mt][0],ah[mt][1],ah[mt][2],ah[mt][3], sb + MG_AH + aoff);
                LDM4(al[mt][0],al[mt][1],al[mt][2],al[mt][3], sb + MG_AL + aoff);
            }
            uint32_t bh[4][2], bl[4][2];
            #pragma unroll
            for (int ng = 0; ng < 2; ng++){
                uint32_t boff = (uint32_t)((wn*32 + ng*16 + b_noff)*(MG_STRIDE*2)
                                           + (ks*16 + b_koff)*2);
                uint32_t r0,r1,r2,r3;
                LDM4(r0,r1,r2,r3, sb + MG_BH + boff);
                bh[ng*2][0]=r0; bh[ng*2][1]=r1; bh[ng*2+1][0]=r2; bh[ng*2+1][1]=r3;
                LDM4(r0,r1,r2,r3, sb + MG_BL + boff);
                bl[ng*2][0]=r0; bl[ng*2][1]=r1; bl[ng*2+1][0]=r2; bl[ng*2+1][1]=r3;
            }
            #pragma unroll
            for (int mt = 0; mt < 2; mt++)
                #pragma unroll
                for (int nt = 0; nt < 4; nt++){
                    MMA16816(acc[mt][nt], ah[mt], bh[nt]);
                    MMA16816(acc[mt][nt], ah[mt], bl[nt]);
                    MMA16816(acc[mt][nt], al[mt], bh[nt]);
                }
        }
        __syncthreads();
    }

    #pragma unroll
    for (int mt = 0; mt < 2; mt++){
        #pragma unroll
        for (int nt = 0; nt < 4; nt++){
            int row0 = bm + wm*32 + mt*16 + gID;
            int col  = bn + wn*32 + nt*8 + qid*2;
            float2 v0 = make_float2(acc[mt][nt][0], acc[mt][nt][1]);
            float2 v1 = make_float2(acc[mt][nt][2], acc[mt][nt][3]);
            if (BIAS){
                float2 bv = *(const float2*)&bias[col];
                v0.x += bv.x; v0.y += bv.y;
                v1.x += bv.x; v1.y += bv.y;
            }
            float* p0 = C + (size_t)row0*N + col;
            float* p1 = C + (size_t)(row0+8)*N + col;
            if (ADD){
                float2 o0 = *(const float2*)p0, o1 = *(const float2*)p1;
                v0.x += o0.x; v0.y += o0.y;
                v1.x += o1.x; v1.y += o1.y;
            }
            *(float2*)p0 = v0;
            *(float2*)p1 = v1;
        }
    }
}

// ---------------- one-shot weight prep: transposes + densify + gate folding --
__global__ void __launch_bounds__(256) k_prep(
    const float* sgw0, const float* sgw1,
    const float* sfu0, const float* sfd0, const float* mup0, const float* mdn0,
    const float* mfu0, const float* mfd0,
    const float* sfu1, const float* sfd1, const float* mup1, const float* mdn1,
    const float* mfu1, const float* mfd1,
    const float* headw,
    const float* qkvw, const float* igw, const float* fgw){
    int bx = blockIdx.x, tid = threadIdx.x;
    if (bx < 416){
        const int cum[13]  = {32,48,112,144,176,192,224,240,304,336,368,384,416};
        const float* srcs[13] = {sfu0,sfd0,mup0,mdn0,mfu0,mfd0,sfu1,sfd1,mup1,mdn1,mfu1,mfd1,headw};
        const int Ks[13]   = {128,128,128,256,128,128,128,128,128,256,128,128,128};
        const int Ns[13]   = {256,128,512,128,256,128,256,128,512,128,256,128,256};
        const int dsts[13] = {W_SFU(0),W_SFD(0),W_MUP(0),W_MDN(0),W_MFU(0),W_MFD(0),
                              W_SFU(1),W_SFD(1),W_MUP(1),W_MDN(1),W_MFU(1),W_MFD(1),W_HEAD};
        int j = 0;
        while (bx >= cum[j]) j++;
        int tile = bx - (j ? cum[j-1] : 0);
        const float* src = srcs[j];
        int K = Ks[j], N = Ns[j], dst = dsts[j];
        int tilesN = N >> 5;
        int bk = (tile / tilesN)*32, bn = (tile % tilesN)*32;
        __shared__ float t[32][33];
        int tx = tid & 31, ty = tid >> 5;
        #pragma unroll
        for (int r = 0; r < 32; r += 8)
            t[ty+r][tx] = src[(size_t)(bk+ty+r)*N + bn+tx];
        __syncthreads();
        #pragma unroll
        for (int r = 0; r < 32; r += 8){
            float v = t[tx][ty+r];
            __nv_bfloat16 h = __float2bfloat16(v);
            size_t o = (size_t)dst + (size_t)(bn+ty+r)*K + bk+tx;
            g_wt_hi[o] = h;
            g_wt_lo[o] = __float2bfloat16(v - __bfloat162float(h));
        }
    } else if (bx < 544){
        int bx2 = bx - 416;
        int L = bx2 >> 6, blk = bx2 & 63;
        const float* gw = L ? sgw1 : sgw0;
        #pragma unroll
        for (int u = 0; u < 4; u++){
            int idx = blk*1024 + u*256 + tid;     // over 128*512
            int d = idx >> 9;
            int o = idx & 511;
            int g = o >> 7;
            int ne = o & 127;
            int n = ne >> 5, e = ne & 31;
            float wv = 0.0f;
            if ((d >> 5) == n) wv = gw[(((g*NHs + n)*HDs + e)*HDs) + (d & 31)];
            __nv_bfloat16 h = __float2bfloat16(wv);
            size_t oo = (size_t)W_SGX(L) + (size_t)o*Dd + d;
            g_wt_hi[oo] = h;
            g_wt_lo[oo] = __float2bfloat16(wv - __bfloat162float(h));
        }
    } else {
        int L = bx - 544;
        const float* qw  = qkvw + L*3072;
        const float* igp = igw  + L*3072;
        const float* fgp = fgw  + L*3072;
        int c = tid, n = c >> 2, i = c & 3;
        float aig[4]={0,0,0,0}, big_[4]={0,0,0,0}, afg[4]={0,0,0,0}, bfg_[4]={0,0,0,0};
        #pragma unroll
        for (int o = 0; o < 4; o++){
            float w0 = qw[n*16+o*4+i];
            float w1 = qw[1024+n*16+o*4+i];
            float w2 = qw[2048+n*16+o*4+i];
            int j0 = (n*4+o)*4, j1 = (256+n*4+o)*4, j2 = (512+n*4+o)*4;
            #pragma unroll
            for (int hm = 0; hm < 4; hm++){
                aig[hm]  += w0*igp[j0+hm] + w1*igp[j1+hm];
                big_[hm] += w2*igp[j2+hm];
                afg[hm]  += w0*fgp[j0+hm] + w1*fgp[j1+hm];
                bfg_[hm] += w2*fgp[j2+hm];
            }
        }
        #pragma unroll
        for (int hm = 0; hm < 4; hm++){
            g_gw_eff[L*4096 + 0*1024 + c*4 + hm] = aig[hm];
            g_gw_eff[L*4096 + 1*1024 + c*4 + hm] = big_[hm];
            g_gw_eff[L*4096 + 2*1024 + c*4 + hm] = afg[hm];
            g_gw_eff[L*4096 + 3*1024 + c*4 + hm] = bfg_[hm];
        }
    }
}

// ---------------- embedding --------------------------------------------------
__global__ void k_embed(const int* __restrict__ x, const float* __restrict__ emb){
    int t = blockIdx.x;
    g_h[t*Dd + threadIdx.x] = emb[x[t]*Dd + threadIdx.x];
}

// ---------------- sLSTM scan + fused group-norm/residual, gx prefetched ------
__global__ void __launch_bounds__(256) k_scan(const float* __restrict__ rec,
                                              const float* __restrict__ gn){
    int n  = blockIdx.x & 3;
    int bg = blockIdx.x >> 2;
    int w  = threadIdx.x >> 5;
    int e  = threadIdx.x & 31;
    int b  = bg*8 + w;
    __shared__ float rw[4][HDs][36];
    __shared__ float hs[8][HDs];
    for (int idx = threadIdx.x; idx < 4*HDs*HDs; idx += 256){
        int g = idx >> 10, rem = idx & 1023;
        int e2 = rem >> 5, d = rem & 31;
        rw[g][e2][d] = rec[((size_t)(g*NHs+n)*HDs + e2)*HDs + d];
    }
    hs[w][e] = 0.0f;
    __syncthreads();
    const int gb = n*HDs + e;
    const float gnw = gn[gb];
    const float* gx0 = g_big + (size_t)(b*Ss)*512 + gb;
    float c=0.0f, nn=0.0f, m=0.0f;
    float r0 = gx0[0], r1 = gx0[Dd], r2 = gx0[2*Dd], r3 = gx0[3*Dd];
    for(int s=0;s<Ss;s++){
        // prefetch next step's gate pre-activations (independent of h)
        float n0=0.f, n1=0.f, n2=0.f, n3=0.f;
        if (s+1 < Ss){
            const float* np = gx0 + (size_t)(s+1)*512;
            n0 = np[0]; n1 = np[Dd]; n2 = np[2*Dd]; n3 = np[3*Dd];
        }
        #pragma unroll
        for(int dq=0; dq<8; dq++){
            float4 hv = *(const float4*)&hs[w][dq*4];
            float4 w0 = *(const float4*)&rw[0][e][dq*4];
            float4 w1 = *(const float4*)&rw[1][e][dq*4];
            float4 w2 = *(const float4*)&rw[2][e][dq*4];
            float4 w3 = *(const float4*)&rw[3][e][dq*4];
            r0 += hv.x*w0.x + hv.y*w0.y + hv.z*w0.z + hv.w*w0.w;
            r1 += hv.x*w1.x + hv.y*w1.y + hv.z*w1.z + hv.w*w1.w;
            r2 += hv.x*w2.x + hv.y*w2.y + hv.z*w2.z + hv.w*w2.w;
            r3 += hv.x*w3.x + hv.y*w3.y + hv.z*w3.z + hv.w*w3.w;
        }
        float lfm = m + logsigf(r1);
        float mn  = fmaxf(r0, lfm);
        float i   = expf(r0-mn);
        float f   = expf(lfm-mn);
        c  = f*c + i*tanhf(r2);
        nn = f*nn + i;
        float hnew = sigf(r3) * c / nn;
        m = mn;
        // fused group norm (group = this warp's 32 lanes) + residual
        float s1 = hnew, s2 = hnew*hnew;
        #pragma unroll
        for(int o=16;o;o>>=1){ s1 += __shfl_xor_sync(~0u,s1,o); s2 += __shfl_xor_sync(~0u,s2,o); }
        float mu = s1*(1.0f/HDs), var = s2*(1.0f/HDs)-mu*mu;
        float rr = rsqrtf(var + 1e-5f);
        g_h[((size_t)(b*Ss+s))*Dd + gb] += (hnew-mu)*rr*gnw;
        __syncwarp();
        hs[w][e] = hnew;
        __syncwarp();
        r0 = n0; r1 = n1; r2 = n2; r3 = n3;
    }
}

// ---------------- fused conv+silu+qkv+gates: 8 tokens per block --------------
__global__ void __launch_bounds__(256) k_cq(
        const float* __restrict__ cw, const float* __restrict__ cb,
        const float* __restrict__ qkvw, const float* __restrict__ gweff,
        const float* __restrict__ igb, const float* __restrict__ fgb){
    __shared__ float xms[11][256];
    __shared__ float xcv[8][256];
    __shared__ float4 Aig[256], Big[256], Afg[256], Bfg[256];
    int blk = blockIdx.x, b = blk>>3, sg = blk&7;
    int tid = threadIdx.x;
    int t0 = b*Ss + sg*8;

    Aig[tid] = *(const float4*)&gweff[0*1024 + tid*4];
    Big[tid] = *(const float4*)&gweff[1*1024 + tid*4];
    Afg[tid] = *(const float4*)&gweff[2*1024 + tid*4];
    Bfg[tid] = *(const float4*)&gweff[3*1024 + tid*4];

    for (int idx = tid; idx < 11*256; idx += 256){
        int r = idx >> 8, c = idx & 255;
        int s = sg*8 + r - 3;
        xms[r][c] = (s >= 0) ? g_big[(size_t)(b*Ss+s)*512 + c] : 0.0f;
    }
    int c = tid, n = c>>2, o = c&3;
    float cwv0=cw[c*4], cwv1=cw[c*4+1], cwv2=cw[c*4+2], cwv3=cw[c*4+3], cbv=cb[c];
    float wq[4], wk[4], wv[4];
    #pragma unroll
    for (int i2 = 0; i2 < 4; i2++){
        wq[i2] = qkvw[       n*16 + o*4 + i2];
        wk[i2] = qkvw[1024 + n*16 + o*4 + i2];
        wv[i2] = qkvw[2048 + n*16 + o*4 + i2];
    }
    __syncthreads();
    #pragma unroll
    for (int s = 0; s < 8; s++){
        float acc = cbv + xms[s][c]*cwv0 + xms[s+1][c]*cwv1 + xms[s+2][c]*cwv2 + xms[s+3][c]*cwv3;
        float xc = acc*sigf(acc);
        xcv[s][c] = xc;
        g_xconv[(size_t)(t0+s)*256 + c] = xc;
    }
    __syncthreads();
    #pragma unroll
    for (int s = 0; s < 8; s++){
        float q=0, k=0, v=0;
        #pragma unroll
        for (int i2 = 0; i2 < 4; i2++){
            float xc = xcv[s][n*4+i2];
            float xm = xms[s+3][n*4+i2];
            q += xc*wq[i2]; k += xc*wk[i2]; v += xm*wv[i2];
        }
        g_q[(size_t)(t0+s)*256 + c] = q;
        g_k[(size_t)(t0+s)*256 + c] = k;
        g_v[(size_t)(t0+s)*256 + c] = v;
    }
    // gates via folded weights: warp w -> token sg*8+w
    int w = tid >> 5, lane = tid & 31;
    float4 ia = make_float4(0,0,0,0), fa = make_float4(0,0,0,0);
    for (int j = lane; j < 256; j += 32){
        float xc = xcv[w][j], xm = xms[w+3][j];
        float4 A = Aig[j], B = Big[j], A2 = Afg[j], B2 = Bfg[j];
        ia.x += xc*A.x + xm*B.x;  ia.y += xc*A.y + xm*B.y;
        ia.z += xc*A.z + xm*B.z;  ia.w += xc*A.w + xm*B.w;
        fa.x += xc*A2.x + xm*B2.x; fa.y += xc*A2.y + xm*B2.y;
        fa.z += xc*A2.z + xm*B2.z; fa.w += xc*A2.w + xm*B2.w;
    }
    #pragma unroll
    for (int o2=16;o2;o2>>=1){
        ia.x += __shfl_xor_sync(~0u,ia.x,o2); ia.y += __shfl_xor_sync(~0u,ia.y,o2);
        ia.z += __shfl_xor_sync(~0u,ia.z,o2); ia.w += __shfl_xor_sync(~0u,ia.w,o2);
        fa.x += __shfl_xor_sync(~0u,fa.x,o2); fa.y += __shfl_xor_sync(~0u,fa.y,o2);
        fa.z += __shfl_xor_sync(~0u,fa.z,o2); fa.w += __shfl_xor_sync(~0u,fa.w,o2);
    }
    if (lane == 0){
        int s_ = sg*8 + w;
        g_ig[(size_t)(b*NHMc+0)*Ss + s_] = ia.x + igb[0];
        g_ig[(size_t)(b*NHMc+1)*Ss + s_] = ia.y + igb[1];
        g_ig[(size_t)(b*NHMc+2)*Ss + s_] = ia.z + igb[2];
        g_ig[(size_t)(b*NHMc+3)*Ss + s_] = ia.w + igb[3];
        g_fg[(size_t)(b*NHMc+0)*Ss + s_] = fa.x + fgb[0];
        g_fg[(size_t)(b*NHMc+1)*Ss + s_] = fa.y + fgb[1];
        g_fg[(size_t)(b*NHMc+2)*Ss + s_] = fa.z + fgb[2];
        g_fg[(size_t)(b*NHMc+3)*Ss + s_] = fa.w + fgb[3];
    }
}

// ---------------- mLSTM attention + fused groupnorm/skip/silu combine --------
__global__ void __launch_bounds__(256) k_attn(const float* __restrict__ onw,
                                              const float* __restrict__ skip){
    int blk = blockIdx.x; int b = blk >> 2, hm = blk & 3;
    __shared__ float qs[Ss][DHMc+1], ks[Ss][DHMc+1], vs[Ss][DHMc+1];
    __shared__ float cldf[Ss+1], igs[Ss];
    __shared__ float cn[8][Ss];
    int tid = threadIdx.x;
    for(int l=tid; l<Ss*DHMc; l+=256){
        int j = l >> 6, d = l & 63;
        size_t base = ((size_t)(b*Ss+j))*INNERc + hm*DHMc + d;
        qs[j][d] = g_q[base];
        ks[j][d] = g_k[base];
        vs[j][d] = g_v[base];
    }
    if (tid < Ss){
        igs[tid] = g_ig[(size_t)(b*NHMc+hm)*Ss + tid];
        cldf[tid+1] = logsigf(g_fg[(size_t)(b*NHMc+hm)*Ss + tid]);
    }
    if (tid == 0) cldf[0] = 0.0f;
    __syncthreads();
    // parallel inclusive scan over cldf[1..64]
    for (int off = 1; off < Ss; off <<= 1){
        float add = 0.0f;
        if (tid < Ss && tid >= off) add = cldf[tid+1-off];
        __syncthreads();
        if (tid < Ss && tid >= off) cldf[tid+1] += add;
        __syncthreads();
    }
    int w = tid >> 5, lane = tid & 31;
    int cg0 = hm*DHMc + lane, cg1 = cg0 + 32;
    float onw0 = onw[cg0], onw1 = onw[cg1];
    float sk0 = skip[cg0], sk1 = skip[cg1];
    for(int r=0;r<8;r++){
        int i = w*8 + r;
        int j1 = lane + 32;
        float dot0=0, dot1=0, ld0=-1e30f, ld1=-1e30f;
        if (lane <= i){
            #pragma unroll
            for(int d=0; d<DHMc; d++) dot0 += qs[i][d]*ks[lane][d];
            ld0 = cldf[i+1]-cldf[lane+1] + igs[lane];
        }
        if (j1 <= i){
            #pragma unroll
            for(int d=0; d<DHMc; d++) dot1 += qs[i][d]*ks[j1][d];
            ld1 = cldf[i+1]-cldf[j1+1] + igs[j1];
        }
        float mx = fmaxf(ld0, ld1);
        #pragma unroll
        for(int o=16;o;o>>=1) mx = fmaxf(mx, __shfl_xor_sync(~0u,mx,o));
        float cm0 = (lane <= i) ? dot0*0.125f*expf(ld0-mx) : 0.0f;
        float cm1 = (j1   <= i) ? dot1*0.125f*expf(ld1-mx) : 0.0f;
        float sm = cm0 + cm1;
        #pragma unroll
        for(int o=16;o;o>>=1) sm += __shfl_xor_sync(~0u,sm,o);
        float norm = fmaxf(fabsf(sm), expf(-mx)) + 1e-6f;
        cn[w][lane] = cm0/norm;
        cn[w][j1]   = cm1/norm;
        __syncwarp();
        float a0=0, a1=0;
        for(int j=0;j<=i;j++){
            float cc = cn[w][j];
            a0 += cc*vs[j][lane];
            a1 += cc*vs[j][lane+32];
        }
        // fused multi-head LN (64 dims = warp's a0,a1) + skip/silu combine
        float s1 = a0+a1, s2 = a0*a0+a1*a1;
        #pragma unroll
        for(int o=16;o;o>>=1){ s1 += __shfl_xor_sync(~0u,s1,o); s2 += __shfl_xor_sync(~0u,s2,o); }
        float mu = s1*(1.0f/DHMc), var = s2*(1.0f/DHMc)-mu*mu;
        float rr = rsqrtf(var + 1e-5f);
        size_t t = (size_t)(b*Ss+i);
        float z0 = g_big[t*512 + 256 + cg0], z1 = g_big[t*512 + 256 + cg1];
        float x0 = g_xconv[t*256 + cg0],     x1 = g_xconv[t*256 + cg1];
        g_q[t*256 + cg0] = ((a0-mu)*rr*onw0 + sk0*x0) * z0*sigf(z0);
        g_q[t*256 + cg1] = ((a1-mu)*rr*onw1 + sk1*x1) * z1*sigf(z1);
        __syncwarp();
    }
}

// ---------------- host-side --------------------------------------------------
static float* symf(const void* s){ void* p=nullptr; cudaGetSymbolAddress(&p, s); return (float*)p; }

extern "C" void kernel_launch(void* const* d_in, const int* in_sizes, int n_in,
                              void* d_out, int out_size){
    const int*   x         = (const int*)  d_in[0];
    const float* embed     = (const float*)d_in[1];
    const float* s_ln1     = (const float*)d_in[2];
    const float* s_gates_w = (const float*)d_in[3];
    const float* s_rec     = (const float*)d_in[4];
    const float* s_bias    = (const float*)d_in[5];
    const float* s_gn      = (const float*)d_in[6];
    const float* s_ln2     = (const float*)d_in[7];
    const float* s_ff_up   = (const float*)d_in[8];
    const float* s_ff_down = (const float*)d_in[9];
    const float* m_ln1     = (const float*)d_in[10];
    const float* m_up      = (const float*)d_in[11];
    const float* m_conv_w  = (const float*)d_in[12];
    const float* m_conv_b  = (const float*)d_in[13];
    const float* m_qkv_w   = (const float*)d_in[14];
    const float* m_ig_w    = (const float*)d_in[15];
    const float* m_ig_b    = (const float*)d_in[16];
    const float* m_fg_w    = (const float*)d_in[17];
    const float* m_fg_b    = (const float*)d_in[18];
    const float* m_skip    = (const float*)d_in[19];
    const float* m_onorm   = (const float*)d_in[20];
    const float* m_down    = (const float*)d_in[21];
    const float* m_ln2     = (const float*)d_in[22];
    const float* m_ff_up   = (const float*)d_in[23];
    const float* m_ff_down = (const float*)d_in[24];
    const float* post_ln   = (const float*)d_in[25];
    const float* head_w    = (const float*)d_in[26];
    const float* head_b    = (const float*)d_in[27];

    float* h    = symf(g_h);
    float* big  = symf(g_big);
    float* ffn  = symf(g_ffn);
    float* qb   = symf(g_q);
    float* gweff= symf(g_gw_eff);

    float* out = (float*)d_out;

    cudaFuncSetAttribute(k_mgemm<false,true ,true ,false>, cudaFuncAttributeMaxDynamicSharedMemorySize, MG_SMEM);
    cudaFuncSetAttribute(k_mgemm<false,false,true ,false>, cudaFuncAttributeMaxDynamicSharedMemorySize, MG_SMEM);
    cudaFuncSetAttribute(k_mgemm<true ,false,false,true >, cudaFuncAttributeMaxDynamicSharedMemorySize, MG_SMEM);
    cudaFuncSetAttribute(k_mgemm<true ,false,false,false>, cudaFuncAttributeMaxDynamicSharedMemorySize, MG_SMEM);

    // one-shot weight prep + embedding
    k_prep<<<546,256>>>(
        s_gates_w, s_gates_w + (size_t)4*NHs*HDs*HDs,
        s_ff_up, s_ff_down, m_up, m_down, m_ff_up, m_ff_down,
        s_ff_up + (size_t)Dd*2*FFc, s_ff_down + (size_t)FFc*Dd,
        m_up + (size_t)Dd*2*INNERc, m_down + (size_t)INNERc*Dd,
        m_ff_up + (size_t)Dd*2*FFc, m_ff_down + (size_t)FFc*Dd,
        head_w, m_qkv_w, m_ig_w, m_fg_w);
    k_embed<<<Tt, Dd>>>(x, embed);

    for(int i=0;i<2;i++){
        // ---- sLSTM ----
        k_mgemm<false,true,true,false><<<dim3(8, Tt/128),256,MG_SMEM>>>(
            h, big, s_bias + i*4*Dd, s_ln1 + i*Dd, W_SGX(i), 4*Dd, Dd);
        k_scan<<<NHs*(Bb/8),256>>>(s_rec + (size_t)i*4*NHs*HDs*HDs, s_gn + i*Dd);

        // ---- FFN 1 ----
        k_mgemm<false,false,true,false><<<dim3(4, Tt/128),256,MG_SMEM>>>(
            h, ffn, nullptr, s_ln2 + i*Dd, W_SFU(i), 2*FFc, Dd);
        k_mgemm<true,false,false,true><<<dim3(2, Tt/128),256,MG_SMEM>>>(
            ffn, h, nullptr, nullptr, W_SFD(i), Dd, FFc);

        // ---- mLSTM ----
        k_mgemm<false,false,true,false><<<dim3(8, Tt/128),256,MG_SMEM>>>(
            h, big, nullptr, m_ln1 + i*Dd, W_MUP(i), 2*INNERc, Dd);
        k_cq<<<Bb*8,256>>>(m_conv_w + (size_t)i*INNERc*Kc, m_conv_b + i*INNERc,
                           m_qkv_w + (size_t)i*3072, gweff + i*4096,
                           m_ig_b + i*NHMc, m_fg_b + i*NHMc);
        k_attn<<<Bb*NHMc,256>>>(m_onorm + i*INNERc, m_skip + i*INNERc);
        k_mgemm<true,false,false,false><<<dim3(2, Tt/128),256,MG_SMEM>>>(
            qb, h, nullptr, nullptr, W_MDN(i), Dd, INNERc);

        // ---- FFN 2 ----
        k_mgemm<false,false,true,false><<<dim3(4, Tt/128),256,MG_SMEM>>>(
            h, ffn, nullptr, m_ln2 + i*Dd, W_MFU(i), 2*FFc, Dd);
        k_mgemm<true,false,false,true><<<dim3(2, Tt/128),256,MG_SMEM>>>(
            ffn, h, nullptr, nullptr, W_MFD(i), Dd, FFc);
    }

    // ---- final LN + head ----
    k_mgemm<false,true,true,false><<<dim3(4, Tt/128),256,MG_SMEM>>>(
        h, out, head_b, post_ln, W_HEAD, Vv, Dd);
}

// round 10
// speedup vs baseline: 5.8709x; 1.0975x over previous
#include <cuda_runtime.h>
#include <cuda_bf16.h>
#include <math.h>
#include <stdint.h>

#define Bb     512
#define Ss     64
#define Dd     128
#define Vv     256
#define NHs    4
#define HDs    32
#define INNERc 256
#define NHMc   4
#define DHMc   64
#define NBc    64
#define Kc     4
#define FFc    128
#define Tt     (Bb*Ss)   /* 32768 tokens */

// ---------------- workspaces (static device globals; no allocation) ----------
__device__ float g_h[Tt*Dd];            // residual stream
__device__ float g_big[Tt*2*INNERc];    // slstm gx [t][512]  OR  mlstm up out [t][512]
__device__ float g_ffn[Tt*2*FFc];       // ffn up output
__device__ float g_xconv[Tt*INNERc];
__device__ float g_q[Tt*INNERc];        // q, later reused as mlstm combine buffer
__device__ float g_k[Tt*INNERc];
__device__ float g_v[Tt*INNERc];
__device__ float g_ig[Bb*NHMc*Ss];
__device__ float g_fg[Bb*NHMc*Ss];

// all GEMM weights, transposed+split [N][K]
#define W_SGX(i)  ((i)*262144 + 0)
#define W_SFU(i)  ((i)*262144 + 65536)
#define W_SFD(i)  ((i)*262144 + 98304)
#define W_MUP(i)  ((i)*262144 + 114688)
#define W_MDN(i)  ((i)*262144 + 180224)
#define W_MFU(i)  ((i)*262144 + 212992)
#define W_MFD(i)  ((i)*262144 + 245760)
#define W_HEAD    (524288)
#define W_TOTAL   (557056)
__device__ __nv_bfloat16 g_wt_hi[W_TOTAL];
__device__ __nv_bfloat16 g_wt_lo[W_TOTAL];
__device__ float g_gw_eff[2*4096];      // folded gate weights [L][4][256][4]

// ---------------- device math helpers ---------------------------------------
__device__ __forceinline__ float sigf(float x){ return 1.0f/(1.0f+expf(-x)); }
__device__ __forceinline__ float logsigf(float x){ return fminf(x,0.0f) - log1pf(expf(-fabsf(x))); }
__device__ __forceinline__ float geluf(float x){
    float x3 = x*x*x;
    return 0.5f*x*(1.0f+tanhf(0.7978845608028654f*(x+0.044715f*x3)));
}
__device__ __forceinline__ uint32_t smem_u32(const void* p){
    uint32_t a;
    asm("{ .reg .u64 t; cvta.to.shared.u64 t, %1; cvt.u32.u64 %0, t; }" : "=r"(a) : "l"(p));
    return a;
}
__device__ __forceinline__ void split2(float a, float b, uint32_t &hi, uint32_t &lo){
    __nv_bfloat162 h = __floats2bfloat162_rn(a, b);
    float ra = a - __bfloat162float(h.x);
    float rb = b - __bfloat162float(h.y);
    __nv_bfloat162 l = __floats2bfloat162_rn(ra, rb);
    hi = *(uint32_t*)&h; lo = *(uint32_t*)&l;
}

#define LDM4(r0,r1,r2,r3,addr) \
    asm volatile("ldmatrix.sync.aligned.m8n8.x4.shared.b16 {%0,%1,%2,%3}, [%4];" \
        : "=r"(r0),"=r"(r1),"=r"(r2),"=r"(r3) : "r"(addr))

#define MMA16816(d,a,b) \
    asm volatile("mma.sync.aligned.m16n8k16.row.col.f32.bf16.bf16.f32 " \
        "{%0,%1,%2,%3}, {%4,%5,%6,%7}, {%8,%9}, {%0,%1,%2,%3};" \
        : "+f"((d)[0]),"+f"((d)[1]),"+f"((d)[2]),"+f"((d)[3]) \
        : "r"((a)[0]),"r"((a)[1]),"r"((a)[2]),"r"((a)[3]), "r"((b)[0]),"r"((b)[1]))

// smem layout: A tiles 128x136 bf16 (hi/lo), B tiles 64x136 bf16 (hi/lo)
#define MG_STRIDE 136
#define MG_AH 0
#define MG_AL (128*MG_STRIDE*2)
#define MG_BH (2*128*MG_STRIDE*2)
#define MG_BL (MG_BH + 64*MG_STRIDE*2)
#define MG_SMEM (MG_BL + 64*MG_STRIDE*2)   /* 104448 B */

// ---------------- tensor-core GEMM: C[M,N] (+)= f(A)[M,K] @ Wt^T (+bias) -----
// NB>1 requires K==128: A is staged ONCE, then NB 64-wide B sub-tiles are
// processed in a loop reusing the staged A. NB==1 keeps the multi-k-chunk path.
template<bool ADD, bool BIAS, bool LN, bool GLU, int NB>
__global__ void __launch_bounds__(256,2) k_mgemm(
        const float* __restrict__ A, float* __restrict__ C,
        const float* __restrict__ bias, const float* __restrict__ lnw,
        int woff, int N, int K){
    extern __shared__ char smem[];
    const int tid = threadIdx.x, w = tid>>5, lane = tid&31;
    const int bm = blockIdx.y*128;
    const int wm = w & 3, wn = w >> 2;
    const int gID = lane >> 2, qid = lane & 3;

    const int a_row = lane & 15;
    const int a_koff = (lane >> 4) * 8;
    const int b_noff = (lane & 7) + ((lane >> 4) & 1) * 8;
    const int b_koff = ((lane >> 3) & 1) * 8;

    const uint32_t sb = smem_u32(smem);

    // ---- A staging for k-chunk kc ----
    auto stageA = [&](int kc){
        #pragma unroll
        for (int it = 0; it < 8; it++){
            int g4 = tid + it*256;
            int row = g4 >> 4, kg = g4 & 15;
            float4 v0, v1;
            if (GLU){
                const float* ap = A + (size_t)(bm+row)*256 + kg*8;
                float4 gg0 = *(const float4*)ap,      gg1 = *(const float4*)(ap+4);
                float4 uu0 = *(const float4*)(ap+128), uu1 = *(const float4*)(ap+132);
                v0.x = geluf(gg0.x)*uu0.x; v0.y = geluf(gg0.y)*uu0.y;
                v0.z = geluf(gg0.z)*uu0.z; v0.w = geluf(gg0.w)*uu0.w;
                v1.x = geluf(gg1.x)*uu1.x; v1.y = geluf(gg1.y)*uu1.y;
                v1.z = geluf(gg1.z)*uu1.z; v1.w = geluf(gg1.w)*uu1.w;
            } else {
                const float4* ap = (const float4*)(A + (size_t)(bm+row)*K + kc*128 + kg*8);
                v0 = ap[0]; v1 = ap[1];
            }
            if (LN){
                float s  = v0.x+v0.y+v0.z+v0.w + v1.x+v1.y+v1.z+v1.w;
                float ss = v0.x*v0.x+v0.y*v0.y+v0.z*v0.z+v0.w*v0.w
                         + v1.x*v1.x+v1.y*v1.y+v1.z*v1.z+v1.w*v1.w;
                #pragma unroll
                for (int o = 1; o < 16; o <<= 1){
                    s  += __shfl_xor_sync(~0u, s,  o);
                    ss += __shfl_xor_sync(~0u, ss, o);
                }
                float mu  = s*(1.0f/128.0f);
                float var = ss*(1.0f/128.0f) - mu*mu;
                float rr  = rsqrtf(var + 1e-5f);
                float4 w0 = *(const float4*)&lnw[kg*8];
                float4 w1 = *(const float4*)&lnw[kg*8+4];
                v0.x = (v0.x-mu)*rr*w0.x; v0.y = (v0.y-mu)*rr*w0.y;
                v0.z = (v0.z-mu)*rr*w0.z; v0.w = (v0.w-mu)*rr*w0.w;
                v1.x = (v1.x-mu)*rr*w1.x; v1.y = (v1.y-mu)*rr*w1.y;
                v1.z = (v1.z-mu)*rr*w1.z; v1.w = (v1.w-mu)*rr*w1.w;
            }
            uint32_t h0,h1,h2,h3, l0,l1,l2,l3;
            split2(v0.x, v0.y, h0, l0);
            split2(v0.z, v0.w, h1, l1);
            split2(v1.x, v1.y, h2, l2);
            split2(v1.z, v1.w, h3, l3);
            uint32_t off = (uint32_t)(row*(MG_STRIDE*2) + kg*16);
            *(uint4*)(smem + MG_AH + off) = make_uint4(h0,h1,h2,h3);
            *(uint4*)(smem + MG_AL + off) = make_uint4(l0,l1,l2,l3);
        }
    };
    auto stageB = [&](int bn, int kc){
        #pragma unroll
        for (int it = 0; it < 4; it++){
            int g4 = tid + it*256;
            int n = g4 >> 4, kg = g4 & 15;
            size_t gi = (size_t)woff + (size_t)(bn+n)*K + kc*128 + kg*8;
            uint4 hv = *(const uint4*)(g_wt_hi + gi);
            uint4 lv = *(const uint4*)(g_wt_lo + gi);
            uint32_t off = (uint32_t)(n*(MG_STRIDE*2) + kg*16);
            *(uint4*)(smem + MG_BH + off) = hv;
            *(uint4*)(smem + MG_BL + off) = lv;
        }
    };
    auto compute = [&](float (&acc)[2][4][4]){
        #pragma unroll
        for (int ks = 0; ks < 8; ks++){
            uint32_t ah[2][4], al[2][4];
            #pragma unroll
            for (int mt = 0; mt < 2; mt++){
                uint32_t aoff = (uint32_t)((wm*32 + mt*16 + a_row)*(MG_STRIDE*2)
                                           + (ks*16 + a_koff)*2);
                LDM4(ah[mt][0],ah[mt][1],ah[mt][2],ah[mt][3], sb + MG_AH + aoff);
                LDM4(al[mt][0],al[mt][1],al[mt][2],al[mt][3], sb + MG_AL + aoff);
            }
            uint32_t bh[4][2], bl[4][2];
            #pragma unroll
            for (int ng = 0; ng < 2; ng++){
                uint32_t boff = (uint32_t)((wn*32 + ng*16 + b_noff)*(MG_STRIDE*2)
                                           + (ks*16 + b_koff)*2);
                uint32_t r0,r1,r2,r3;
                LDM4(r0,r1,r2,r3, sb + MG_BH + boff);
                bh[ng*2][0]=r0; bh[ng*2][1]=r1; bh[ng*2+1][0]=r2; bh[ng*2+1][1]=r3;
                LDM4(r0,r1,r2,r3, sb + MG_BL + boff);
                bl[ng*2][0]=r0; bl[ng*2][1]=r1; bl[ng*2+1][0]=r2; bl[ng*2+1][1]=r3;
            }
            #pragma unroll
            for (int mt = 0; mt < 2; mt++)
                #pragma unroll
                for (int nt = 0; nt < 4; nt++){
                    MMA16816(acc[mt][nt], ah[mt], bh[nt]);
                    MMA16816(acc[mt][nt], ah[mt], bl[nt]);
                    MMA16816(acc[mt][nt], al[mt], bh[nt]);
                }
        }
    };
    auto epilogue = [&](float (&acc)[2][4][4], int bn){
        #pragma unroll
        for (int mt = 0; mt < 2; mt++){
            #pragma unroll
            for (int nt = 0; nt < 4; nt++){
                int row0 = bm + wm*32 + mt*16 + gID;
                int col  = bn + wn*32 + nt*8 + qid*2;
                float2 v0 = make_float2(acc[mt][nt][0], acc[mt][nt][1]);
                float2 v1 = make_float2(acc[mt][nt][2], acc[mt][nt][3]);
                if (BIAS){
                    float2 bv = *(const float2*)&bias[col];
                    v0.x += bv.x; v0.y += bv.y;
                    v1.x += bv.x; v1.y += bv.y;
                }
                float* p0 = C + (size_t)row0*N + col;
                float* p1 = C + (size_t)(row0+8)*N + col;
                if (ADD){
                    float2 o0 = *(const float2*)p0, o1 = *(const float2*)p1;
                    v0.x += o0.x; v0.y += o0.y;
                    v1.x += o1.x; v1.y += o1.y;
                }
                *(float2*)p0 = v0;
                *(float2*)p1 = v1;
            }
        }
    };

    if constexpr (NB == 1){
        const int bn = blockIdx.x*64;
        float acc[2][4][4] = {};
        const int nchunk = K >> 7;
        for (int kc = 0; kc < nchunk; kc++){
            stageA(kc);
            stageB(bn, kc);
            __syncthreads();
            compute(acc);
            __syncthreads();
        }
        epilogue(acc, bn);
    } else {
        const int bn0 = blockIdx.x*64*NB;
        stageA(0);
        #pragma unroll
        for (int sub = 0; sub < NB; sub++){
            stageB(bn0 + sub*64, 0);
            __syncthreads();
            float acc[2][4][4] = {};
            compute(acc);
            epilogue(acc, bn0 + sub*64);
            __syncthreads();
        }
    }
}

// ---------------- one-shot weight prep: transposes + densify + gate folding --
__global__ void __launch_bounds__(256) k_prep(
    const float* sgw0, const float* sgw1,
    const float* sfu0, const float* sfd0, const float* mup0, const float* mdn0,
    const float* mfu0, const float* mfd0,
    const float* sfu1, const float* sfd1, const float* mup1, const float* mdn1,
    const float* mfu1, const float* mfd1,
    const float* headw,
    const float* qkvw, const float* igw, const float* fgw){
    int bx = blockIdx.x, tid = threadIdx.x;
    if (bx < 416){
        const int cum[13]  = {32,48,112,144,176,192,224,240,304,336,368,384,416};
        const float* srcs[13] = {sfu0,sfd0,mup0,mdn0,mfu0,mfd0,sfu1,sfd1,mup1,mdn1,mfu1,mfd1,headw};
        const int Ks[13]   = {128,128,128,256,128,128,128,128,128,256,128,128,128};
        const int Ns[13]   = {256,128,512,128,256,128,256,128,512,128,256,128,256};
        const int dsts[13] = {W_SFU(0),W_SFD(0),W_MUP(0),W_MDN(0),W_MFU(0),W_MFD(0),
                              W_SFU(1),W_SFD(1),W_MUP(1),W_MDN(1),W_MFU(1),W_MFD(1),W_HEAD};
        int j = 0;
        while (bx >= cum[j]) j++;
        int tile = bx - (j ? cum[j-1] : 0);
        const float* src = srcs[j];
        int K = Ks[j], N = Ns[j], dst = dsts[j];
        int tilesN = N >> 5;
        int bk = (tile / tilesN)*32, bn = (tile % tilesN)*32;
        __shared__ float t[32][33];
        int tx = tid & 31, ty = tid >> 5;
        #pragma unroll
        for (int r = 0; r < 32; r += 8)
            t[ty+r][tx] = src[(size_t)(bk+ty+r)*N + bn+tx];
        __syncthreads();
        #pragma unroll
        for (int r = 0; r < 32; r += 8){
            float v = t[tx][ty+r];
            __nv_bfloat16 h = __float2bfloat16(v);
            size_t o = (size_t)dst + (size_t)(bn+ty+r)*K + bk+tx;
            g_wt_hi[o] = h;
            g_wt_lo[o] = __float2bfloat16(v - __bfloat162float(h));
        }
    } else if (bx < 544){
        int bx2 = bx - 416;
        int L = bx2 >> 6, blk = bx2 & 63;
        const float* gw = L ? sgw1 : sgw0;
        #pragma unroll
        for (int u = 0; u < 4; u++){
            int idx = blk*1024 + u*256 + tid;     // over 128*512
            int d = idx >> 9;
            int o = idx & 511;
            int g = o >> 7;
            int ne = o & 127;
            int n = ne >> 5, e = ne & 31;
            float wv = 0.0f;
            if ((d >> 5) == n) wv = gw[(((g*NHs + n)*HDs + e)*HDs) + (d & 31)];
            __nv_bfloat16 h = __float2bfloat16(wv);
            size_t oo = (size_t)W_SGX(L) + (size_t)o*Dd + d;
            g_wt_hi[oo] = h;
            g_wt_lo[oo] = __float2bfloat16(wv - __bfloat162float(h));
        }
    } else {
        int L = bx - 544;
        const float* qw  = qkvw + L*3072;
        const float* igp = igw  + L*3072;
        const float* fgp = fgw  + L*3072;
        int c = tid, n = c >> 2, i = c & 3;
        float aig[4]={0,0,0,0}, big_[4]={0,0,0,0}, afg[4]={0,0,0,0}, bfg_[4]={0,0,0,0};
        #pragma unroll
        for (int o = 0; o < 4; o++){
            float w0 = qw[n*16+o*4+i];
            float w1 = qw[1024+n*16+o*4+i];
            float w2 = qw[2048+n*16+o*4+i];
            int j0 = (n*4+o)*4, j1 = (256+n*4+o)*4, j2 = (512+n*4+o)*4;
            #pragma unroll
            for (int hm = 0; hm < 4; hm++){
                aig[hm]  += w0*igp[j0+hm] + w1*igp[j1+hm];
                big_[hm] += w2*igp[j2+hm];
                afg[hm]  += w0*fgp[j0+hm] + w1*fgp[j1+hm];
                bfg_[hm] += w2*fgp[j2+hm];
            }
        }
        #pragma unroll
        for (int hm = 0; hm < 4; hm++){
            g_gw_eff[L*4096 + 0*1024 + c*4 + hm] = aig[hm];
            g_gw_eff[L*4096 + 1*1024 + c*4 + hm] = big_[hm];
            g_gw_eff[L*4096 + 2*1024 + c*4 + hm] = afg[hm];
            g_gw_eff[L*4096 + 3*1024 + c*4 + hm] = bfg_[hm];
        }
    }
}

// ---------------- embedding --------------------------------------------------
__global__ void k_embed(const int* __restrict__ x, const float* __restrict__ emb){
    int t = blockIdx.x;
    g_h[t*Dd + threadIdx.x] = emb[x[t]*Dd + threadIdx.x];
}

// ---------------- sLSTM scan + fused group-norm/residual, gx prefetched ------
__global__ void __launch_bounds__(256) k_scan(const float* __restrict__ rec,
                                              const float* __restrict__ gn){
    int n  = blockIdx.x & 3;
    int bg = blockIdx.x >> 2;
    int w  = threadIdx.x >> 5;
    int e  = threadIdx.x & 31;
    int b  = bg*8 + w;
    __shared__ float rw[4][HDs][36];
    __shared__ float hs[8][HDs];
    for (int idx = threadIdx.x; idx < 4*HDs*HDs; idx += 256){
        int g = idx >> 10, rem = idx & 1023;
        int e2 = rem >> 5, d = rem & 31;
        rw[g][e2][d] = rec[((size_t)(g*NHs+n)*HDs + e2)*HDs + d];
    }
    hs[w][e] = 0.0f;
    __syncthreads();
    const int gb = n*HDs + e;
    const float gnw = gn[gb];
    const float* gx0 = g_big + (size_t)(b*Ss)*512 + gb;
    float c=0.0f, nn=0.0f, m=0.0f;
    float r0 = gx0[0], r1 = gx0[Dd], r2 = gx0[2*Dd], r3 = gx0[3*Dd];
    for(int s=0;s<Ss;s++){
        float n0=0.f, n1=0.f, n2=0.f, n3=0.f;
        if (s+1 < Ss){
            const float* np = gx0 + (size_t)(s+1)*512;
            n0 = np[0]; n1 = np[Dd]; n2 = np[2*Dd]; n3 = np[3*Dd];
        }
        #pragma unroll
        for(int dq=0; dq<8; dq++){
            float4 hv = *(const float4*)&hs[w][dq*4];
            float4 w0 = *(const float4*)&rw[0][e][dq*4];
            float4 w1 = *(const float4*)&rw[1][e][dq*4];
            float4 w2 = *(const float4*)&rw[2][e][dq*4];
            float4 w3 = *(const float4*)&rw[3][e][dq*4];
            r0 += hv.x*w0.x + hv.y*w0.y + hv.z*w0.z + hv.w*w0.w;
            r1 += hv.x*w1.x + hv.y*w1.y + hv.z*w1.z + hv.w*w1.w;
            r2 += hv.x*w2.x + hv.y*w2.y + hv.z*w2.z + hv.w*w2.w;
            r3 += hv.x*w3.x + hv.y*w3.y + hv.z*w3.z + hv.w*w3.w;
        }
        float lfm = m + logsigf(r1);
        float mn  = fmaxf(r0, lfm);
        float i   = expf(r0-mn);
        float f   = expf(lfm-mn);
        c  = f*c + i*tanhf(r2);
        nn = f*nn + i;
        float hnew = sigf(r3) * c / nn;
        m = mn;
        float s1 = hnew, s2 = hnew*hnew;
        #pragma unroll
        for(int o=16;o;o>>=1){ s1 += __shfl_xor_sync(~0u,s1,o); s2 += __shfl_xor_sync(~0u,s2,o); }
        float mu = s1*(1.0f/HDs), var = s2*(1.0f/HDs)-mu*mu;
        float rr = rsqrtf(var + 1e-5f);
        g_h[((size_t)(b*Ss+s))*Dd + gb] += (hnew-mu)*rr*gnw;
        __syncwarp();
        hs[w][e] = hnew;
        __syncwarp();
        r0 = n0; r1 = n1; r2 = n2; r3 = n3;
    }
}

// ---------------- fused conv+silu+qkv+gates: 8 tokens per block --------------
__global__ void __launch_bounds__(256) k_cq(
        const float* __restrict__ cw, const float* __restrict__ cb,
        const float* __restrict__ qkvw, const float* __restrict__ gweff,
        const float* __restrict__ igb, const float* __restrict__ fgb){
    __shared__ float xms[11][256];
    __shared__ float xcv[8][256];
    __shared__ float4 Aig[256], Big[256], Afg[256], Bfg[256];
    int blk = blockIdx.x, b = blk>>3, sg = blk&7;
    int tid = threadIdx.x;
    int t0 = b*Ss + sg*8;

    Aig[tid] = *(const float4*)&gweff[0*1024 + tid*4];
    Big[tid] = *(const float4*)&gweff[1*1024 + tid*4];
    Afg[tid] = *(const float4*)&gweff[2*1024 + tid*4];
    Bfg[tid] = *(const float4*)&gweff[3*1024 + tid*4];

    for (int idx = tid; idx < 11*256; idx += 256){
        int r = idx >> 8, c = idx & 255;
        int s = sg*8 + r - 3;
        xms[r][c] = (s >= 0) ? g_big[(size_t)(b*Ss+s)*512 + c] : 0.0f;
    }
    int c = tid, n = c>>2, o = c&3;
    float cwv0=cw[c*4], cwv1=cw[c*4+1], cwv2=cw[c*4+2], cwv3=cw[c*4+3], cbv=cb[c];
    float wq[4], wk[4], wv[4];
    #pragma unroll
    for (int i2 = 0; i2 < 4; i2++){
        wq[i2] = qkvw[       n*16 + o*4 + i2];
        wk[i2] = qkvw[1024 + n*16 + o*4 + i2];
        wv[i2] = qkvw[2048 + n*16 + o*4 + i2];
    }
    __syncthreads();
    #pragma unroll
    for (int s = 0; s < 8; s++){
        float acc = cbv + xms[s][c]*cwv0 + xms[s+1][c]*cwv1 + xms[s+2][c]*cwv2 + xms[s+3][c]*cwv3;
        float xc = acc*sigf(acc);
        xcv[s][c] = xc;
        g_xconv[(size_t)(t0+s)*256 + c] = xc;
    }
    __syncthreads();
    #pragma unroll
    for (int s = 0; s < 8; s++){
        float q=0, k=0, v=0;
        #pragma unroll
        for (int i2 = 0; i2 < 4; i2++){
            float xc = xcv[s][n*4+i2];
            float xm = xms[s+3][n*4+i2];
            q += xc*wq[i2]; k += xc*wk[i2]; v += xm*wv[i2];
        }
        g_q[(size_t)(t0+s)*256 + c] = q;
        g_k[(size_t)(t0+s)*256 + c] = k;
        g_v[(size_t)(t0+s)*256 + c] = v;
    }
    int w = tid >> 5, lane = tid & 31;
    float4 ia = make_float4(0,0,0,0), fa = make_float4(0,0,0,0);
    for (int j = lane; j < 256; j += 32){
        float xc = xcv[w][j], xm = xms[w+3][j];
        float4 A = Aig[j], B = Big[j], A2 = Afg[j], B2 = Bfg[j];
        ia.x += xc*A.x + xm*B.x;  ia.y += xc*A.y + xm*B.y;
        ia.z += xc*A.z + xm*B.z;  ia.w += xc*A.w + xm*B.w;
        fa.x += xc*A2.x + xm*B2.x; fa.y += xc*A2.y + xm*B2.y;
        fa.z += xc*A2.z + xm*B2.z; fa.w += xc*A2.w + xm*B2.w;
    }
    #pragma unroll
    for (int o2=16;o2;o2>>=1){
        ia.x += __shfl_xor_sync(~0u,ia.x,o2); ia.y += __shfl_xor_sync(~0u,ia.y,o2);
        ia.z += __shfl_xor_sync(~0u,ia.z,o2); ia.w += __shfl_xor_sync(~0u,ia.w,o2);
        fa.x += __shfl_xor_sync(~0u,fa.x,o2); fa.y += __shfl_xor_sync(~0u,fa.y,o2);
        fa.z += __shfl_xor_sync(~0u,fa.z,o2); fa.w += __shfl_xor_sync(~0u,fa.w,o2);
    }
    if (lane == 0){
        int s_ = sg*8 + w;
        g_ig[(size_t)(b*NHMc+0)*Ss + s_] = ia.x + igb[0];
        g_ig[(size_t)(b*NHMc+1)*Ss + s_] = ia.y + igb[1];
        g_ig[(size_t)(b*NHMc+2)*Ss + s_] = ia.z + igb[2];
        g_ig[(size_t)(b*NHMc+3)*Ss + s_] = ia.w + igb[3];
        g_fg[(size_t)(b*NHMc+0)*Ss + s_] = fa.x + fgb[0];
        g_fg[(size_t)(b*NHMc+1)*Ss + s_] = fa.y + fgb[1];
        g_fg[(size_t)(b*NHMc+2)*Ss + s_] = fa.z + fgb[2];
        g_fg[(size_t)(b*NHMc+3)*Ss + s_] = fa.w + fgb[3];
    }
}

// ---------------- mLSTM attention + fused groupnorm/skip/silu combine --------
__global__ void __launch_bounds__(256) k_attn(const float* __restrict__ onw,
                                              const float* __restrict__ skip){
    int blk = blockIdx.x; int b = blk >> 2, hm = blk & 3;
    __shared__ float qs[Ss][DHMc+1], ks[Ss][DHMc+1], vs[Ss][DHMc+1];
    __shared__ float cldf[Ss+1], igs[Ss];
    __shared__ float cn[8][Ss];
    int tid = threadIdx.x;
    for(int l=tid; l<Ss*DHMc; l+=256){
        int j = l >> 6, d = l & 63;
        size_t base = ((size_t)(b*Ss+j))*INNERc + hm*DHMc + d;
        qs[j][d] = g_q[base];
        ks[j][d] = g_k[base];
        vs[j][d] = g_v[base];
    }
    if (tid < Ss){
        igs[tid] = g_ig[(size_t)(b*NHMc+hm)*Ss + tid];
        cldf[tid+1] = logsigf(g_fg[(size_t)(b*NHMc+hm)*Ss + tid]);
    }
    if (tid == 0) cldf[0] = 0.0f;
    __syncthreads();
    for (int off = 1; off < Ss; off <<= 1){
        float add = 0.0f;
        if (tid < Ss && tid >= off) add = cldf[tid+1-off];
        __syncthreads();
        if (tid < Ss && tid >= off) cldf[tid+1] += add;
        __syncthreads();
    }
    int w = tid >> 5, lane = tid & 31;
    int cg0 = hm*DHMc + lane, cg1 = cg0 + 32;
    float onw0 = onw[cg0], onw1 = onw[cg1];
    float sk0 = skip[cg0], sk1 = skip[cg1];
    for(int r=0;r<8;r++){
        int i = w*8 + r;
        int j1 = lane + 32;
        float dot0=0, dot1=0, ld0=-1e30f, ld1=-1e30f;
        if (lane <= i){
            #pragma unroll
            for(int d=0; d<DHMc; d++) dot0 += qs[i][d]*ks[lane][d];
            ld0 = cldf[i+1]-cldf[lane+1] + igs[lane];
        }
        if (j1 <= i){
            #pragma unroll
            for(int d=0; d<DHMc; d++) dot1 += qs[i][d]*ks[j1][d];
            ld1 = cldf[i+1]-cldf[j1+1] + igs[j1];
        }
        float mx = fmaxf(ld0, ld1);
        #pragma unroll
        for(int o=16;o;o>>=1) mx = fmaxf(mx, __shfl_xor_sync(~0u,mx,o));
        float cm0 = (lane <= i) ? dot0*0.125f*expf(ld0-mx) : 0.0f;
        float cm1 = (j1   <= i) ? dot1*0.125f*expf(ld1-mx) : 0.0f;
        float sm = cm0 + cm1;
        #pragma unroll
        for(int o=16;o;o>>=1) sm += __shfl_xor_sync(~0u,sm,o);
        float norm = fmaxf(fabsf(sm), expf(-mx)) + 1e-6f;
        cn[w][lane] = cm0/norm;
        cn[w][j1]   = cm1/norm;
        __syncwarp();
        float a0=0, a1=0;
        for(int j=0;j<=i;j++){
            float cc = cn[w][j];
            a0 += cc*vs[j][lane];
            a1 += cc*vs[j][lane+32];
        }
        float s1 = a0+a1, s2 = a0*a0+a1*a1;
        #pragma unroll
        for(int o=16;o;o>>=1){ s1 += __shfl_xor_sync(~0u,s1,o); s2 += __shfl_xor_sync(~0u,s2,o); }
        float mu = s1*(1.0f/DHMc), var = s2*(1.0f/DHMc)-mu*mu;
        float rr = rsqrtf(var + 1e-5f);
        size_t t = (size_t)(b*Ss+i);
        float z0 = g_big[t*512 + 256 + cg0], z1 = g_big[t*512 + 256 + cg1];
        float x0 = g_xconv[t*256 + cg0],     x1 = g_xconv[t*256 + cg1];
        g_q[t*256 + cg0] = ((a0-mu)*rr*onw0 + sk0*x0) * z0*sigf(z0);
        g_q[t*256 + cg1] = ((a1-mu)*rr*onw1 + sk1*x1) * z1*sigf(z1);
        __syncwarp();
    }
}

// ---------------- host-side --------------------------------------------------
static float* symf(const void* s){ void* p=nullptr; cudaGetSymbolAddress(&p, s); return (float*)p; }

extern "C" void kernel_launch(void* const* d_in, const int* in_sizes, int n_in,
                              void* d_out, int out_size){
    const int*   x         = (const int*)  d_in[0];
    const float* embed     = (const float*)d_in[1];
    const float* s_ln1     = (const float*)d_in[2];
    const float* s_gates_w = (const float*)d_in[3];
    const float* s_rec     = (const float*)d_in[4];
    const float* s_bias    = (const float*)d_in[5];
    const float* s_gn      = (const float*)d_in[6];
    const float* s_ln2     = (const float*)d_in[7];
    const float* s_ff_up   = (const float*)d_in[8];
    const float* s_ff_down = (const float*)d_in[9];
    const float* m_ln1     = (const float*)d_in[10];
    const float* m_up      = (const float*)d_in[11];
    const float* m_conv_w  = (const float*)d_in[12];
    const float* m_conv_b  = (const float*)d_in[13];
    const float* m_qkv_w   = (const float*)d_in[14];
    const float* m_ig_w    = (const float*)d_in[15];
    const float* m_ig_b    = (const float*)d_in[16];
    const float* m_fg_w    = (const float*)d_in[17];
    const float* m_fg_b    = (const float*)d_in[18];
    const float* m_skip    = (const float*)d_in[19];
    const float* m_onorm   = (const float*)d_in[20];
    const float* m_down    = (const float*)d_in[21];
    const float* m_ln2     = (const float*)d_in[22];
    const float* m_ff_up   = (const float*)d_in[23];
    const float* m_ff_down = (const float*)d_in[24];
    const float* post_ln   = (const float*)d_in[25];
    const float* head_w    = (const float*)d_in[26];
    const float* head_b    = (const float*)d_in[27];

    float* h    = symf(g_h);
    float* big  = symf(g_big);
    float* ffn  = symf(g_ffn);
    float* qb   = symf(g_q);
    float* gweff= symf(g_gw_eff);

    float* out = (float*)d_out;

    cudaFuncSetAttribute(k_mgemm<false,true ,true ,false,8>, cudaFuncAttributeMaxDynamicSharedMemorySize, MG_SMEM);
    cudaFuncSetAttribute(k_mgemm<false,false,true ,false,8>, cudaFuncAttributeMaxDynamicSharedMemorySize, MG_SMEM);
    cudaFuncSetAttribute(k_mgemm<false,false,true ,false,4>, cudaFuncAttributeMaxDynamicSharedMemorySize, MG_SMEM);
    cudaFuncSetAttribute(k_mgemm<true ,false,false,true ,2>, cudaFuncAttributeMaxDynamicSharedMemorySize, MG_SMEM);
    cudaFuncSetAttribute(k_mgemm<true ,false,false,false,1>, cudaFuncAttributeMaxDynamicSharedMemorySize, MG_SMEM);
    cudaFuncSetAttribute(k_mgemm<false,true ,true ,false,4>, cudaFuncAttributeMaxDynamicSharedMemorySize, MG_SMEM);

    k_prep<<<546,256>>>(
        s_gates_w, s_gates_w + (size_t)4*NHs*HDs*HDs,
        s_ff_up, s_ff_down, m_up, m_down, m_ff_up, m_ff_down,
        s_ff_up + (size_t)Dd*2*FFc, s_ff_down + (size_t)FFc*Dd,
        m_up + (size_t)Dd*2*INNERc, m_down + (size_t)INNERc*Dd,
        m_ff_up + (size_t)Dd*2*FFc, m_ff_down + (size_t)FFc*Dd,
        head_w, m_qkv_w, m_ig_w, m_fg_w);
    k_embed<<<Tt, Dd>>>(x, embed);

    for(int i=0;i<2;i++){
        // ---- sLSTM ----
        k_mgemm<false,true,true,false,8><<<dim3(1, Tt/128),256,MG_SMEM>>>(
            h, big, s_bias + i*4*Dd, s_ln1 + i*Dd, W_SGX(i), 4*Dd, Dd);
        k_scan<<<NHs*(Bb/8),256>>>(s_rec + (size_t)i*4*NHs*HDs*HDs, s_gn + i*Dd);

        // ---- FFN 1 ----
        k_mgemm<false,false,true,false,4><<<dim3(1, Tt/128),256,MG_SMEM>>>(
            h, ffn, nullptr, s_ln2 + i*Dd, W_SFU(i), 2*FFc, Dd);
        k_mgemm<true,false,false,true,2><<<dim3(1, Tt/128),256,MG_SMEM>>>(
            ffn, h, nullptr, nullptr, W_SFD(i), Dd, FFc);

        // ---- mLSTM ----
        k_mgemm<false,false,true,false,8><<<dim3(1, Tt/128),256,MG_SMEM>>>(
            h, big, nullptr, m_ln1 + i*Dd, W_MUP(i), 2*INNERc, Dd);
        k_cq<<<Bb*8,256>>>(m_conv_w + (size_t)i*INNERc*Kc, m_conv_b + i*INNERc,
                           m_qkv_w + (size_t)i*3072, gweff + i*4096,
                           m_ig_b + i*NHMc, m_fg_b + i*NHMc);
        k_attn<<<Bb*NHMc,256>>>(m_onorm + i*INNERc, m_skip + i*INNERc);
        k_mgemm<true,false,false,false,1><<<dim3(2, Tt/128),256,MG_SMEM>>>(
            qb, h, nullptr, nullptr, W_MDN(i), Dd, INNERc);

        // ---- FFN 2 ----
        k_mgemm<false,false,true,false,4><<<dim3(1, Tt/128),256,MG_SMEM>>>(
            h, ffn, nullptr, m_ln2 + i*Dd, W_MFU(i), 2*FFc, Dd);
        k_mgemm<true,false,false,true,2><<<dim3(1, Tt/128),256,MG_SMEM>>>(
            ffn, h, nullptr, nullptr, W_MFD(i), Dd, FFc);
    }

    // ---- final LN + head ----
    k_mgemm<false,true,true,false,4><<<dim3(1, Tt/128),256,MG_SMEM>>>(
        h, out, head_b, post_ln, W_HEAD, Vv, Dd);
}

// round 11
// speedup vs baseline: 5.8729x; 1.0003x over previous
#include <cuda_runtime.h>
#include <cuda_bf16.h>
#include <math.h>
#include <stdint.h>

#define Bb     512
#define Ss     64
#define Dd     128
#define Vv     256
#define NHs    4
#define HDs    32
#define INNERc 256
#define NHMc   4
#define DHMc   64
#define NBc    64
#define Kc     4
#define FFc    128
#define Tt     (Bb*Ss)   /* 32768 tokens */

// ---------------- workspaces (static device globals; no allocation) ----------
__device__ float g_h[Tt*Dd];            // residual stream
__device__ float g_big[Tt*2*INNERc];    // slstm gx [t][512]  OR  mlstm up out [t][512]
__device__ float g_ffn[Tt*2*FFc];       // ffn up output
__device__ float g_xconv[Tt*INNERc];
__device__ float g_q[Tt*INNERc];        // q, later reused as mlstm combine buffer
__device__ float g_k[Tt*INNERc];
__device__ float g_v[Tt*INNERc];
__device__ float g_ig[Bb*NHMc*Ss];
__device__ float g_fg[Bb*NHMc*Ss];

// all GEMM weights, transposed+split [N][K]
#define W_SGX(i)  ((i)*262144 + 0)
#define W_SFU(i)  ((i)*262144 + 65536)
#define W_SFD(i)  ((i)*262144 + 98304)
#define W_MUP(i)  ((i)*262144 + 114688)
#define W_MDN(i)  ((i)*262144 + 180224)
#define W_MFU(i)  ((i)*262144 + 212992)
#define W_MFD(i)  ((i)*262144 + 245760)
#define W_HEAD    (524288)
#define W_TOTAL   (557056)
__device__ __nv_bfloat16 g_wt_hi[W_TOTAL];
__device__ __nv_bfloat16 g_wt_lo[W_TOTAL];
__device__ float g_gw_eff[2*4096];      // folded gate weights [L][4][256][4]

// ---------------- device math helpers ---------------------------------------
__device__ __forceinline__ float sigf(float x){ return 1.0f/(1.0f+expf(-x)); }
__device__ __forceinline__ float logsigf(float x){ return fminf(x,0.0f) - log1pf(expf(-fabsf(x))); }
__device__ __forceinline__ float geluf(float x){
    float x3 = x*x*x;
    return 0.5f*x*(1.0f+tanhf(0.7978845608028654f*(x+0.044715f*x3)));
}
__device__ __forceinline__ uint32_t smem_u32(const void* p){
    uint32_t a;
    asm("{ .reg .u64 t; cvta.to.shared.u64 t, %1; cvt.u32.u64 %0, t; }" : "=r"(a) : "l"(p));
    return a;
}
__device__ __forceinline__ void split2(float a, float b, uint32_t &hi, uint32_t &lo){
    __nv_bfloat162 h = __floats2bfloat162_rn(a, b);
    float ra = a - __bfloat162float(h.x);
    float rb = b - __bfloat162float(h.y);
    __nv_bfloat162 l = __floats2bfloat162_rn(ra, rb);
    hi = *(uint32_t*)&h; lo = *(uint32_t*)&l;
}

#define LDM4(r0,r1,r2,r3,addr) \
    asm volatile("ldmatrix.sync.aligned.m8n8.x4.shared.b16 {%0,%1,%2,%3}, [%4];" \
        : "=r"(r0),"=r"(r1),"=r"(r2),"=r"(r3) : "r"(addr))

#define MMA16816(d,a,b) \
    asm volatile("mma.sync.aligned.m16n8k16.row.col.f32.bf16.bf16.f32 " \
        "{%0,%1,%2,%3}, {%4,%5,%6,%7}, {%8,%9}, {%0,%1,%2,%3};" \
        : "+f"((d)[0]),"+f"((d)[1]),"+f"((d)[2]),"+f"((d)[3]) \
        : "r"((a)[0]),"r"((a)[1]),"r"((a)[2]),"r"((a)[3]), "r"((b)[0]),"r"((b)[1]))

// smem layout: A tiles 128x136 bf16 (hi/lo), B tiles 64x136 bf16 (hi/lo)
#define MG_STRIDE 136
#define MG_AH 0
#define MG_AL (128*MG_STRIDE*2)
#define MG_BH (2*128*MG_STRIDE*2)
#define MG_BL (MG_BH + 64*MG_STRIDE*2)
#define MG_SMEM (MG_BL + 64*MG_STRIDE*2)   /* 104448 B */

// ---------------- tensor-core GEMM: C[M,N] (+)= f(A)[M,K] @ Wt^T (+bias) -----
// NB>1 requires K==128: A is staged ONCE, then NB 64-wide B sub-tiles are
// processed in a loop reusing the staged A. NB==1 keeps the multi-k-chunk path.
template<bool ADD, bool BIAS, bool LN, bool GLU, int NB>
__global__ void __launch_bounds__(256,2) k_mgemm(
        const float* __restrict__ A, float* __restrict__ C,
        const float* __restrict__ bias, const float* __restrict__ lnw,
        int woff, int N, int K){
    extern __shared__ char smem[];
    const int tid = threadIdx.x, w = tid>>5, lane = tid&31;
    const int bm = blockIdx.y*128;
    const int wm = w & 3, wn = w >> 2;
    const int gID = lane >> 2, qid = lane & 3;

    const int a_row = lane & 15;
    const int a_koff = (lane >> 4) * 8;
    const int b_noff = (lane & 7) + ((lane >> 4) & 1) * 8;
    const int b_koff = ((lane >> 3) & 1) * 8;

    const uint32_t sb = smem_u32(smem);

    auto stageA = [&](int kc){
        #pragma unroll
        for (int it = 0; it < 8; it++){
            int g4 = tid + it*256;
            int row = g4 >> 4, kg = g4 & 15;
            float4 v0, v1;
            if (GLU){
                const float* ap = A + (size_t)(bm+row)*256 + kg*8;
                float4 gg0 = *(const float4*)ap,      gg1 = *(const float4*)(ap+4);
                float4 uu0 = *(const float4*)(ap+128), uu1 = *(const float4*)(ap+132);
                v0.x = geluf(gg0.x)*uu0.x; v0.y = geluf(gg0.y)*uu0.y;
                v0.z = geluf(gg0.z)*uu0.z; v0.w = geluf(gg0.w)*uu0.w;
                v1.x = geluf(gg1.x)*uu1.x; v1.y = geluf(gg1.y)*uu1.y;
                v1.z = geluf(gg1.z)*uu1.z; v1.w = geluf(gg1.w)*uu1.w;
            } else {
                const float4* ap = (const float4*)(A + (size_t)(bm+row)*K + kc*128 + kg*8);
                v0 = ap[0]; v1 = ap[1];
            }
            if (LN){
                float s  = v0.x+v0.y+v0.z+v0.w + v1.x+v1.y+v1.z+v1.w;
                float ss = v0.x*v0.x+v0.y*v0.y+v0.z*v0.z+v0.w*v0.w
                         + v1.x*v1.x+v1.y*v1.y+v1.z*v1.z+v1.w*v1.w;
                #pragma unroll
                for (int o = 1; o < 16; o <<= 1){
                    s  += __shfl_xor_sync(~0u, s,  o);
                    ss += __shfl_xor_sync(~0u, ss, o);
                }
                float mu  = s*(1.0f/128.0f);
                float var = ss*(1.0f/128.0f) - mu*mu;
                float rr  = rsqrtf(var + 1e-5f);
                float4 w0 = *(const float4*)&lnw[kg*8];
                float4 w1 = *(const float4*)&lnw[kg*8+4];
                v0.x = (v0.x-mu)*rr*w0.x; v0.y = (v0.y-mu)*rr*w0.y;
                v0.z = (v0.z-mu)*rr*w0.z; v0.w = (v0.w-mu)*rr*w0.w;
                v1.x = (v1.x-mu)*rr*w1.x; v1.y = (v1.y-mu)*rr*w1.y;
                v1.z = (v1.z-mu)*rr*w1.z; v1.w = (v1.w-mu)*rr*w1.w;
            }
            uint32_t h0,h1,h2,h3, l0,l1,l2,l3;
            split2(v0.x, v0.y, h0, l0);
            split2(v0.z, v0.w, h1, l1);
            split2(v1.x, v1.y, h2, l2);
            split2(v1.z, v1.w, h3, l3);
            uint32_t off = (uint32_t)(row*(MG_STRIDE*2) + kg*16);
            *(uint4*)(smem + MG_AH + off) = make_uint4(h0,h1,h2,h3);
            *(uint4*)(smem + MG_AL + off) = make_uint4(l0,l1,l2,l3);
        }
    };
    auto stageB = [&](int bn, int kc){
        #pragma unroll
        for (int it = 0; it < 4; it++){
            int g4 = tid + it*256;
            int n = g4 >> 4, kg = g4 & 15;
            size_t gi = (size_t)woff + (size_t)(bn+n)*K + kc*128 + kg*8;
            uint4 hv = *(const uint4*)(g_wt_hi + gi);
            uint4 lv = *(const uint4*)(g_wt_lo + gi);
            uint32_t off = (uint32_t)(n*(MG_STRIDE*2) + kg*16);
            *(uint4*)(smem + MG_BH + off) = hv;
            *(uint4*)(smem + MG_BL + off) = lv;
        }
    };
    auto compute = [&](float (&acc)[2][4][4]){
        #pragma unroll
        for (int ks = 0; ks < 8; ks++){
            uint32_t ah[2][4], al[2][4];
            #pragma unroll
            for (int mt = 0; mt < 2; mt++){
                uint32_t aoff = (uint32_t)((wm*32 + mt*16 + a_row)*(MG_STRIDE*2)
                                           + (ks*16 + a_koff)*2);
                LDM4(ah[mt][0],ah[mt][1],ah[mt][2],ah[mt][3], sb + MG_AH + aoff);
                LDM4(al[mt][0],al[mt][1],al[mt][2],al[mt][3], sb + MG_AL + aoff);
            }
            uint32_t bh[4][2], bl[4][2];
            #pragma unroll
            for (int ng = 0; ng < 2; ng++){
                uint32_t boff = (uint32_t)((wn*32 + ng*16 + b_noff)*(MG_STRIDE*2)
                                           + (ks*16 + b_koff)*2);
                uint32_t r0,r1,r2,r3;
                LDM4(r0,r1,r2,r3, sb + MG_BH + boff);
                bh[ng*2][0]=r0; bh[ng*2][1]=r1; bh[ng*2+1][0]=r2; bh[ng*2+1][1]=r3;
                LDM4(r0,r1,r2,r3, sb + MG_BL + boff);
                bl[ng*2][0]=r0; bl[ng*2][1]=r1; bl[ng*2+1][0]=r2; bl[ng*2+1][1]=r3;
            }
            #pragma unroll
            for (int mt = 0; mt < 2; mt++)
                #pragma unroll
                for (int nt = 0; nt < 4; nt++){
                    MMA16816(acc[mt][nt], ah[mt], bh[nt]);
                    MMA16816(acc[mt][nt], ah[mt], bl[nt]);
                    MMA16816(acc[mt][nt], al[mt], bh[nt]);
                }
        }
    };
    auto epilogue = [&](float (&acc)[2][4][4], int bn){
        #pragma unroll
        for (int mt = 0; mt < 2; mt++){
            #pragma unroll
            for (int nt = 0; nt < 4; nt++){
                int row0 = bm + wm*32 + mt*16 + gID;
                int col  = bn + wn*32 + nt*8 + qid*2;
                float2 v0 = make_float2(acc[mt][nt][0], acc[mt][nt][1]);
                float2 v1 = make_float2(acc[mt][nt][2], acc[mt][nt][3]);
                if (BIAS){
                    float2 bv = *(const float2*)&bias[col];
                    v0.x += bv.x; v0.y += bv.y;
                    v1.x += bv.x; v1.y += bv.y;
                }
                float* p0 = C + (size_t)row0*N + col;
                float* p1 = C + (size_t)(row0+8)*N + col;
                if (ADD){
                    float2 o0 = *(const float2*)p0, o1 = *(const float2*)p1;
                    v0.x += o0.x; v0.y += o0.y;
                    v1.x += o1.x; v1.y += o1.y;
                }
                *(float2*)p0 = v0;
                *(float2*)p1 = v1;
            }
        }
    };

    if constexpr (NB == 1){
        const int bn = blockIdx.x*64;
        float acc[2][4][4] = {};
        const int nchunk = K >> 7;
        for (int kc = 0; kc < nchunk; kc++){
            stageA(kc);
            stageB(bn, kc);
            __syncthreads();
            compute(acc);
            __syncthreads();
        }
        epilogue(acc, bn);
    } else {
        const int bn0 = blockIdx.x*64*NB;
        stageA(0);
        #pragma unroll
        for (int sub = 0; sub < NB; sub++){
            stageB(bn0 + sub*64, 0);
            __syncthreads();
            float acc[2][4][4] = {};
            compute(acc);
            epilogue(acc, bn0 + sub*64);
            __syncthreads();
        }
    }
}

// ---------------- one-shot weight prep: transposes + densify + gate folding --
__global__ void __launch_bounds__(256) k_prep(
    const float* sgw0, const float* sgw1,
    const float* sfu0, const float* sfd0, const float* mup0, const float* mdn0,
    const float* mfu0, const float* mfd0,
    const float* sfu1, const float* sfd1, const float* mup1, const float* mdn1,
    const float* mfu1, const float* mfd1,
    const float* headw,
    const float* qkvw, const float* igw, const float* fgw){
    int bx = blockIdx.x, tid = threadIdx.x;
    if (bx < 416){
        const int cum[13]  = {32,48,112,144,176,192,224,240,304,336,368,384,416};
        const float* srcs[13] = {sfu0,sfd0,mup0,mdn0,mfu0,mfd0,sfu1,sfd1,mup1,mdn1,mfu1,mfd1,headw};
        const int Ks[13]   = {128,128,128,256,128,128,128,128,128,256,128,128,128};
        const int Ns[13]   = {256,128,512,128,256,128,256,128,512,128,256,128,256};
        const int dsts[13] = {W_SFU(0),W_SFD(0),W_MUP(0),W_MDN(0),W_MFU(0),W_MFD(0),
                              W_SFU(1),W_SFD(1),W_MUP(1),W_MDN(1),W_MFU(1),W_MFD(1),W_HEAD};
        int j = 0;
        while (bx >= cum[j]) j++;
        int tile = bx - (j ? cum[j-1] : 0);
        const float* src = srcs[j];
        int K = Ks[j], N = Ns[j], dst = dsts[j];
        int tilesN = N >> 5;
        int bk = (tile / tilesN)*32, bn = (tile % tilesN)*32;
        __shared__ float t[32][33];
        int tx = tid & 31, ty = tid >> 5;
        #pragma unroll
        for (int r = 0; r < 32; r += 8)
            t[ty+r][tx] = src[(size_t)(bk+ty+r)*N + bn+tx];
        __syncthreads();
        #pragma unroll
        for (int r = 0; r < 32; r += 8){
            float v = t[tx][ty+r];
            __nv_bfloat16 h = __float2bfloat16(v);
            size_t o = (size_t)dst + (size_t)(bn+ty+r)*K + bk+tx;
            g_wt_hi[o] = h;
            g_wt_lo[o] = __float2bfloat16(v - __bfloat162float(h));
        }
    } else if (bx < 544){
        int bx2 = bx - 416;
        int L = bx2 >> 6, blk = bx2 & 63;
        const float* gw = L ? sgw1 : sgw0;
        #pragma unroll
        for (int u = 0; u < 4; u++){
            int idx = blk*1024 + u*256 + tid;     // over 128*512
            int d = idx >> 9;
            int o = idx & 511;
            int g = o >> 7;
            int ne = o & 127;
            int n = ne >> 5, e = ne & 31;
            float wv = 0.0f;
            if ((d >> 5) == n) wv = gw[(((g*NHs + n)*HDs + e)*HDs) + (d & 31)];
            __nv_bfloat16 h = __float2bfloat16(wv);
            size_t oo = (size_t)W_SGX(L) + (size_t)o*Dd + d;
            g_wt_hi[oo] = h;
            g_wt_lo[oo] = __float2bfloat16(wv - __bfloat162float(h));
        }
    } else {
        int L = bx - 544;
        const float* qw  = qkvw + L*3072;
        const float* igp = igw  + L*3072;
        const float* fgp = fgw  + L*3072;
        int c = tid, n = c >> 2, i = c & 3;
        float aig[4]={0,0,0,0}, big_[4]={0,0,0,0}, afg[4]={0,0,0,0}, bfg_[4]={0,0,0,0};
        #pragma unroll
        for (int o = 0; o < 4; o++){
            float w0 = qw[n*16+o*4+i];
            float w1 = qw[1024+n*16+o*4+i];
            float w2 = qw[2048+n*16+o*4+i];
            int j0 = (n*4+o)*4, j1 = (256+n*4+o)*4, j2 = (512+n*4+o)*4;
            #pragma unroll
            for (int hm = 0; hm < 4; hm++){
                aig[hm]  += w0*igp[j0+hm] + w1*igp[j1+hm];
                big_[hm] += w2*igp[j2+hm];
                afg[hm]  += w0*fgp[j0+hm] + w1*fgp[j1+hm];
                bfg_[hm] += w2*fgp[j2+hm];
            }
        }
        #pragma unroll
        for (int hm = 0; hm < 4; hm++){
            g_gw_eff[L*4096 + 0*1024 + c*4 + hm] = aig[hm];
            g_gw_eff[L*4096 + 1*1024 + c*4 + hm] = big_[hm];
            g_gw_eff[L*4096 + 2*1024 + c*4 + hm] = afg[hm];
            g_gw_eff[L*4096 + 3*1024 + c*4 + hm] = bfg_[hm];
        }
    }
}

// ---------------- embedding --------------------------------------------------
__global__ void k_embed(const int* __restrict__ x, const float* __restrict__ emb){
    int t = blockIdx.x;
    g_h[t*Dd + threadIdx.x] = emb[x[t]*Dd + threadIdx.x];
}

// ---------------- sLSTM scan: 16 warps/block (one wave), fused GN/residual ---
__global__ void __launch_bounds__(512) k_scan(const float* __restrict__ rec,
                                              const float* __restrict__ gn){
    int n  = blockIdx.x & 3;
    int bg = blockIdx.x >> 2;            // 0..31
    int w  = threadIdx.x >> 5;           // 0..15
    int e  = threadIdx.x & 31;
    int b  = bg*16 + w;
    __shared__ float rw[4][HDs][36];
    __shared__ float hs[16][HDs];
    for (int idx = threadIdx.x; idx < 4*HDs*HDs; idx += 512){
        int g = idx >> 10, rem = idx & 1023;
        int e2 = rem >> 5, d = rem & 31;
        rw[g][e2][d] = rec[((size_t)(g*NHs+n)*HDs + e2)*HDs + d];
    }
    hs[w][e] = 0.0f;
    __syncthreads();
    const int gb = n*HDs + e;
    const float gnw = gn[gb];
    const float* gx0 = g_big + (size_t)(b*Ss)*512 + gb;
    float c=0.0f, nn=0.0f, m=0.0f;
    float r0 = gx0[0], r1 = gx0[Dd], r2 = gx0[2*Dd], r3 = gx0[3*Dd];
    for(int s=0;s<Ss;s++){
        float n0=0.f, n1=0.f, n2=0.f, n3=0.f;
        if (s+1 < Ss){
            const float* np = gx0 + (size_t)(s+1)*512;
            n0 = np[0]; n1 = np[Dd]; n2 = np[2*Dd]; n3 = np[3*Dd];
        }
        #pragma unroll
        for(int dq=0; dq<8; dq++){
            float4 hv = *(const float4*)&hs[w][dq*4];
            float4 w0 = *(const float4*)&rw[0][e][dq*4];
            float4 w1 = *(const float4*)&rw[1][e][dq*4];
            float4 w2 = *(const float4*)&rw[2][e][dq*4];
            float4 w3 = *(const float4*)&rw[3][e][dq*4];
            r0 += hv.x*w0.x + hv.y*w0.y + hv.z*w0.z + hv.w*w0.w;
            r1 += hv.x*w1.x + hv.y*w1.y + hv.z*w1.z + hv.w*w1.w;
            r2 += hv.x*w2.x + hv.y*w2.y + hv.z*w2.z + hv.w*w2.w;
            r3 += hv.x*w3.x + hv.y*w3.y + hv.z*w3.z + hv.w*w3.w;
        }
        float lfm = m + logsigf(r1);
        float mn  = fmaxf(r0, lfm);
        float i   = expf(r0-mn);
        float f   = expf(lfm-mn);
        c  = f*c + i*tanhf(r2);
        nn = f*nn + i;
        float hnew = sigf(r3) * c / nn;
        m = mn;
        // publish h for next step FIRST, then do GN off the critical path
        __syncwarp();
        hs[w][e] = hnew;
        __syncwarp();
        float s1 = hnew, s2 = hnew*hnew;
        #pragma unroll
        for(int o=16;o;o>>=1){ s1 += __shfl_xor_sync(~0u,s1,o); s2 += __shfl_xor_sync(~0u,s2,o); }
        float mu = s1*(1.0f/HDs), var = s2*(1.0f/HDs)-mu*mu;
        float rr = rsqrtf(var + 1e-5f);
        g_h[((size_t)(b*Ss+s))*Dd + gb] += (hnew-mu)*rr*gnw;
        r0 = n0; r1 = n1; r2 = n2; r3 = n3;
    }
}

// ---------------- fused conv+silu+qkv+gates: 8 tokens per block --------------
__global__ void __launch_bounds__(256) k_cq(
        const float* __restrict__ cw, const float* __restrict__ cb,
        const float* __restrict__ qkvw, const float* __restrict__ gweff,
        const float* __restrict__ igb, const float* __restrict__ fgb){
    __shared__ float xms[11][256];
    __shared__ float xcv[8][256];
    __shared__ float4 Aig[256], Big[256], Afg[256], Bfg[256];
    int blk = blockIdx.x, b = blk>>3, sg = blk&7;
    int tid = threadIdx.x;
    int t0 = b*Ss + sg*8;

    Aig[tid] = *(const float4*)&gweff[0*1024 + tid*4];
    Big[tid] = *(const float4*)&gweff[1*1024 + tid*4];
    Afg[tid] = *(const float4*)&gweff[2*1024 + tid*4];
    Bfg[tid] = *(const float4*)&gweff[3*1024 + tid*4];

    for (int idx = tid; idx < 11*256; idx += 256){
        int r = idx >> 8, c = idx & 255;
        int s = sg*8 + r - 3;
        xms[r][c] = (s >= 0) ? g_big[(size_t)(b*Ss+s)*512 + c] : 0.0f;
    }
    int c = tid, n = c>>2, o = c&3;
    float cwv0=cw[c*4], cwv1=cw[c*4+1], cwv2=cw[c*4+2], cwv3=cw[c*4+3], cbv=cb[c];
    float wq[4], wk[4], wv[4];
    #pragma unroll
    for (int i2 = 0; i2 < 4; i2++){
        wq[i2] = qkvw[       n*16 + o*4 + i2];
        wk[i2] = qkvw[1024 + n*16 + o*4 + i2];
        wv[i2] = qkvw[2048 + n*16 + o*4 + i2];
    }
    __syncthreads();
    #pragma unroll
    for (int s = 0; s < 8; s++){
        float acc = cbv + xms[s][c]*cwv0 + xms[s+1][c]*cwv1 + xms[s+2][c]*cwv2 + xms[s+3][c]*cwv3;
        float xc = acc*sigf(acc);
        xcv[s][c] = xc;
        g_xconv[(size_t)(t0+s)*256 + c] = xc;
    }
    __syncthreads();
    #pragma unroll
    for (int s = 0; s < 8; s++){
        float q=0, k=0, v=0;
        #pragma unroll
        for (int i2 = 0; i2 < 4; i2++){
            float xc = xcv[s][n*4+i2];
            float xm = xms[s+3][n*4+i2];
            q += xc*wq[i2]; k += xc*wk[i2]; v += xm*wv[i2];
        }
        g_q[(size_t)(t0+s)*256 + c] = q;
        g_k[(size_t)(t0+s)*256 + c] = k;
        g_v[(size_t)(t0+s)*256 + c] = v;
    }
    int w = tid >> 5, lane = tid & 31;
    float4 ia = make_float4(0,0,0,0), fa = make_float4(0,0,0,0);
    for (int j = lane; j < 256; j += 32){
        float xc = xcv[w][j], xm = xms[w+3][j];
        float4 A = Aig[j], B = Big[j], A2 = Afg[j], B2 = Bfg[j];
        ia.x += xc*A.x + xm*B.x;  ia.y += xc*A.y + xm*B.y;
        ia.z += xc*A.z + xm*B.z;  ia.w += xc*A.w + xm*B.w;
        fa.x += xc*A2.x + xm*B2.x; fa.y += xc*A2.y + xm*B2.y;
        fa.z += xc*A2.z + xm*B2.z; fa.w += xc*A2.w + xm*B2.w;
    }
    #pragma unroll
    for (int o2=16;o2;o2>>=1){
        ia.x += __shfl_xor_sync(~0u,ia.x,o2); ia.y += __shfl_xor_sync(~0u,ia.y,o2);
        ia.z += __shfl_xor_sync(~0u,ia.z,o2); ia.w += __shfl_xor_sync(~0u,ia.w,o2);
        fa.x += __shfl_xor_sync(~0u,fa.x,o2); fa.y += __shfl_xor_sync(~0u,fa.y,o2);
        fa.z += __shfl_xor_sync(~0u,fa.z,o2); fa.w += __shfl_xor_sync(~0u,fa.w,o2);
    }
    if (lane == 0){
        int s_ = sg*8 + w;
        g_ig[(size_t)(b*NHMc+0)*Ss + s_] = ia.x + igb[0];
        g_ig[(size_t)(b*NHMc+1)*Ss + s_] = ia.y + igb[1];
        g_ig[(size_t)(b*NHMc+2)*Ss + s_] = ia.z + igb[2];
        g_ig[(size_t)(b*NHMc+3)*Ss + s_] = ia.w + igb[3];
        g_fg[(size_t)(b*NHMc+0)*Ss + s_] = fa.x + fgb[0];
        g_fg[(size_t)(b*NHMc+1)*Ss + s_] = fa.y + fgb[1];
        g_fg[(size_t)(b*NHMc+2)*Ss + s_] = fa.z + fgb[2];
        g_fg[(size_t)(b*NHMc+3)*Ss + s_] = fa.w + fgb[3];
    }
}

// ---------------- mLSTM attention + fused groupnorm/skip/silu combine --------
__global__ void __launch_bounds__(256) k_attn(const float* __restrict__ onw,
                                              const float* __restrict__ skip){
    int blk = blockIdx.x; int b = blk >> 2, hm = blk & 3;
    __shared__ float qs[Ss][DHMc+1], ks[Ss][DHMc+1], vs[Ss][DHMc+1];
    __shared__ float cldf[Ss+1], igs[Ss];
    __shared__ float cn[8][Ss];
    int tid = threadIdx.x;
    for(int l=tid; l<Ss*DHMc; l+=256){
        int j = l >> 6, d = l & 63;
        size_t base = ((size_t)(b*Ss+j))*INNERc + hm*DHMc + d;
        qs[j][d] = g_q[base];
        ks[j][d] = g_k[base];
        vs[j][d] = g_v[base];
    }
    if (tid < Ss){
        igs[tid] = g_ig[(size_t)(b*NHMc+hm)*Ss + tid];
        cldf[tid+1] = logsigf(g_fg[(size_t)(b*NHMc+hm)*Ss + tid]);
    }
    if (tid == 0) cldf[0] = 0.0f;
    __syncthreads();
    for (int off = 1; off < Ss; off <<= 1){
        float add = 0.0f;
        if (tid < Ss && tid >= off) add = cldf[tid+1-off];
        __syncthreads();
        if (tid < Ss && tid >= off) cldf[tid+1] += add;
        __syncthreads();
    }
    int w = tid >> 5, lane = tid & 31;
    int cg0 = hm*DHMc + lane, cg1 = cg0 + 32;
    float onw0 = onw[cg0], onw1 = onw[cg1];
    float sk0 = skip[cg0], sk1 = skip[cg1];
    for(int r=0;r<8;r++){
        int i = w*8 + r;
        int j1 = lane + 32;
        float dot0=0, dot1=0, ld0=-1e30f, ld1=-1e30f;
        if (lane <= i){
            #pragma unroll
            for(int d=0; d<DHMc; d++) dot0 += qs[i][d]*ks[lane][d];
            ld0 = cldf[i+1]-cldf[lane+1] + igs[lane];
        }
        if (j1 <= i){
            #pragma unroll
            for(int d=0; d<DHMc; d++) dot1 += qs[i][d]*ks[j1][d];
            ld1 = cldf[i+1]-cldf[j1+1] + igs[j1];
        }
        float mx = fmaxf(ld0, ld1);
        #pragma unroll
        for(int o=16;o;o>>=1) mx = fmaxf(mx, __shfl_xor_sync(~0u,mx,o));
        float cm0 = (lane <= i) ? dot0*0.125f*expf(ld0-mx) : 0.0f;
        float cm1 = (j1   <= i) ? dot1*0.125f*expf(ld1-mx) : 0.0f;
        float sm = cm0 + cm1;
        #pragma unroll
        for(int o=16;o;o>>=1) sm += __shfl_xor_sync(~0u,sm,o);
        float norm = fmaxf(fabsf(sm), expf(-mx)) + 1e-6f;
        cn[w][lane] = cm0/norm;
        cn[w][j1]   = cm1/norm;
        __syncwarp();
        float a0=0, a1=0;
        for(int j=0;j<=i;j++){
            float cc = cn[w][j];
            a0 += cc*vs[j][lane];
            a1 += cc*vs[j][lane+32];
        }
        float s1 = a0+a1, s2 = a0*a0+a1*a1;
        #pragma unroll
        for(int o=16;o;o>>=1){ s1 += __shfl_xor_sync(~0u,s1,o); s2 += __shfl_xor_sync(~0u,s2,o); }
        float mu = s1*(1.0f/DHMc), var = s2*(1.0f/DHMc)-mu*mu;
        float rr = rsqrtf(var + 1e-5f);
        size_t t = (size_t)(b*Ss+i);
        float z0 = g_big[t*512 + 256 + cg0], z1 = g_big[t*512 + 256 + cg1];
        float x0 = g_xconv[t*256 + cg0],     x1 = g_xconv[t*256 + cg1];
        g_q[t*256 + cg0] = ((a0-mu)*rr*onw0 + sk0*x0) * z0*sigf(z0);
        g_q[t*256 + cg1] = ((a1-mu)*rr*onw1 + sk1*x1) * z1*sigf(z1);
        __syncwarp();
    }
}

// ---------------- host-side --------------------------------------------------
static float* symf(const void* s){ void* p=nullptr; cudaGetSymbolAddress(&p, s); return (float*)p; }

extern "C" void kernel_launch(void* const* d_in, const int* in_sizes, int n_in,
                              void* d_out, int out_size){
    const int*   x         = (const int*)  d_in[0];
    const float* embed     = (const float*)d_in[1];
    const float* s_ln1     = (const float*)d_in[2];
    const float* s_gates_w = (const float*)d_in[3];
    const float* s_rec     = (const float*)d_in[4];
    const float* s_bias    = (const float*)d_in[5];
    const float* s_gn      = (const float*)d_in[6];
    const float* s_ln2     = (const float*)d_in[7];
    const float* s_ff_up   = (const float*)d_in[8];
    const float* s_ff_down = (const float*)d_in[9];
    const float* m_ln1     = (const float*)d_in[10];
    const float* m_up      = (const float*)d_in[11];
    const float* m_conv_w  = (const float*)d_in[12];
    const float* m_conv_b  = (const float*)d_in[13];
    const float* m_qkv_w   = (const float*)d_in[14];
    const float* m_ig_w    = (const float*)d_in[15];
    const float* m_ig_b    = (const float*)d_in[16];
    const float* m_fg_w    = (const float*)d_in[17];
    const float* m_fg_b    = (const float*)d_in[18];
    const float* m_skip    = (const float*)d_in[19];
    const float* m_onorm   = (const float*)d_in[20];
    const float* m_down    = (const float*)d_in[21];
    const float* m_ln2     = (const float*)d_in[22];
    const float* m_ff_up   = (const float*)d_in[23];
    const float* m_ff_down = (const float*)d_in[24];
    const float* post_ln   = (const float*)d_in[25];
    const float* head_w    = (const float*)d_in[26];
    const float* head_b    = (const float*)d_in[27];

    float* h    = symf(g_h);
    float* big  = symf(g_big);
    float* ffn  = symf(g_ffn);
    float* qb   = symf(g_q);
    float* gweff= symf(g_gw_eff);

    float* out = (float*)d_out;

    cudaFuncSetAttribute(k_mgemm<false,true ,true ,false,8>, cudaFuncAttributeMaxDynamicSharedMemorySize, MG_SMEM);
    cudaFuncSetAttribute(k_mgemm<false,false,true ,false,8>, cudaFuncAttributeMaxDynamicSharedMemorySize, MG_SMEM);
    cudaFuncSetAttribute(k_mgemm<false,false,true ,false,4>, cudaFuncAttributeMaxDynamicSharedMemorySize, MG_SMEM);
    cudaFuncSetAttribute(k_mgemm<true ,false,false,true ,2>, cudaFuncAttributeMaxDynamicSharedMemorySize, MG_SMEM);
    cudaFuncSetAttribute(k_mgemm<true ,false,false,false,1>, cudaFuncAttributeMaxDynamicSharedMemorySize, MG_SMEM);
    cudaFuncSetAttribute(k_mgemm<false,true ,true ,false,4>, cudaFuncAttributeMaxDynamicSharedMemorySize, MG_SMEM);

    k_prep<<<546,256>>>(
        s_gates_w, s_gates_w + (size_t)4*NHs*HDs*HDs,
        s_ff_up, s_ff_down, m_up, m_down, m_ff_up, m_ff_down,
        s_ff_up + (size_t)Dd*2*FFc, s_ff_down + (size_t)FFc*Dd,
        m_up + (size_t)Dd*2*INNERc, m_down + (size_t)INNERc*Dd,
        m_ff_up + (size_t)Dd*2*FFc, m_ff_down + (size_t)FFc*Dd,
        head_w, m_qkv_w, m_ig_w, m_fg_w);
    k_embed<<<Tt, Dd>>>(x, embed);

    for(int i=0;i<2;i++){
        // ---- sLSTM ----
        k_mgemm<false,true,true,false,8><<<dim3(1, Tt/128),256,MG_SMEM>>>(
            h, big, s_bias + i*4*Dd, s_ln1 + i*Dd, W_SGX(i), 4*Dd, Dd);
        k_scan<<<NHs*(Bb/16),512>>>(s_rec + (size_t)i*4*NHs*HDs*HDs, s_gn + i*Dd);

        // ---- FFN 1 ----
        k_mgemm<false,false,true,false,4><<<dim3(1, Tt/128),256,MG_SMEM>>>(
            h, ffn, nullptr, s_ln2 + i*Dd, W_SFU(i), 2*FFc, Dd);
        k_mgemm<true,false,false,true,2><<<dim3(1, Tt/128),256,MG_SMEM>>>(
            ffn, h, nullptr, nullptr, W_SFD(i), Dd, FFc);

        // ---- mLSTM ----
        k_mgemm<false,false,true,false,8><<<dim3(1, Tt/128),256,MG_SMEM>>>(
            h, big, nullptr, m_ln1 + i*Dd, W_MUP(i), 2*INNERc, Dd);
        k_cq<<<Bb*8,256>>>(m_conv_w + (size_t)i*INNERc*Kc, m_conv_b + i*INNERc,
                           m_qkv_w + (size_t)i*3072, gweff + i*4096,
                           m_ig_b + i*NHMc, m_fg_b + i*NHMc);
        k_attn<<<Bb*NHMc,256>>>(m_onorm + i*INNERc, m_skip + i*INNERc);
        k_mgemm<true,false,false,false,1><<<dim3(2, Tt/128),256,MG_SMEM>>>(
            qb, h, nullptr, nullptr, W_MDN(i), Dd, INNERc);

        // ---- FFN 2 ----
        k_mgemm<false,false,true,false,4><<<dim3(1, Tt/128),256,MG_SMEM>>>(
            h, ffn, nullptr, m_ln2 + i*Dd, W_MFU(i), 2*FFc, Dd);
        k_mgemm<true,false,false,true,2><<<dim3(1, Tt/128),256,MG_SMEM>>>(
            ffn, h, nullptr, nullptr, W_MFD(i), Dd, FFc);
    }

    // ---- final LN + head ----
    k_mgemm<false,true,true,false,4><<<dim3(1, Tt/128),256,MG_SMEM>>>(
        h, out, head_b, post_ln, W_HEAD, Vv, Dd);
}